// round 10
// baseline (speedup 1.0000x reference)
#include <cuda_runtime.h>
#include <cstdint>

// ======================= device scratch (no cudaMalloc allowed) =======================
__device__ float g_buf0[16*128*128*64];   // enc1 out / dt1 out
__device__ float g_buf1[16*64*64*128];
__device__ float g_buf2[16*64*64*128];
__device__ float g_tmpb[16*64*64*32];
__device__ float g_fbuf[16*64*64*128];
__device__ float g_qbuf[16*64*64*128];
__device__ float g_ehalf[512];

__device__ __forceinline__ uint32_t f2tf32(float x) {
    uint32_t r; asm("cvt.rna.tf32.f32 %0, %1;" : "=r"(r) : "f"(x)); return r;
}
__device__ __forceinline__ void mma_tf32(float* d, const uint32_t* a, const uint32_t* b) {
    asm volatile(
        "mma.sync.aligned.m16n8k8.row.col.f32.tf32.tf32.f32 "
        "{%0,%1,%2,%3}, {%4,%5,%6,%7}, {%8,%9}, {%0,%1,%2,%3};"
        : "+f"(d[0]), "+f"(d[1]), "+f"(d[2]), "+f"(d[3])
        : "r"(a[0]), "r"(a[1]), "r"(a[2]), "r"(a[3]), "r"(b[0]), "r"(b[1]));
}

// Fragment-order smem layouts (slab = 32 k):
// A: tiles [ksb(4)][mTile(BM/16)] of 128 words; thread (lr,lc)=lane gets uint4 at
//    tile*128 + lane*4 = {(r,klo),(r+8,klo),(r,khi),(r+8,khi)} — exactly a[0..3].
// B: tiles [ksb(4)][nTile(BN/8)] of 64 words; thread lane gets uint2 at tile*64+lane*2
//    = {(k=ks+lc), (k=ks+lc+4)} for col c = nTile*8+lr — exactly b[0..1].
// Writer formulas:
//   A word(m, kloc): (( (kloc>>3)*(BM/16) + (m>>4) )*128) + (m&7)*16 + (kloc&3)*4
//                    + ((m>>3)&1) + 2*((kloc&7)>>2)
//   B word(c, kloc): (( (kloc>>3)*(BN/8) + (c>>3) )*64) + ((c&7)*4 + (kloc&3))*2
//                    + ((kloc&7)>>2)

// ======================= fp32 tiled implicit-GEMM conv (enc1 only) =======================
template<int BM,int BN,int BK,int TM,int TN,
         int CIN,int COUT,int KH,int KW,int STRIDE,int PAD,
         int INH,int INW,int NB,
         bool RELU_IN,bool HAS_BIAS,bool ADD,bool RELU_OUT>
__global__ void __launch_bounds__(256)
conv_gemm(const float* __restrict__ in, const float* __restrict__ wgt,
          const float* __restrict__ bias, const float* __restrict__ addsrc,
          float* __restrict__ out)
{
    constexpr int MH = INH / STRIDE;
    constexpr int MW = INW / STRIDE;
    constexpr int K  = KH*KW*CIN;
    constexpr int THREADS = (BM/TM)*(BN/TN);
    static_assert(THREADS == 256, "block must be 256 threads");

    __shared__ __align__(16) float As[BK][BM+4];
    __shared__ __align__(16) float Bs[BK][BN];

    const int tid = threadIdx.x;
    const int m0  = blockIdx.x * BM;
    const int n0  = blockIdx.y * BN;

    const int tcol = tid % (BN/TN);
    const int trow = tid / (BN/TN);

    float acc[TM][TN];
    #pragma unroll
    for (int i = 0; i < TM; i++)
        #pragma unroll
        for (int j = 0; j < TN; j++) acc[i][j] = 0.f;

    for (int k0 = 0; k0 < K; k0 += BK) {
        #pragma unroll
        for (int i = 0; i < (BM*BK)/THREADS; i++) {
            int l = tid + i*THREADS;
            int mloc = l / BK, kloc = l % BK;
            int m = m0 + mloc;
            int k = k0 + kloc;
            int mx = m % MW; int t = m / MW; int my = t % MH; int n = t / MH;
            float v = 0.f;
            int ci = k % CIN; int r = k / CIN;
            int kw = r % KW, kh = r / KW;
            int iy = my*STRIDE - PAD + kh;
            int ix = mx*STRIDE - PAD + kw;
            if (iy >= 0 && iy < INH && ix >= 0 && ix < INW)
                v = in[((n*INH + iy)*INW + ix)*CIN + ci];
            if (RELU_IN) v = fmaxf(v, 0.f);
            As[kloc][mloc] = v;
        }
        #pragma unroll
        for (int i = 0; i < (BK*BN)/THREADS; i++) {
            int l = tid + i*THREADS;
            int kloc = l / BN, nloc = l % BN;
            int k = k0 + kloc;
            Bs[kloc][nloc] = wgt[k*COUT + n0 + nloc];
        }
        __syncthreads();
        #pragma unroll
        for (int kk = 0; kk < BK; kk++) {
            float ra[TM], rb[TN];
            #pragma unroll
            for (int i = 0; i < TM; i += 4) {
                float4 t4 = *reinterpret_cast<const float4*>(&As[kk][trow*TM + i]);
                ra[i]=t4.x; ra[i+1]=t4.y; ra[i+2]=t4.z; ra[i+3]=t4.w;
            }
            #pragma unroll
            for (int j = 0; j < TN; j += 4) {
                float4 t4 = *reinterpret_cast<const float4*>(&Bs[kk][tcol*TN + j]);
                rb[j]=t4.x; rb[j+1]=t4.y; rb[j+2]=t4.z; rb[j+3]=t4.w;
            }
            #pragma unroll
            for (int i = 0; i < TM; i++)
                #pragma unroll
                for (int j = 0; j < TN; j++)
                    acc[i][j] += ra[i]*rb[j];
        }
        __syncthreads();
    }
    #pragma unroll
    for (int i = 0; i < TM; i++) {
        int m = m0 + trow*TM + i;
        int obase = m*COUT;
        #pragma unroll
        for (int j = 0; j < TN; j++) {
            int c = n0 + tcol*TN + j;
            float v = acc[i][j];
            if (HAS_BIAS) v += bias[c];
            if (ADD)      v += addsrc[obase + c];
            if (RELU_OUT) v = fmaxf(v, 0.f);
            out[obase + c] = v;
        }
    }
}

// ====== tf32 mma.sync implicit-GEMM conv: fragment-ordered smem, register staging ======
// DB=1: ping-pong buffers, one sync per slab. DB=0: single buffer, two syncs.
// SPLIT=3: 3xTF32 hi/lo (encoder, ~fp32 precision); SPLIT=1: plain tf32 (decoder).
template<int CIN,int COUT,int KH,int KW,int STRIDE,int PAD,int INH,int INW,
         bool RELU_IN,bool HAS_BIAS,bool ADD,bool RELU_OUT,bool TRANS,int SPLIT,int DB>
__global__ void __launch_bounds__(256)
mma_conv5(const float* __restrict__ in, const float* __restrict__ wgt,
          const float* __restrict__ bias, const float* __restrict__ addsrc,
          float* __restrict__ out)
{
    constexpr int MH = TRANS ? INH : INH / STRIDE;
    constexpr int MW = TRANS ? INW : INW / STRIDE;
    constexpr int K  = TRANS ? 4*CIN : KH*KW*CIN;
    constexpr int BM = 128, BK = 32, BN = COUT;
    constexpr int S  = K / BK;
    constexpr int WARPS_N = (BN >= 64) ? 2 : 1;
    constexpr int WARPS_M = 8 / WARPS_N;
    constexpr int WM = BM / WARPS_M;
    constexpr int WN = BN / WARPS_N;
    constexpr int MF = WM / 16;
    constexpr int NF = WN / 8;
    constexpr int A_WORDS = 4*(BM/16)*128;      // 4096
    constexpr int B_WORDS = 4*(BN/8)*64;        // 32*BN
    constexpr int NCOPY = (SPLIT==3 ? 2 : 1);
    constexpr int CSZ = NCOPY*(A_WORDS + B_WORDS);
    constexpr int NBREG = (BK*BN)/(4*256);

    extern __shared__ __align__(16) uint32_t smem[];

    const int tid  = threadIdx.x;
    const int wid  = tid >> 5;
    const int lane = tid & 31;
    const int m0   = blockIdx.x * BM;
    const int py   = TRANS ? (int)(blockIdx.z >> 1) : 0;
    const int px   = TRANS ? (int)(blockIdx.z & 1)  : 0;
    const int wm   = wid / WARPS_N;
    const int wn   = wid % WARPS_N;
    const int lr   = lane >> 2;
    const int lc   = lane & 3;

    float acc[MF][NF][4];
    #pragma unroll
    for (int i = 0; i < MF; i++)
        #pragma unroll
        for (int j = 0; j < NF; j++)
            #pragma unroll
            for (int r = 0; r < 4; r++) acc[i][j][r] = 0.f;

    float4 aR[4];
    float4 bR[NBREG];

    auto load_regs = [&](int s) {
        const int k0 = s * BK;
        #pragma unroll
        for (int it = 0; it < 4; it++) {
            int l = tid + it*256;
            int m = l >> 3, kq = l & 7;
            int k = k0 + kq*4;
            int mg = m0 + m;
            int mx = mg % MW; int t = mg / MW; int my = t % MH; int n = t / MH;
            int iy, ix, ci;
            if (TRANS) {
                ci = k % CIN; int ab = k / CIN;
                int bb = ab & 1, aa = ab >> 1;
                iy = my + py + aa - 1;
                ix = mx + px + bb - 1;
            } else {
                ci = k % CIN; int r = k / CIN;
                int kw = r % KW, kh = r / KW;
                iy = my*STRIDE - PAD + kh;
                ix = mx*STRIDE - PAD + kw;
            }
            if (iy >= 0 && iy < INH && ix >= 0 && ix < INW)
                aR[it] = *reinterpret_cast<const float4*>(&in[((n*INH + iy)*INW + ix)*CIN + ci]);
            else
                aR[it] = make_float4(0.f,0.f,0.f,0.f);
        }
        #pragma unroll
        for (int it = 0; it < NBREG; it++) {
            int l = tid + it*256;
            int co = (l % (BN/4))*4;
            int kk = l / (BN/4);
            int k = k0 + kk;
            if (TRANS) {
                int ci = k % CIN; int ab = k / CIN;
                int bb = ab & 1, aa = ab >> 1;
                int widx = ((2*aa + py)*KW + (2*bb + px))*CIN + ci;
                bR[it] = *reinterpret_cast<const float4*>(&wgt[widx*COUT + co]);
            } else {
                bR[it] = *reinterpret_cast<const float4*>(&wgt[k*COUT + co]);
            }
        }
    };

    auto store_regs = [&](int buf) {
        uint32_t* AsH = smem + buf*CSZ;
        uint32_t* AsL = AsH + A_WORDS;
        uint32_t* BsH = AsH + NCOPY*A_WORDS;
        uint32_t* BsL = BsH + B_WORDS;
        #pragma unroll
        for (int it = 0; it < 4; it++) {
            int l = tid + it*256;
            int m = l >> 3, kq = l & 7;
            float4 v = aR[it];
            if (RELU_IN) {
                v.x = fmaxf(v.x, 0.f); v.y = fmaxf(v.y, 0.f);
                v.z = fmaxf(v.z, 0.f); v.w = fmaxf(v.w, 0.f);
            }
            // A fragment base for (m, kloc=kq*4+e): tile=(kq>>1)*(BM/16)+(m>>4)
            int w0 = (((kq >> 1)*(BM/16) + (m >> 4))*128) + (m & 7)*16
                   + ((m >> 3) & 1) + 2*(kq & 1);
            uint32_t hx = f2tf32(v.x), hy = f2tf32(v.y), hz = f2tf32(v.z), hw = f2tf32(v.w);
            AsH[w0     ] = hx;  AsH[w0 +  4] = hy;
            AsH[w0 +  8] = hz;  AsH[w0 + 12] = hw;
            if (SPLIT == 3) {
                AsL[w0     ] = f2tf32(v.x - __uint_as_float(hx));
                AsL[w0 +  4] = f2tf32(v.y - __uint_as_float(hy));
                AsL[w0 +  8] = f2tf32(v.z - __uint_as_float(hz));
                AsL[w0 + 12] = f2tf32(v.w - __uint_as_float(hw));
            }
        }
        #pragma unroll
        for (int it = 0; it < NBREG; it++) {
            int l = tid + it*256;
            int co = (l % (BN/4))*4;
            int kk = l / (BN/4);
            float4 w = bR[it];
            // B fragment base for (c=co+e, kloc=kk): tile=(kk>>3)*(BN/8)+(co>>3)
            int w0 = (((kk >> 3)*(BN/8) + (co >> 3))*64)
                   + ((co & 7)*4 + (kk & 3))*2 + ((kk & 7) >> 2);
            uint32_t hx = f2tf32(w.x), hy = f2tf32(w.y), hz = f2tf32(w.z), hw = f2tf32(w.w);
            BsH[w0     ] = hx;  BsH[w0 +  8] = hy;
            BsH[w0 + 16] = hz;  BsH[w0 + 24] = hw;
            if (SPLIT == 3) {
                BsL[w0     ] = f2tf32(w.x - __uint_as_float(hx));
                BsL[w0 +  8] = f2tf32(w.y - __uint_as_float(hy));
                BsL[w0 + 16] = f2tf32(w.z - __uint_as_float(hz));
                BsL[w0 + 24] = f2tf32(w.w - __uint_as_float(hw));
            }
        }
    };

    auto compute = [&](int buf) {
        const uint32_t* AsH = smem + buf*CSZ;
        const uint32_t* AsL = AsH + A_WORDS;
        const uint32_t* BsH = AsH + NCOPY*A_WORDS;
        const uint32_t* BsL = BsH + B_WORDS;
        #pragma unroll
        for (int ksb = 0; ksb < 4; ksb++) {
            uint32_t ah[MF][4], al[MF][4];
            #pragma unroll
            for (int i = 0; i < MF; i++) {
                int tile = ksb*(BM/16) + wm*MF + i;
                uint4 v = *reinterpret_cast<const uint4*>(&AsH[tile*128 + lane*4]);
                ah[i][0]=v.x; ah[i][1]=v.y; ah[i][2]=v.z; ah[i][3]=v.w;
                if (SPLIT == 3) {
                    uint4 u = *reinterpret_cast<const uint4*>(&AsL[tile*128 + lane*4]);
                    al[i][0]=u.x; al[i][1]=u.y; al[i][2]=u.z; al[i][3]=u.w;
                }
            }
            #pragma unroll
            for (int j = 0; j < NF; j++) {
                int tile = ksb*(BN/8) + wn*NF + j;
                uint2 h2 = *reinterpret_cast<const uint2*>(&BsH[tile*64 + lane*2]);
                uint32_t bh[2] = { h2.x, h2.y };
                #pragma unroll
                for (int i = 0; i < MF; i++)
                    mma_tf32(acc[i][j], ah[i], bh);
                if (SPLIT == 3) {
                    uint2 l2 = *reinterpret_cast<const uint2*>(&BsL[tile*64 + lane*2]);
                    uint32_t bl[2] = { l2.x, l2.y };
                    #pragma unroll
                    for (int i = 0; i < MF; i++) {
                        mma_tf32(acc[i][j], al[i], bh);
                        mma_tf32(acc[i][j], ah[i], bl);
                    }
                }
            }
        }
    };

    if (DB == 1) {
        load_regs(0);
        store_regs(0);
        __syncthreads();
        for (int s = 0; s < S; s++) {
            if (s + 1 < S) load_regs(s + 1);
            compute(s & 1);
            if (s + 1 < S) store_regs((s + 1) & 1);
            __syncthreads();
        }
    } else {
        load_regs(0);
        for (int s = 0; s < S; s++) {
            if (s > 0) __syncthreads();
            store_regs(0);
            __syncthreads();
            if (s + 1 < S) load_regs(s + 1);
            compute(0);
        }
    }

    // ---- epilogue ----
    #pragma unroll
    for (int i = 0; i < MF; i++) {
        int r0 = m0 + wm*WM + i*16 + lr;
        #pragma unroll
        for (int half = 0; half < 2; half++) {
            int mg = r0 + half*8;
            int obase;
            if (TRANS) {
                int mx = mg % MW; int t = mg / MW; int my = t % MH; int n = t / MH;
                obase = ((n*(2*INH) + 2*my + py)*(2*INW) + 2*mx + px)*COUT;
            } else {
                obase = mg*COUT;
            }
            #pragma unroll
            for (int j = 0; j < NF; j++) {
                int c = wn*WN + j*8 + 2*lc;
                float v0 = acc[i][j][half*2 + 0];
                float v1 = acc[i][j][half*2 + 1];
                if (HAS_BIAS) {
                    float2 bv = *reinterpret_cast<const float2*>(&bias[c]);
                    v0 += bv.x; v1 += bv.y;
                }
                if (ADD) {
                    float2 av = *reinterpret_cast<const float2*>(&addsrc[obase + c]);
                    v0 += av.x; v1 += av.y;
                }
                if (RELU_OUT) { v0 = fmaxf(v0, 0.f); v1 = fmaxf(v1, 0.f); }
                float2 ov; ov.x = v0; ov.y = v1;
                *reinterpret_cast<float2*>(&out[obase + c]) = ov;
            }
        }
    }
}

// ======================= codebook half-norms =======================
__global__ void emb_prep(const float* __restrict__ emb, float* __restrict__ ehalf)
{
    int c = blockIdx.x;
    int k = threadIdx.x;
    float v = emb[c*128 + k];
    float sq = v*v;
    #pragma unroll
    for (int o = 16; o; o >>= 1) sq += __shfl_xor_sync(0xffffffffu, sq, o);
    __shared__ float red[4];
    if ((k & 31) == 0) red[k >> 5] = sq;
    __syncthreads();
    if (k == 0) ehalf[c] = 0.5f*(red[0]+red[1]+red[2]+red[3]);
}

// ======================= VQ via 3xTF32 tensor GEMM + fragment argmax =======================
// Fragment-ordered smem for both operands (B built from emb directly — no embT).
__global__ void __launch_bounds__(256)
vq_mma(const float* __restrict__ f, const float* __restrict__ emb,
       const float* __restrict__ ehalf, float* __restrict__ q)
{
    constexpr int A_WORDS = 4096, B_WORDS = 4096;   // 1 slab each, BM=128/BN=128
    extern __shared__ __align__(16) uint32_t vsm[];
    uint32_t* AsH = vsm;
    uint32_t* AsL = AsH + A_WORDS;
    uint32_t* BsH = AsL + A_WORDS;
    uint32_t* BsL = BsH + B_WORDS;
    __shared__ float bestV[128][2];
    __shared__ int   bestI[128][2];
    __shared__ int   rowIdx[128];

    const int tid  = threadIdx.x;
    const int wid  = tid >> 5;
    const int lane = tid & 31;
    const int lr   = lane >> 2;
    const int lc   = lane & 3;
    const int m0   = blockIdx.x * 128;
    const int wm   = wid >> 1;    // 0..3, WM=32 (MF=2)
    const int wn   = wid & 1;     // 0..1, WN=64 (NF=8)

    float best[4];
    int   bidx[4];
    #pragma unroll
    for (int t = 0; t < 4; t++) { best[t] = -3.4e38f; bidx[t] = 0; }

    for (int nc = 0; nc < 4; nc++) {
        float acc[2][8][4];
        #pragma unroll
        for (int i = 0; i < 2; i++)
            #pragma unroll
            for (int j = 0; j < 8; j++)
                #pragma unroll
                for (int r = 0; r < 4; r++) acc[i][j][r] = 0.f;

        for (int s = 0; s < 4; s++) {
            const int k0 = s*32;
            // A slab: f rows, fragment-ordered
            #pragma unroll
            for (int it = 0; it < 4; it++) {
                int l = tid + it*256;
                int m = l >> 3, kq = l & 7;
                float4 v = *reinterpret_cast<const float4*>(&f[(m0 + m)*128 + k0 + kq*4]);
                int w0 = (((kq >> 1)*8 + (m >> 4))*128) + (m & 7)*16
                       + ((m >> 3) & 1) + 2*(kq & 1);
                uint32_t hx = f2tf32(v.x), hy = f2tf32(v.y), hz = f2tf32(v.z), hw = f2tf32(v.w);
                AsH[w0] = hx; AsH[w0+4] = hy; AsH[w0+8] = hz; AsH[w0+12] = hw;
                AsL[w0]    = f2tf32(v.x - __uint_as_float(hx));
                AsL[w0+4]  = f2tf32(v.y - __uint_as_float(hy));
                AsL[w0+8]  = f2tf32(v.z - __uint_as_float(hz));
                AsL[w0+12] = f2tf32(v.w - __uint_as_float(hw));
            }
            // B slab: emb codes nc*128..+127, fragment-ordered
            #pragma unroll
            for (int it = 0; it < 4; it++) {
                int l = tid + it*256;
                int cl = l >> 3, kq = l & 7;
                float4 w = *reinterpret_cast<const float4*>(
                    &emb[(nc*128 + cl)*128 + k0 + kq*4]);
                int w0 = (((kq >> 1)*16 + (cl >> 3))*64)
                       + (cl & 7)*8 + 0*2 + (kq & 1);
                // per element e: kloc = kq*4+e -> (kloc&3)=e, word += e*2
                uint32_t hx = f2tf32(w.x), hy = f2tf32(w.y), hz = f2tf32(w.z), hw = f2tf32(w.w);
                BsH[w0] = hx; BsH[w0+2] = hy; BsH[w0+4] = hz; BsH[w0+6] = hw;
                BsL[w0]   = f2tf32(w.x - __uint_as_float(hx));
                BsL[w0+2] = f2tf32(w.y - __uint_as_float(hy));
                BsL[w0+4] = f2tf32(w.z - __uint_as_float(hz));
                BsL[w0+6] = f2tf32(w.w - __uint_as_float(hw));
            }
            __syncthreads();
            #pragma unroll
            for (int ksb = 0; ksb < 4; ksb++) {
                uint32_t ah[2][4], al[2][4];
                #pragma unroll
                for (int i = 0; i < 2; i++) {
                    int tile = ksb*8 + wm*2 + i;
                    uint4 v = *reinterpret_cast<const uint4*>(&AsH[tile*128 + lane*4]);
                    ah[i][0]=v.x; ah[i][1]=v.y; ah[i][2]=v.z; ah[i][3]=v.w;
                    uint4 u = *reinterpret_cast<const uint4*>(&AsL[tile*128 + lane*4]);
                    al[i][0]=u.x; al[i][1]=u.y; al[i][2]=u.z; al[i][3]=u.w;
                }
                #pragma unroll
                for (int j = 0; j < 8; j++) {
                    int tile = ksb*16 + wn*8 + j;
                    uint2 h2 = *reinterpret_cast<const uint2*>(&BsH[tile*64 + lane*2]);
                    uint2 l2 = *reinterpret_cast<const uint2*>(&BsL[tile*64 + lane*2]);
                    uint32_t bh[2] = { h2.x, h2.y };
                    uint32_t bl[2] = { l2.x, l2.y };
                    #pragma unroll
                    for (int i = 0; i < 2; i++) {
                        mma_tf32(acc[i][j], al[i], bh);
                        mma_tf32(acc[i][j], ah[i], bl);
                        mma_tf32(acc[i][j], ah[i], bh);
                    }
                }
            }
            __syncthreads();
        }
        // running argmax update for this n-chunk (this warp's column subset)
        #pragma unroll
        for (int i = 0; i < 2; i++) {
            #pragma unroll
            for (int half = 0; half < 2; half++) {
                int slot = i*2 + half;
                #pragma unroll
                for (int j = 0; j < 8; j++) {
                    int col = nc*128 + wn*64 + j*8 + 2*lc;
                    float s0 = acc[i][j][half*2 + 0] - __ldg(&ehalf[col]);
                    float s1 = acc[i][j][half*2 + 1] - __ldg(&ehalf[col + 1]);
                    if (s0 > best[slot] || (s0 == best[slot] && col < bidx[slot]))
                        { best[slot] = s0; bidx[slot] = col; }
                    if (s1 > best[slot] || (s1 == best[slot] && col + 1 < bidx[slot]))
                        { best[slot] = s1; bidx[slot] = col + 1; }
                }
            }
        }
    }
    // intra-warp quad reduce, then cross-wn combine in smem
    #pragma unroll
    for (int slot = 0; slot < 4; slot++) {
        #pragma unroll
        for (int off = 1; off < 4; off <<= 1) {
            float ov = __shfl_xor_sync(0xffffffffu, best[slot], off);
            int   oi = __shfl_xor_sync(0xffffffffu, bidx[slot], off);
            if (ov > best[slot] || (ov == best[slot] && oi < bidx[slot]))
                { best[slot] = ov; bidx[slot] = oi; }
        }
        if (lc == 0) {
            int i = slot >> 1, half = slot & 1;
            int row = wm*32 + i*16 + half*8 + lr;
            bestV[row][wn] = best[slot];
            bestI[row][wn] = bidx[slot];
        }
    }
    __syncthreads();
    for (int r = tid; r < 128; r += 256) {
        float v0 = bestV[r][0], v1 = bestV[r][1];
        int   i0 = bestI[r][0], i1 = bestI[r][1];
        rowIdx[r] = (v1 > v0 || (v1 == v0 && i1 < i0)) ? i1 : i0;
    }
    __syncthreads();
    for (int l = tid; l < 128*128; l += 256) {
        int r = l >> 7, j = l & 127;
        q[(m0 + r)*128 + j] = emb[rowIdx[r]*128 + j];
    }
}

// ======================= dt2: 4x4 s2 tconv 64->3, direct =======================
__global__ void __launch_bounds__(256)
dt2_kernel(const float* __restrict__ in,
           const float* __restrict__ wgt,
           const float* __restrict__ bias,
           float* __restrict__ out)
{
    __shared__ float ws[4*4*64*3];
    for (int l = threadIdx.x; l < 3072; l += 256) ws[l] = wgt[l];
    __syncthreads();

    const int py = blockIdx.z >> 1, px = blockIdx.z & 1;
    const int m = blockIdx.x * 256 + threadIdx.x;
    const int xq = m & 127; int t = m >> 7; const int yq = t & 127; const int n = t >> 7;

    float a0 = __ldg(&bias[0]), a1 = __ldg(&bias[1]), a2 = __ldg(&bias[2]);
    #pragma unroll
    for (int aa = 0; aa < 2; aa++) {
        #pragma unroll
        for (int bb = 0; bb < 2; bb++) {
            int iy = yq + py + aa - 1;
            int ix = xq + px + bb - 1;
            if (iy < 0 || iy >= 128 || ix < 0 || ix >= 128) continue;
            const float* ip = in + ((n*128 + iy)*128 + ix)*64;
            const float* wp = ws + ((2*aa + py)*4 + (2*bb + px))*64*3;
            #pragma unroll
            for (int ci = 0; ci < 64; ci += 4) {
                float4 v = *reinterpret_cast<const float4*>(ip + ci);
                const float* w0 = wp + ci*3;
                a0 += v.x*w0[0];  a1 += v.x*w0[1];  a2 += v.x*w0[2];
                a0 += v.y*w0[3];  a1 += v.y*w0[4];  a2 += v.y*w0[5];
                a0 += v.z*w0[6];  a1 += v.z*w0[7];  a2 += v.z*w0[8];
                a0 += v.w*w0[9];  a1 += v.w*w0[10]; a2 += v.w*w0[11];
            }
        }
    }
    const int oy = 2*yq + py, ox = 2*xq + px;
    float* op = out + ((n*256 + oy)*256 + ox)*3;
    op[0] = a0; op[1] = a1; op[2] = a2;
}

// ======================= host launcher =======================
extern "C" void kernel_launch(void* const* d_in, const int* in_sizes, int n_in,
                              void* d_out, int out_size)
{
    (void)in_sizes; (void)n_in;
    const float* x       = (const float*)d_in[0];
    const float* emb     = (const float*)d_in[1];
    const float* enc_w1  = (const float*)d_in[2];
    const float* enc_b1  = (const float*)d_in[3];
    const float* enc_w2  = (const float*)d_in[4];
    const float* enc_b2  = (const float*)d_in[5];
    const float* enc_w3  = (const float*)d_in[6];
    const float* enc_b3  = (const float*)d_in[7];
    const float* erb1_w1 = (const float*)d_in[8];
    const float* erb1_w2 = (const float*)d_in[9];
    const float* erb2_w1 = (const float*)d_in[10];
    const float* erb2_w2 = (const float*)d_in[11];
    const float* dec_w   = (const float*)d_in[12];
    const float* dec_b   = (const float*)d_in[13];
    const float* drb1_w1 = (const float*)d_in[14];
    const float* drb1_w2 = (const float*)d_in[15];
    const float* drb2_w1 = (const float*)d_in[16];
    const float* drb2_w2 = (const float*)d_in[17];
    const float* dt1_w   = (const float*)d_in[18];
    const float* dt1_b   = (const float*)d_in[19];
    const float* dt2_w   = (const float*)d_in[20];
    const float* dt2_b   = (const float*)d_in[21];

    float* out = (float*)d_out;
    const int YS = 16*256*256*3;
    const int FS = 16*64*64*128;

    float *buf0,*buf1,*buf2,*tmpb,*ehalf,*fb,*qb;
    cudaGetSymbolAddress((void**)&buf0,  g_buf0);
    cudaGetSymbolAddress((void**)&buf1,  g_buf1);
    cudaGetSymbolAddress((void**)&buf2,  g_buf2);
    cudaGetSymbolAddress((void**)&tmpb,  g_tmpb);
    cudaGetSymbolAddress((void**)&ehalf, g_ehalf);
    cudaGetSymbolAddress((void**)&fb,    g_fbuf);
    cudaGetSymbolAddress((void**)&qb,    g_qbuf);

    const bool full = (out_size >= YS + 2*FS);
    float* fptr = full ? (out + YS)      : fb;
    float* qptr = full ? (out + YS + FS) : qb;

    dim3 b(256);

    // smem bytes: NCOPY*(4096 + 32*BN) words per copy, xBUF, x4B
    const int SM3_128_S = 2*(4096 + 4096)*4;        // 65536, single-buffer
    const int SM3_32_D  = 2*2*(4096 + 1024)*4;      // 81920, double-buffer
    const int SM1_128_D = 2*(4096 + 4096)*4;        // 65536
    const int SM1_64_D  = 2*(4096 + 2048)*4;        // 49152
    const int SM1_32_D  = 2*(4096 + 1024)*4;        // 40960
    const int SMV       = (2*4096 + 2*4096)*4;      // 65536

    // ---- encoder (3xTF32) ----
    auto kEnc2 = mma_conv5<64,128,4,4,2,1, 128,128, false,true,false,true,false,3,0>;
    auto kEnc3 = mma_conv5<128,128,3,3,1,1, 64,64, false,true,false,false,false,3,0>;
    auto kEw1  = mma_conv5<128,32, 3,3,1,1, 64,64, true,false,false,true,false,3,1>;
    auto kEw2  = mma_conv5<32,128, 1,1,1,0, 64,64, false,false,true,false,false,3,0>;
    auto kEw2R = mma_conv5<32,128, 1,1,1,0, 64,64, false,false,true,true,false,3,0>;
    // ---- decoder (single-pass tf32, double-buffered) ----
    auto kDec  = mma_conv5<128,128,3,3,1,1, 64,64, false,true,false,false,false,1,1>;
    auto kDw1  = mma_conv5<128,32, 3,3,1,1, 64,64, true,false,false,true,false,1,1>;
    auto kDw2  = mma_conv5<32,128, 1,1,1,0, 64,64, false,false,true,false,false,1,1>;
    auto kDw2R = mma_conv5<32,128, 1,1,1,0, 64,64, false,false,true,true,false,1,1>;
    auto kDt1  = mma_conv5<128,64, 4,4,2,0, 64,64, false,true,false,true,true,1,1>;

    cudaFuncSetAttribute(kEnc2, cudaFuncAttributeMaxDynamicSharedMemorySize, SM3_128_S);
    cudaFuncSetAttribute(kEnc3, cudaFuncAttributeMaxDynamicSharedMemorySize, SM3_128_S);
    cudaFuncSetAttribute(kEw1,  cudaFuncAttributeMaxDynamicSharedMemorySize, SM3_32_D);
    cudaFuncSetAttribute(kEw2,  cudaFuncAttributeMaxDynamicSharedMemorySize, SM3_128_S);
    cudaFuncSetAttribute(kEw2R, cudaFuncAttributeMaxDynamicSharedMemorySize, SM3_128_S);
    cudaFuncSetAttribute(kDec,  cudaFuncAttributeMaxDynamicSharedMemorySize, SM1_128_D);
    cudaFuncSetAttribute(kDw1,  cudaFuncAttributeMaxDynamicSharedMemorySize, SM1_32_D);
    cudaFuncSetAttribute(kDw2,  cudaFuncAttributeMaxDynamicSharedMemorySize, SM1_128_D);
    cudaFuncSetAttribute(kDw2R, cudaFuncAttributeMaxDynamicSharedMemorySize, SM1_128_D);
    cudaFuncSetAttribute(kDt1,  cudaFuncAttributeMaxDynamicSharedMemorySize, SM1_64_D);
    cudaFuncSetAttribute(vq_mma, cudaFuncAttributeMaxDynamicSharedMemorySize, SMV);

    // ---- encoder ----
    conv_gemm<64,64,16,4,4,  3,64,4,4,2,1, 256,256,16, false,true,false,true>
        <<<dim3(4096,1,1),b>>>(x, enc_w1, enc_b1, nullptr, buf0);
    kEnc2<<<dim3(512,1,1), b, SM3_128_S>>>(buf0, enc_w2, enc_b2, nullptr, buf1);
    kEnc3<<<dim3(512,1,1), b, SM3_128_S>>>(buf1, enc_w3, enc_b3, nullptr, buf2);
    kEw1 <<<dim3(512,1,1), b, SM3_32_D >>>(buf2, erb1_w1, nullptr, nullptr, tmpb);
    kEw2 <<<dim3(512,1,1), b, SM3_128_S>>>(tmpb, erb1_w2, nullptr, buf2, buf2);
    kEw1 <<<dim3(512,1,1), b, SM3_32_D >>>(buf2, erb2_w1, nullptr, nullptr, tmpb);
    kEw2R<<<dim3(512,1,1), b, SM3_128_S>>>(tmpb, erb2_w2, nullptr, buf2, fptr);

    // ---- VQ (3xTF32 scores, fp32 norms, full-codebook argmax) ----
    emb_prep<<<512,128>>>(emb, ehalf);
    vq_mma<<<512, b, SMV>>>(fptr, emb, ehalf, qptr);

    // ---- decoder ----
    kDec <<<dim3(512,1,1), b, SM1_128_D>>>(qptr, dec_w, dec_b, nullptr, buf1);
    kDw1 <<<dim3(512,1,1), b, SM1_32_D >>>(buf1, drb1_w1, nullptr, nullptr, tmpb);
    kDw2 <<<dim3(512,1,1), b, SM1_128_D>>>(tmpb, drb1_w2, nullptr, buf1, buf1);
    kDw1 <<<dim3(512,1,1), b, SM1_32_D >>>(buf1, drb2_w1, nullptr, nullptr, tmpb);
    kDw2R<<<dim3(512,1,1), b, SM1_128_D>>>(tmpb, drb2_w2, nullptr, buf1, buf2);
    kDt1 <<<dim3(512,1,4), b, SM1_64_D >>>(buf2, dt1_w, dt1_b, nullptr, buf0);

    dt2_kernel<<<dim3(1024,1,4),b>>>(buf0, dt2_w, dt2_b, out);
}

// round 11
// speedup vs baseline: 2.2212x; 2.2212x over previous
#include <cuda_runtime.h>
#include <cstdint>

// ======================= device scratch (no cudaMalloc allowed) =======================
__device__ float g_buf0[16*128*128*64];   // enc1 out / dt1 out
__device__ float g_buf1[16*64*64*128];
__device__ float g_buf2[16*64*64*128];
__device__ float g_tmpb[16*64*64*32];
__device__ float g_fbuf[16*64*64*128];
__device__ float g_qbuf[16*64*64*128];
__device__ float g_embT[128*512];
__device__ float g_ehalf[512];

__device__ __forceinline__ uint32_t f2tf32(float x) {
    uint32_t r; asm("cvt.rna.tf32.f32 %0, %1;" : "=r"(r) : "f"(x)); return r;
}
__device__ __forceinline__ void mma_tf32(float* d, const uint32_t* a, const uint32_t* b) {
    asm volatile(
        "mma.sync.aligned.m16n8k8.row.col.f32.tf32.tf32.f32 "
        "{%0,%1,%2,%3}, {%4,%5,%6,%7}, {%8,%9}, {%0,%1,%2,%3};"
        : "+f"(d[0]), "+f"(d[1]), "+f"(d[2]), "+f"(d[3])
        : "r"(a[0]), "r"(a[1]), "r"(a[2]), "r"(a[3]), "r"(b[0]), "r"(b[1]));
}

// ======================= fp32 tiled implicit-GEMM conv (enc1 only) =======================
template<int BM,int BN,int BK,int TM,int TN,
         int CIN,int COUT,int KH,int KW,int STRIDE,int PAD,
         int INH,int INW,int NB,
         bool RELU_IN,bool HAS_BIAS,bool ADD,bool RELU_OUT>
__global__ void __launch_bounds__(256)
conv_gemm(const float* __restrict__ in, const float* __restrict__ wgt,
          const float* __restrict__ bias, const float* __restrict__ addsrc,
          float* __restrict__ out)
{
    constexpr int MH = INH / STRIDE;
    constexpr int MW = INW / STRIDE;
    constexpr int K  = KH*KW*CIN;
    constexpr int THREADS = (BM/TM)*(BN/TN);
    static_assert(THREADS == 256, "block must be 256 threads");

    __shared__ __align__(16) float As[BK][BM+4];
    __shared__ __align__(16) float Bs[BK][BN];

    const int tid = threadIdx.x;
    const int m0  = blockIdx.x * BM;
    const int n0  = blockIdx.y * BN;

    const int tcol = tid % (BN/TN);
    const int trow = tid / (BN/TN);

    float acc[TM][TN];
    #pragma unroll
    for (int i = 0; i < TM; i++)
        #pragma unroll
        for (int j = 0; j < TN; j++) acc[i][j] = 0.f;

    for (int k0 = 0; k0 < K; k0 += BK) {
        #pragma unroll
        for (int i = 0; i < (BM*BK)/THREADS; i++) {
            int l = tid + i*THREADS;
            int mloc = l / BK, kloc = l % BK;
            int m = m0 + mloc;
            int k = k0 + kloc;
            int mx = m % MW; int t = m / MW; int my = t % MH; int n = t / MH;
            float v = 0.f;
            int ci = k % CIN; int r = k / CIN;
            int kw = r % KW, kh = r / KW;
            int iy = my*STRIDE - PAD + kh;
            int ix = mx*STRIDE - PAD + kw;
            if (iy >= 0 && iy < INH && ix >= 0 && ix < INW)
                v = in[((n*INH + iy)*INW + ix)*CIN + ci];
            if (RELU_IN) v = fmaxf(v, 0.f);
            As[kloc][mloc] = v;
        }
        #pragma unroll
        for (int i = 0; i < (BK*BN)/THREADS; i++) {
            int l = tid + i*THREADS;
            int kloc = l / BN, nloc = l % BN;
            int k = k0 + kloc;
            Bs[kloc][nloc] = wgt[k*COUT + n0 + nloc];
        }
        __syncthreads();
        #pragma unroll
        for (int kk = 0; kk < BK; kk++) {
            float ra[TM], rb[TN];
            #pragma unroll
            for (int i = 0; i < TM; i += 4) {
                float4 t4 = *reinterpret_cast<const float4*>(&As[kk][trow*TM + i]);
                ra[i]=t4.x; ra[i+1]=t4.y; ra[i+2]=t4.z; ra[i+3]=t4.w;
            }
            #pragma unroll
            for (int j = 0; j < TN; j += 4) {
                float4 t4 = *reinterpret_cast<const float4*>(&Bs[kk][tcol*TN + j]);
                rb[j]=t4.x; rb[j+1]=t4.y; rb[j+2]=t4.z; rb[j+3]=t4.w;
            }
            #pragma unroll
            for (int i = 0; i < TM; i++)
                #pragma unroll
                for (int j = 0; j < TN; j++)
                    acc[i][j] += ra[i]*rb[j];
        }
        __syncthreads();
    }
    #pragma unroll
    for (int i = 0; i < TM; i++) {
        int m = m0 + trow*TM + i;
        int obase = m*COUT;
        #pragma unroll
        for (int j = 0; j < TN; j++) {
            int c = n0 + tcol*TN + j;
            float v = acc[i][j];
            if (HAS_BIAS) v += bias[c];
            if (ADD)      v += addsrc[obase + c];
            if (RELU_OUT) v = fmaxf(v, 0.f);
            out[obase + c] = v;
        }
    }
}

// ====== tf32 mma.sync implicit-GEMM conv: A raw fp32 in smem (cvt at fragment read,
// valid because each A element is read by exactly ONE warp); B pre-converted hi/lo.
// Ping-pong DB everywhere, one sync per slab. SPLIT=3: 3xTF32 (encoder); SPLIT=1: decoder.
template<int CIN,int COUT,int KH,int KW,int STRIDE,int PAD,int INH,int INW,
         bool RELU_IN,bool HAS_BIAS,bool ADD,bool RELU_OUT,bool TRANS,int SPLIT>
__global__ void __launch_bounds__(256)
mma_conv6(const float* __restrict__ in, const float* __restrict__ wgt,
          const float* __restrict__ bias, const float* __restrict__ addsrc,
          float* __restrict__ out)
{
    constexpr int MH = TRANS ? INH : INH / STRIDE;
    constexpr int MW = TRANS ? INW : INW / STRIDE;
    constexpr int K  = TRANS ? 4*CIN : KH*KW*CIN;
    constexpr int BM = 128, BK = 32, BN = COUT;
    constexpr int S  = K / BK;
    constexpr int WARPS_N = (BN >= 64) ? 2 : 1;
    constexpr int WARPS_M = 8 / WARPS_N;
    constexpr int WM = BM / WARPS_M;
    constexpr int WN = BN / WARPS_N;
    constexpr int MF = WM / 16;
    constexpr int NF = WN / 8;
    constexpr int ASTR = BK + 4;
    constexpr int BSTR = BN + 8;
    constexpr int A_WORDS = BM*ASTR;                 // raw fp32 A
    constexpr int B_WORDS = BK*BSTR;
    constexpr int NCOPYB = (SPLIT==3 ? 2 : 1);
    constexpr int CSZ = A_WORDS + NCOPYB*B_WORDS;    // words per buffer
    constexpr int NBREG = (BK*BN)/(4*256);

    extern __shared__ __align__(16) uint32_t smem[];

    const int tid  = threadIdx.x;
    const int wid  = tid >> 5;
    const int lane = tid & 31;
    const int m0   = blockIdx.x * BM;
    const int py   = TRANS ? (int)(blockIdx.z >> 1) : 0;
    const int px   = TRANS ? (int)(blockIdx.z & 1)  : 0;
    const int wm   = wid / WARPS_N;
    const int wn   = wid % WARPS_N;
    const int lr   = lane >> 2;
    const int lc   = lane & 3;

    float acc[MF][NF][4];
    #pragma unroll
    for (int i = 0; i < MF; i++)
        #pragma unroll
        for (int j = 0; j < NF; j++)
            #pragma unroll
            for (int r = 0; r < 4; r++) acc[i][j][r] = 0.f;

    float4 aR[4];
    float4 bR[NBREG];

    auto load_regs = [&](int s) {
        const int k0 = s * BK;
        #pragma unroll
        for (int it = 0; it < 4; it++) {
            int l = tid + it*256;
            int m = l >> 3, kq = l & 7;
            int k = k0 + kq*4;
            int mg = m0 + m;
            int mx = mg % MW; int t = mg / MW; int my = t % MH; int n = t / MH;
            int iy, ix, ci;
            if (TRANS) {
                ci = k % CIN; int ab = k / CIN;
                int bb = ab & 1, aa = ab >> 1;
                iy = my + py + aa - 1;
                ix = mx + px + bb - 1;
            } else {
                ci = k % CIN; int r = k / CIN;
                int kw = r % KW, kh = r / KW;
                iy = my*STRIDE - PAD + kh;
                ix = mx*STRIDE - PAD + kw;
            }
            if (iy >= 0 && iy < INH && ix >= 0 && ix < INW)
                aR[it] = *reinterpret_cast<const float4*>(&in[((n*INH + iy)*INW + ix)*CIN + ci]);
            else
                aR[it] = make_float4(0.f,0.f,0.f,0.f);
        }
        #pragma unroll
        for (int it = 0; it < NBREG; it++) {
            int l = tid + it*256;
            int co = (l % (BN/4))*4;
            int kk = l / (BN/4);
            int k = k0 + kk;
            if (TRANS) {
                int ci = k % CIN; int ab = k / CIN;
                int bb = ab & 1, aa = ab >> 1;
                int widx = ((2*aa + py)*KW + (2*bb + px))*CIN + ci;
                bR[it] = *reinterpret_cast<const float4*>(&wgt[widx*COUT + co]);
            } else {
                bR[it] = *reinterpret_cast<const float4*>(&wgt[k*COUT + co]);
            }
        }
    };

    auto store_regs = [&](int buf) {
        float*    AsF = reinterpret_cast<float*>(smem + buf*CSZ);
        uint32_t* BsH = smem + buf*CSZ + A_WORDS;
        uint32_t* BsL = BsH + B_WORDS;
        #pragma unroll
        for (int it = 0; it < 4; it++) {
            int l = tid + it*256;
            int m = l >> 3, kq = l & 7;
            float4 v = aR[it];
            if (RELU_IN) {
                v.x = fmaxf(v.x, 0.f); v.y = fmaxf(v.y, 0.f);
                v.z = fmaxf(v.z, 0.f); v.w = fmaxf(v.w, 0.f);
            }
            *reinterpret_cast<float4*>(&AsF[m*ASTR + kq*4]) = v;
        }
        #pragma unroll
        for (int it = 0; it < NBREG; it++) {
            int l = tid + it*256;
            int co = (l % (BN/4))*4;
            int kk = l / (BN/4);
            float4 w = bR[it];
            uint4 h;
            h.x = f2tf32(w.x); h.y = f2tf32(w.y); h.z = f2tf32(w.z); h.w = f2tf32(w.w);
            *reinterpret_cast<uint4*>(&BsH[kk*BSTR + co]) = h;
            if (SPLIT == 3) {
                uint4 lo;
                lo.x = f2tf32(w.x - __uint_as_float(h.x));
                lo.y = f2tf32(w.y - __uint_as_float(h.y));
                lo.z = f2tf32(w.z - __uint_as_float(h.z));
                lo.w = f2tf32(w.w - __uint_as_float(h.w));
                *reinterpret_cast<uint4*>(&BsL[kk*BSTR + co]) = lo;
            }
        }
    };

    auto compute = [&](int buf) {
        const float*    AsF = reinterpret_cast<const float*>(smem + buf*CSZ);
        const uint32_t* BsH = smem + buf*CSZ + A_WORDS;
        const uint32_t* BsL = BsH + B_WORDS;
        #pragma unroll
        for (int ks = 0; ks < BK; ks += 8) {
            uint32_t ah[MF][4], al[MF][4];
            #pragma unroll
            for (int i = 0; i < MF; i++) {
                int r = wm*WM + i*16 + lr;
                float v0 = AsF[(r    )*ASTR + ks + lc];
                float v1 = AsF[(r + 8)*ASTR + ks + lc];
                float v2 = AsF[(r    )*ASTR + ks + lc + 4];
                float v3 = AsF[(r + 8)*ASTR + ks + lc + 4];
                ah[i][0] = f2tf32(v0); ah[i][1] = f2tf32(v1);
                ah[i][2] = f2tf32(v2); ah[i][3] = f2tf32(v3);
                if (SPLIT == 3) {
                    al[i][0] = f2tf32(v0 - __uint_as_float(ah[i][0]));
                    al[i][1] = f2tf32(v1 - __uint_as_float(ah[i][1]));
                    al[i][2] = f2tf32(v2 - __uint_as_float(ah[i][2]));
                    al[i][3] = f2tf32(v3 - __uint_as_float(ah[i][3]));
                }
            }
            #pragma unroll
            for (int j = 0; j < NF; j++) {
                int c = wn*WN + j*8 + lr;
                uint32_t bh[2], bl[2];
                bh[0] = BsH[(ks + lc    )*BSTR + c];
                bh[1] = BsH[(ks + lc + 4)*BSTR + c];
                if (SPLIT == 3) {
                    bl[0] = BsL[(ks + lc    )*BSTR + c];
                    bl[1] = BsL[(ks + lc + 4)*BSTR + c];
                }
                #pragma unroll
                for (int i = 0; i < MF; i++) {
                    if (SPLIT == 3) {
                        mma_tf32(acc[i][j], al[i], bh);
                        mma_tf32(acc[i][j], ah[i], bl);
                    }
                    mma_tf32(acc[i][j], ah[i], bh);
                }
            }
        }
    };

    load_regs(0);
    store_regs(0);
    __syncthreads();
    for (int s = 0; s < S; s++) {
        if (s + 1 < S) load_regs(s + 1);
        compute(s & 1);
        if (s + 1 < S) store_regs((s + 1) & 1);
        __syncthreads();
    }

    // ---- epilogue ----
    #pragma unroll
    for (int i = 0; i < MF; i++) {
        int r0 = m0 + wm*WM + i*16 + lr;
        #pragma unroll
        for (int half = 0; half < 2; half++) {
            int mg = r0 + half*8;
            int obase;
            if (TRANS) {
                int mx = mg % MW; int t = mg / MW; int my = t % MH; int n = t / MH;
                obase = ((n*(2*INH) + 2*my + py)*(2*INW) + 2*mx + px)*COUT;
            } else {
                obase = mg*COUT;
            }
            #pragma unroll
            for (int j = 0; j < NF; j++) {
                int c = wn*WN + j*8 + 2*lc;
                float v0 = acc[i][j][half*2 + 0];
                float v1 = acc[i][j][half*2 + 1];
                if (HAS_BIAS) {
                    float2 bv = *reinterpret_cast<const float2*>(&bias[c]);
                    v0 += bv.x; v1 += bv.y;
                }
                if (ADD) {
                    float2 av = *reinterpret_cast<const float2*>(&addsrc[obase + c]);
                    v0 += av.x; v1 += av.y;
                }
                if (RELU_OUT) { v0 = fmaxf(v0, 0.f); v1 = fmaxf(v1, 0.f); }
                float2 ov; ov.x = v0; ov.y = v1;
                *reinterpret_cast<float2*>(&out[obase + c]) = ov;
            }
        }
    }
}

// ======================= codebook prep =======================
__global__ void emb_prep(const float* __restrict__ emb,
                         float* __restrict__ embT, float* __restrict__ ehalf)
{
    int c = blockIdx.x;
    int k = threadIdx.x;
    float v = emb[c*128 + k];
    embT[k*512 + c] = v;
    float s = v*v;
    #pragma unroll
    for (int o = 16; o; o >>= 1) s += __shfl_xor_sync(0xffffffffu, s, o);
    __shared__ float red[4];
    if ((k & 31) == 0) red[k >> 5] = s;
    __syncthreads();
    if (k == 0) ehalf[c] = 0.5f*(red[0]+red[1]+red[2]+red[3]);
}

// ======================= VQ via 3xTF32 tensor GEMM + fragment argmax =======================
// A (f) raw fp32 in smem, cvt hi/lo at fragment read; B (embT) pre-converted hi/lo.
__global__ void __launch_bounds__(256)
vq_mma(const float* __restrict__ f, const float* __restrict__ emb,
       const float* __restrict__ embT, const float* __restrict__ ehalf,
       float* __restrict__ q)
{
    constexpr int ASTR = 36, BSTR = 136;
    constexpr int A_WORDS = 128*ASTR, B_WORDS = 32*BSTR;
    extern __shared__ __align__(16) uint32_t vsm[];
    float*    AsF = reinterpret_cast<float*>(vsm);
    uint32_t* BsH = vsm + A_WORDS;
    uint32_t* BsL = BsH + B_WORDS;
    __shared__ float bestV[128][2];
    __shared__ int   bestI[128][2];
    __shared__ int   rowIdx[128];

    const int tid  = threadIdx.x;
    const int wid  = tid >> 5;
    const int lane = tid & 31;
    const int lr   = lane >> 2;
    const int lc   = lane & 3;
    const int m0   = blockIdx.x * 128;
    const int wm   = wid >> 1;
    const int wn   = wid & 1;

    float best[4];
    int   bidx[4];
    #pragma unroll
    for (int t = 0; t < 4; t++) { best[t] = -3.4e38f; bidx[t] = 0; }

    for (int nc = 0; nc < 4; nc++) {
        float acc[2][8][4];
        #pragma unroll
        for (int i = 0; i < 2; i++)
            #pragma unroll
            for (int j = 0; j < 8; j++)
                #pragma unroll
                for (int r = 0; r < 4; r++) acc[i][j][r] = 0.f;

        for (int s = 0; s < 4; s++) {
            const int k0 = s*32;
            #pragma unroll
            for (int it = 0; it < 4; it++) {
                int l = tid + it*256;
                int m = l >> 3, kq = l & 7;
                float4 v = *reinterpret_cast<const float4*>(&f[(m0 + m)*128 + k0 + kq*4]);
                *reinterpret_cast<float4*>(&AsF[m*ASTR + kq*4]) = v;
            }
            #pragma unroll
            for (int it = 0; it < 4; it++) {
                int l = tid + it*256;
                int co = (l & 31)*4;
                int kk = l >> 5;
                float4 w = *reinterpret_cast<const float4*>(&embT[(k0 + kk)*512 + nc*128 + co]);
                uint4 h;
                h.x = f2tf32(w.x); h.y = f2tf32(w.y); h.z = f2tf32(w.z); h.w = f2tf32(w.w);
                *reinterpret_cast<uint4*>(&BsH[kk*BSTR + co]) = h;
                uint4 lo;
                lo.x = f2tf32(w.x - __uint_as_float(h.x));
                lo.y = f2tf32(w.y - __uint_as_float(h.y));
                lo.z = f2tf32(w.z - __uint_as_float(h.z));
                lo.w = f2tf32(w.w - __uint_as_float(h.w));
                *reinterpret_cast<uint4*>(&BsL[kk*BSTR + co]) = lo;
            }
            __syncthreads();
            #pragma unroll
            for (int ks = 0; ks < 32; ks += 8) {
                uint32_t ah[2][4], al[2][4];
                #pragma unroll
                for (int i = 0; i < 2; i++) {
                    int r = wm*32 + i*16 + lr;
                    float v0 = AsF[(r    )*ASTR + ks + lc];
                    float v1 = AsF[(r + 8)*ASTR + ks + lc];
                    float v2 = AsF[(r    )*ASTR + ks + lc + 4];
                    float v3 = AsF[(r + 8)*ASTR + ks + lc + 4];
                    ah[i][0] = f2tf32(v0); ah[i][1] = f2tf32(v1);
                    ah[i][2] = f2tf32(v2); ah[i][3] = f2tf32(v3);
                    al[i][0] = f2tf32(v0 - __uint_as_float(ah[i][0]));
                    al[i][1] = f2tf32(v1 - __uint_as_float(ah[i][1]));
                    al[i][2] = f2tf32(v2 - __uint_as_float(ah[i][2]));
                    al[i][3] = f2tf32(v3 - __uint_as_float(ah[i][3]));
                }
                #pragma unroll
                for (int j = 0; j < 8; j++) {
                    int c = wn*64 + j*8 + lr;
                    uint32_t bh[2], bl[2];
                    bh[0] = BsH[(ks + lc    )*BSTR + c];
                    bh[1] = BsH[(ks + lc + 4)*BSTR + c];
                    bl[0] = BsL[(ks + lc    )*BSTR + c];
                    bl[1] = BsL[(ks + lc + 4)*BSTR + c];
                    #pragma unroll
                    for (int i = 0; i < 2; i++) {
                        mma_tf32(acc[i][j], al[i], bh);
                        mma_tf32(acc[i][j], ah[i], bl);
                        mma_tf32(acc[i][j], ah[i], bh);
                    }
                }
            }
            __syncthreads();
        }
        #pragma unroll
        for (int i = 0; i < 2; i++) {
            #pragma unroll
            for (int half = 0; half < 2; half++) {
                int slot = i*2 + half;
                #pragma unroll
                for (int j = 0; j < 8; j++) {
                    int col = nc*128 + wn*64 + j*8 + 2*lc;
                    float s0 = acc[i][j][half*2 + 0] - __ldg(&ehalf[col]);
                    float s1 = acc[i][j][half*2 + 1] - __ldg(&ehalf[col + 1]);
                    if (s0 > best[slot] || (s0 == best[slot] && col < bidx[slot]))
                        { best[slot] = s0; bidx[slot] = col; }
                    if (s1 > best[slot] || (s1 == best[slot] && col + 1 < bidx[slot]))
                        { best[slot] = s1; bidx[slot] = col + 1; }
                }
            }
        }
    }
    #pragma unroll
    for (int slot = 0; slot < 4; slot++) {
        #pragma unroll
        for (int off = 1; off < 4; off <<= 1) {
            float ov = __shfl_xor_sync(0xffffffffu, best[slot], off);
            int   oi = __shfl_xor_sync(0xffffffffu, bidx[slot], off);
            if (ov > best[slot] || (ov == best[slot] && oi < bidx[slot]))
                { best[slot] = ov; bidx[slot] = oi; }
        }
        if (lc == 0) {
            int i = slot >> 1, half = slot & 1;
            int row = wm*32 + i*16 + half*8 + lr;
            bestV[row][wn] = best[slot];
            bestI[row][wn] = bidx[slot];
        }
    }
    __syncthreads();
    for (int r = tid; r < 128; r += 256) {
        float v0 = bestV[r][0], v1 = bestV[r][1];
        int   i0 = bestI[r][0], i1 = bestI[r][1];
        rowIdx[r] = (v1 > v0 || (v1 == v0 && i1 < i0)) ? i1 : i0;
    }
    __syncthreads();
    for (int l = tid; l < 128*128; l += 256) {
        int r = l >> 7, j = l & 127;
        q[(m0 + r)*128 + j] = emb[rowIdx[r]*128 + j];
    }
}

// ======================= dt2: 4x4 s2 tconv 64->3, direct =======================
__global__ void __launch_bounds__(256)
dt2_kernel(const float* __restrict__ in,
           const float* __restrict__ wgt,
           const float* __restrict__ bias,
           float* __restrict__ out)
{
    __shared__ float ws[4*4*64*3];
    for (int l = threadIdx.x; l < 3072; l += 256) ws[l] = wgt[l];
    __syncthreads();

    const int py = blockIdx.z >> 1, px = blockIdx.z & 1;
    const int m = blockIdx.x * 256 + threadIdx.x;
    const int xq = m & 127; int t = m >> 7; const int yq = t & 127; const int n = t >> 7;

    float a0 = __ldg(&bias[0]), a1 = __ldg(&bias[1]), a2 = __ldg(&bias[2]);
    #pragma unroll
    for (int aa = 0; aa < 2; aa++) {
        #pragma unroll
        for (int bb = 0; bb < 2; bb++) {
            int iy = yq + py + aa - 1;
            int ix = xq + px + bb - 1;
            if (iy < 0 || iy >= 128 || ix < 0 || ix >= 128) continue;
            const float* ip = in + ((n*128 + iy)*128 + ix)*64;
            const float* wp = ws + ((2*aa + py)*4 + (2*bb + px))*64*3;
            #pragma unroll
            for (int ci = 0; ci < 64; ci += 4) {
                float4 v = *reinterpret_cast<const float4*>(ip + ci);
                const float* w0 = wp + ci*3;
                a0 += v.x*w0[0];  a1 += v.x*w0[1];  a2 += v.x*w0[2];
                a0 += v.y*w0[3];  a1 += v.y*w0[4];  a2 += v.y*w0[5];
                a0 += v.z*w0[6];  a1 += v.z*w0[7];  a2 += v.z*w0[8];
                a0 += v.w*w0[9];  a1 += v.w*w0[10]; a2 += v.w*w0[11];
            }
        }
    }
    const int oy = 2*yq + py, ox = 2*xq + px;
    float* op = out + ((n*256 + oy)*256 + ox)*3;
    op[0] = a0; op[1] = a1; op[2] = a2;
}

// ======================= host launcher =======================
extern "C" void kernel_launch(void* const* d_in, const int* in_sizes, int n_in,
                              void* d_out, int out_size)
{
    (void)in_sizes; (void)n_in;
    const float* x       = (const float*)d_in[0];
    const float* emb     = (const float*)d_in[1];
    const float* enc_w1  = (const float*)d_in[2];
    const float* enc_b1  = (const float*)d_in[3];
    const float* enc_w2  = (const float*)d_in[4];
    const float* enc_b2  = (const float*)d_in[5];
    const float* enc_w3  = (const float*)d_in[6];
    const float* enc_b3  = (const float*)d_in[7];
    const float* erb1_w1 = (const float*)d_in[8];
    const float* erb1_w2 = (const float*)d_in[9];
    const float* erb2_w1 = (const float*)d_in[10];
    const float* erb2_w2 = (const float*)d_in[11];
    const float* dec_w   = (const float*)d_in[12];
    const float* dec_b   = (const float*)d_in[13];
    const float* drb1_w1 = (const float*)d_in[14];
    const float* drb1_w2 = (const float*)d_in[15];
    const float* drb2_w1 = (const float*)d_in[16];
    const float* drb2_w2 = (const float*)d_in[17];
    const float* dt1_w   = (const float*)d_in[18];
    const float* dt1_b   = (const float*)d_in[19];
    const float* dt2_w   = (const float*)d_in[20];
    const float* dt2_b   = (const float*)d_in[21];

    float* out = (float*)d_out;
    const int YS = 16*256*256*3;
    const int FS = 16*64*64*128;

    float *buf0,*buf1,*buf2,*tmpb,*embT,*ehalf,*fb,*qb;
    cudaGetSymbolAddress((void**)&buf0,  g_buf0);
    cudaGetSymbolAddress((void**)&buf1,  g_buf1);
    cudaGetSymbolAddress((void**)&buf2,  g_buf2);
    cudaGetSymbolAddress((void**)&tmpb,  g_tmpb);
    cudaGetSymbolAddress((void**)&embT,  g_embT);
    cudaGetSymbolAddress((void**)&ehalf, g_ehalf);
    cudaGetSymbolAddress((void**)&fb,    g_fbuf);
    cudaGetSymbolAddress((void**)&qb,    g_qbuf);

    const bool full = (out_size >= YS + 2*FS);
    float* fptr = full ? (out + YS)      : fb;
    float* qptr = full ? (out + YS + FS) : qb;

    dim3 b(256);

    // smem bytes: 2 x (A_raw 4608 + NCOPYB x B) words x 4B
    const int SM3_128 = 2*(4608 + 2*4352)*4;   // 106496
    const int SM3_32  = 2*(4608 + 2*1280)*4;   // 57344
    const int SM1_128 = 2*(4608 + 4352)*4;     // 71680
    const int SM1_64  = 2*(4608 + 2304)*4;     // 55296
    const int SM1_32  = 2*(4608 + 1280)*4;     // 47104
    const int SM_VQ   = (4608 + 2*4352)*4;     // 53248

    // ---- encoder (3xTF32) ----
    auto kEnc2 = mma_conv6<64,128,4,4,2,1, 128,128, false,true,false,true,false,3>;
    auto kEnc3 = mma_conv6<128,128,3,3,1,1, 64,64, false,true,false,false,false,3>;
    auto kEw1  = mma_conv6<128,32, 3,3,1,1, 64,64, true,false,false,true,false,3>;
    auto kEw2  = mma_conv6<32,128, 1,1,1,0, 64,64, false,false,true,false,false,3>;
    auto kEw2R = mma_conv6<32,128, 1,1,1,0, 64,64, false,false,true,true,false,3>;
    // ---- decoder (single-pass tf32) ----
    auto kDec  = mma_conv6<128,128,3,3,1,1, 64,64, false,true,false,false,false,1>;
    auto kDw1  = mma_conv6<128,32, 3,3,1,1, 64,64, true,false,false,true,false,1>;
    auto kDw2  = mma_conv6<32,128, 1,1,1,0, 64,64, false,false,true,false,false,1>;
    auto kDw2R = mma_conv6<32,128, 1,1,1,0, 64,64, false,false,true,true,false,1>;
    auto kDt1  = mma_conv6<128,64, 4,4,2,0, 64,64, false,true,false,true,true,1>;

    cudaFuncSetAttribute(kEnc2, cudaFuncAttributeMaxDynamicSharedMemorySize, SM3_128);
    cudaFuncSetAttribute(kEnc3, cudaFuncAttributeMaxDynamicSharedMemorySize, SM3_128);
    cudaFuncSetAttribute(kEw1,  cudaFuncAttributeMaxDynamicSharedMemorySize, SM3_32);
    cudaFuncSetAttribute(kEw2,  cudaFuncAttributeMaxDynamicSharedMemorySize, SM3_128);
    cudaFuncSetAttribute(kEw2R, cudaFuncAttributeMaxDynamicSharedMemorySize, SM3_128);
    cudaFuncSetAttribute(kDec,  cudaFuncAttributeMaxDynamicSharedMemorySize, SM1_128);
    cudaFuncSetAttribute(kDw1,  cudaFuncAttributeMaxDynamicSharedMemorySize, SM1_32);
    cudaFuncSetAttribute(kDw2,  cudaFuncAttributeMaxDynamicSharedMemorySize, SM1_128);
    cudaFuncSetAttribute(kDw2R, cudaFuncAttributeMaxDynamicSharedMemorySize, SM1_128);
    cudaFuncSetAttribute(kDt1,  cudaFuncAttributeMaxDynamicSharedMemorySize, SM1_64);
    cudaFuncSetAttribute(vq_mma, cudaFuncAttributeMaxDynamicSharedMemorySize, SM_VQ);

    // ---- encoder ----
    conv_gemm<64,64,16,4,4,  3,64,4,4,2,1, 256,256,16, false,true,false,true>
        <<<dim3(4096,1,1),b>>>(x, enc_w1, enc_b1, nullptr, buf0);
    kEnc2<<<dim3(512,1,1), b, SM3_128>>>(buf0, enc_w2, enc_b2, nullptr, buf1);
    kEnc3<<<dim3(512,1,1), b, SM3_128>>>(buf1, enc_w3, enc_b3, nullptr, buf2);
    kEw1 <<<dim3(512,1,1), b, SM3_32 >>>(buf2, erb1_w1, nullptr, nullptr, tmpb);
    kEw2 <<<dim3(512,1,1), b, SM3_128>>>(tmpb, erb1_w2, nullptr, buf2, buf2);
    kEw1 <<<dim3(512,1,1), b, SM3_32 >>>(buf2, erb2_w1, nullptr, nullptr, tmpb);
    kEw2R<<<dim3(512,1,1), b, SM3_128>>>(tmpb, erb2_w2, nullptr, buf2, fptr);

    // ---- VQ (3xTF32 scores, fp32 norms, full-codebook argmax) ----
    emb_prep<<<512,128>>>(emb, embT, ehalf);
    vq_mma<<<512, b, SM_VQ>>>(fptr, emb, embT, ehalf, qptr);

    // ---- decoder ----
    kDec <<<dim3(512,1,1), b, SM1_128>>>(qptr, dec_w, dec_b, nullptr, buf1);
    kDw1 <<<dim3(512,1,1), b, SM1_32 >>>(buf1, drb1_w1, nullptr, nullptr, tmpb);
    kDw2 <<<dim3(512,1,1), b, SM1_128>>>(tmpb, drb1_w2, nullptr, buf1, buf1);
    kDw1 <<<dim3(512,1,1), b, SM1_32 >>>(buf1, drb2_w1, nullptr, nullptr, tmpb);
    kDw2R<<<dim3(512,1,1), b, SM1_128>>>(tmpb, drb2_w2, nullptr, buf1, buf2);
    kDt1 <<<dim3(512,1,4), b, SM1_64 >>>(buf2, dt1_w, dt1_b, nullptr, buf0);

    dt2_kernel<<<dim3(1024,1,4),b>>>(buf0, dt2_w, dt2_b, out);
}

// round 12
// speedup vs baseline: 2.2307x; 1.0043x over previous
#include <cuda_runtime.h>
#include <cstdint>

// ======================= device scratch (no cudaMalloc allowed) =======================
__device__ float g_buf0[16*128*128*64];   // enc1 out / dt1 out
__device__ float g_buf1[16*64*64*128];
__device__ float g_buf2[16*64*64*128];
__device__ float g_tmpb[16*64*64*32];
__device__ float g_fbuf[16*64*64*128];
__device__ float g_qbuf[16*64*64*128];
__device__ float g_embT[128*512];
__device__ float g_ehalf[512];

__device__ __forceinline__ uint32_t f2tf32(float x) {
    uint32_t r; asm("cvt.rna.tf32.f32 %0, %1;" : "=r"(r) : "f"(x)); return r;
}
__device__ __forceinline__ void mma_tf32(float* d, const uint32_t* a, const uint32_t* b) {
    asm volatile(
        "mma.sync.aligned.m16n8k8.row.col.f32.tf32.tf32.f32 "
        "{%0,%1,%2,%3}, {%4,%5,%6,%7}, {%8,%9}, {%0,%1,%2,%3};"
        : "+f"(d[0]), "+f"(d[1]), "+f"(d[2]), "+f"(d[3])
        : "r"(a[0]), "r"(a[1]), "r"(a[2]), "r"(a[3]), "r"(b[0]), "r"(b[1]));
}

// ======================= fp32 tiled implicit-GEMM conv (enc1 only) =======================
template<int BM,int BN,int BK,int TM,int TN,
         int CIN,int COUT,int KH,int KW,int STRIDE,int PAD,
         int INH,int INW,int NB,
         bool RELU_IN,bool HAS_BIAS,bool ADD,bool RELU_OUT>
__global__ void __launch_bounds__(256)
conv_gemm(const float* __restrict__ in, const float* __restrict__ wgt,
          const float* __restrict__ bias, const float* __restrict__ addsrc,
          float* __restrict__ out)
{
    constexpr int MH = INH / STRIDE;
    constexpr int MW = INW / STRIDE;
    constexpr int K  = KH*KW*CIN;
    constexpr int THREADS = (BM/TM)*(BN/TN);
    static_assert(THREADS == 256, "block must be 256 threads");

    __shared__ __align__(16) float As[BK][BM+4];
    __shared__ __align__(16) float Bs[BK][BN];

    const int tid = threadIdx.x;
    const int m0  = blockIdx.x * BM;
    const int n0  = blockIdx.y * BN;

    const int tcol = tid % (BN/TN);
    const int trow = tid / (BN/TN);

    float acc[TM][TN];
    #pragma unroll
    for (int i = 0; i < TM; i++)
        #pragma unroll
        for (int j = 0; j < TN; j++) acc[i][j] = 0.f;

    for (int k0 = 0; k0 < K; k0 += BK) {
        #pragma unroll
        for (int i = 0; i < (BM*BK)/THREADS; i++) {
            int l = tid + i*THREADS;
            int mloc = l / BK, kloc = l % BK;
            int m = m0 + mloc;
            int k = k0 + kloc;
            int mx = m % MW; int t = m / MW; int my = t % MH; int n = t / MH;
            float v = 0.f;
            int ci = k % CIN; int r = k / CIN;
            int kw = r % KW, kh = r / KW;
            int iy = my*STRIDE - PAD + kh;
            int ix = mx*STRIDE - PAD + kw;
            if (iy >= 0 && iy < INH && ix >= 0 && ix < INW)
                v = in[((n*INH + iy)*INW + ix)*CIN + ci];
            if (RELU_IN) v = fmaxf(v, 0.f);
            As[kloc][mloc] = v;
        }
        #pragma unroll
        for (int i = 0; i < (BK*BN)/THREADS; i++) {
            int l = tid + i*THREADS;
            int kloc = l / BN, nloc = l % BN;
            int k = k0 + kloc;
            Bs[kloc][nloc] = wgt[k*COUT + n0 + nloc];
        }
        __syncthreads();
        #pragma unroll
        for (int kk = 0; kk < BK; kk++) {
            float ra[TM], rb[TN];
            #pragma unroll
            for (int i = 0; i < TM; i += 4) {
                float4 t4 = *reinterpret_cast<const float4*>(&As[kk][trow*TM + i]);
                ra[i]=t4.x; ra[i+1]=t4.y; ra[i+2]=t4.z; ra[i+3]=t4.w;
            }
            #pragma unroll
            for (int j = 0; j < TN; j += 4) {
                float4 t4 = *reinterpret_cast<const float4*>(&Bs[kk][tcol*TN + j]);
                rb[j]=t4.x; rb[j+1]=t4.y; rb[j+2]=t4.z; rb[j+3]=t4.w;
            }
            #pragma unroll
            for (int i = 0; i < TM; i++)
                #pragma unroll
                for (int j = 0; j < TN; j++)
                    acc[i][j] += ra[i]*rb[j];
        }
        __syncthreads();
    }
    #pragma unroll
    for (int i = 0; i < TM; i++) {
        int m = m0 + trow*TM + i;
        int obase = m*COUT;
        #pragma unroll
        for (int j = 0; j < TN; j++) {
            int c = n0 + tcol*TN + j;
            float v = acc[i][j];
            if (HAS_BIAS) v += bias[c];
            if (ADD)      v += addsrc[obase + c];
            if (RELU_OUT) v = fmaxf(v, 0.f);
            out[obase + c] = v;
        }
    }
}

// ====== tf32 mma.sync implicit-GEMM conv: A raw fp32 in smem (cvt at fragment read),
// B pre-converted hi/lo; ping-pong DB, one sync per slab. BM templated (128 or 256):
// BM=256 for BN=32 kernels doubles MF -> better MMA:LDS amortization.
template<int BM,int CIN,int COUT,int KH,int KW,int STRIDE,int PAD,int INH,int INW,
         bool RELU_IN,bool HAS_BIAS,bool ADD,bool RELU_OUT,bool TRANS,int SPLIT>
__global__ void __launch_bounds__(256)
mma_conv7(const float* __restrict__ in, const float* __restrict__ wgt,
          const float* __restrict__ bias, const float* __restrict__ addsrc,
          float* __restrict__ out)
{
    constexpr int MH = TRANS ? INH : INH / STRIDE;
    constexpr int MW = TRANS ? INW : INW / STRIDE;
    constexpr int K  = TRANS ? 4*CIN : KH*KW*CIN;
    constexpr int BK = 32, BN = COUT;
    constexpr int S  = K / BK;
    constexpr int WARPS_N = (BN >= 64) ? 2 : 1;
    constexpr int WARPS_M = 8 / WARPS_N;
    constexpr int WM = BM / WARPS_M;
    constexpr int WN = BN / WARPS_N;
    constexpr int MF = WM / 16;
    constexpr int NF = WN / 8;
    constexpr int ASTR = BK + 4;
    constexpr int BSTR = BN + 8;
    constexpr int A_WORDS = BM*ASTR;
    constexpr int B_WORDS = BK*BSTR;
    constexpr int NCOPYB = (SPLIT==3 ? 2 : 1);
    constexpr int CSZ = A_WORDS + NCOPYB*B_WORDS;
    constexpr int NAITER = BM/32;
    constexpr int NBREG = (BK*BN)/(4*256);

    extern __shared__ __align__(16) uint32_t smem[];

    const int tid  = threadIdx.x;
    const int wid  = tid >> 5;
    const int lane = tid & 31;
    const int m0   = blockIdx.x * BM;
    const int py   = TRANS ? (int)(blockIdx.z >> 1) : 0;
    const int px   = TRANS ? (int)(blockIdx.z & 1)  : 0;
    const int wm   = wid / WARPS_N;
    const int wn   = wid % WARPS_N;
    const int lr   = lane >> 2;
    const int lc   = lane & 3;

    float acc[MF][NF][4];
    #pragma unroll
    for (int i = 0; i < MF; i++)
        #pragma unroll
        for (int j = 0; j < NF; j++)
            #pragma unroll
            for (int r = 0; r < 4; r++) acc[i][j][r] = 0.f;

    float4 aR[NAITER];
    float4 bR[NBREG];

    auto load_regs = [&](int s) {
        const int k0 = s * BK;
        #pragma unroll
        for (int it = 0; it < NAITER; it++) {
            int l = tid + it*256;
            int m = l >> 3, kq = l & 7;
            int k = k0 + kq*4;
            int mg = m0 + m;
            int mx = mg % MW; int t = mg / MW; int my = t % MH; int n = t / MH;
            int iy, ix, ci;
            if (TRANS) {
                ci = k % CIN; int ab = k / CIN;
                int bb = ab & 1, aa = ab >> 1;
                iy = my + py + aa - 1;
                ix = mx + px + bb - 1;
            } else {
                ci = k % CIN; int r = k / CIN;
                int kw = r % KW, kh = r / KW;
                iy = my*STRIDE - PAD + kh;
                ix = mx*STRIDE - PAD + kw;
            }
            if (iy >= 0 && iy < INH && ix >= 0 && ix < INW)
                aR[it] = *reinterpret_cast<const float4*>(&in[((n*INH + iy)*INW + ix)*CIN + ci]);
            else
                aR[it] = make_float4(0.f,0.f,0.f,0.f);
        }
        #pragma unroll
        for (int it = 0; it < NBREG; it++) {
            int l = tid + it*256;
            int co = (l % (BN/4))*4;
            int kk = l / (BN/4);
            int k = k0 + kk;
            if (TRANS) {
                int ci = k % CIN; int ab = k / CIN;
                int bb = ab & 1, aa = ab >> 1;
                int widx = ((2*aa + py)*KW + (2*bb + px))*CIN + ci;
                bR[it] = *reinterpret_cast<const float4*>(&wgt[widx*COUT + co]);
            } else {
                bR[it] = *reinterpret_cast<const float4*>(&wgt[k*COUT + co]);
            }
        }
    };

    auto store_regs = [&](int buf) {
        float*    AsF = reinterpret_cast<float*>(smem + buf*CSZ);
        uint32_t* BsH = smem + buf*CSZ + A_WORDS;
        uint32_t* BsL = BsH + B_WORDS;
        #pragma unroll
        for (int it = 0; it < NAITER; it++) {
            int l = tid + it*256;
            int m = l >> 3, kq = l & 7;
            float4 v = aR[it];
            if (RELU_IN) {
                v.x = fmaxf(v.x, 0.f); v.y = fmaxf(v.y, 0.f);
                v.z = fmaxf(v.z, 0.f); v.w = fmaxf(v.w, 0.f);
            }
            *reinterpret_cast<float4*>(&AsF[m*ASTR + kq*4]) = v;
        }
        #pragma unroll
        for (int it = 0; it < NBREG; it++) {
            int l = tid + it*256;
            int co = (l % (BN/4))*4;
            int kk = l / (BN/4);
            float4 w = bR[it];
            uint4 h;
            h.x = f2tf32(w.x); h.y = f2tf32(w.y); h.z = f2tf32(w.z); h.w = f2tf32(w.w);
            *reinterpret_cast<uint4*>(&BsH[kk*BSTR + co]) = h;
            if (SPLIT == 3) {
                uint4 lo;
                lo.x = f2tf32(w.x - __uint_as_float(h.x));
                lo.y = f2tf32(w.y - __uint_as_float(h.y));
                lo.z = f2tf32(w.z - __uint_as_float(h.z));
                lo.w = f2tf32(w.w - __uint_as_float(h.w));
                *reinterpret_cast<uint4*>(&BsL[kk*BSTR + co]) = lo;
            }
        }
    };

    auto compute = [&](int buf) {
        const float*    AsF = reinterpret_cast<const float*>(smem + buf*CSZ);
        const uint32_t* BsH = smem + buf*CSZ + A_WORDS;
        const uint32_t* BsL = BsH + B_WORDS;
        #pragma unroll
        for (int ks = 0; ks < BK; ks += 8) {
            uint32_t ah[MF][4], al[MF][4];
            #pragma unroll
            for (int i = 0; i < MF; i++) {
                int r = wm*WM + i*16 + lr;
                float v0 = AsF[(r    )*ASTR + ks + lc];
                float v1 = AsF[(r + 8)*ASTR + ks + lc];
                float v2 = AsF[(r    )*ASTR + ks + lc + 4];
                float v3 = AsF[(r + 8)*ASTR + ks + lc + 4];
                ah[i][0] = f2tf32(v0); ah[i][1] = f2tf32(v1);
                ah[i][2] = f2tf32(v2); ah[i][3] = f2tf32(v3);
                if (SPLIT == 3) {
                    al[i][0] = f2tf32(v0 - __uint_as_float(ah[i][0]));
                    al[i][1] = f2tf32(v1 - __uint_as_float(ah[i][1]));
                    al[i][2] = f2tf32(v2 - __uint_as_float(ah[i][2]));
                    al[i][3] = f2tf32(v3 - __uint_as_float(ah[i][3]));
                }
            }
            #pragma unroll
            for (int j = 0; j < NF; j++) {
                int c = wn*WN + j*8 + lr;
                uint32_t bh[2], bl[2];
                bh[0] = BsH[(ks + lc    )*BSTR + c];
                bh[1] = BsH[(ks + lc + 4)*BSTR + c];
                if (SPLIT == 3) {
                    bl[0] = BsL[(ks + lc    )*BSTR + c];
                    bl[1] = BsL[(ks + lc + 4)*BSTR + c];
                }
                #pragma unroll
                for (int i = 0; i < MF; i++) {
                    if (SPLIT == 3) {
                        mma_tf32(acc[i][j], al[i], bh);
                        mma_tf32(acc[i][j], ah[i], bl);
                    }
                    mma_tf32(acc[i][j], ah[i], bh);
                }
            }
        }
    };

    load_regs(0);
    store_regs(0);
    __syncthreads();
    for (int s = 0; s < S; s++) {
        if (s + 1 < S) load_regs(s + 1);
        compute(s & 1);
        if (s + 1 < S) store_regs((s + 1) & 1);
        __syncthreads();
    }

    // ---- epilogue ----
    #pragma unroll
    for (int i = 0; i < MF; i++) {
        int r0 = m0 + wm*WM + i*16 + lr;
        #pragma unroll
        for (int half = 0; half < 2; half++) {
            int mg = r0 + half*8;
            int obase;
            if (TRANS) {
                int mx = mg % MW; int t = mg / MW; int my = t % MH; int n = t / MH;
                obase = ((n*(2*INH) + 2*my + py)*(2*INW) + 2*mx + px)*COUT;
            } else {
                obase = mg*COUT;
            }
            #pragma unroll
            for (int j = 0; j < NF; j++) {
                int c = wn*WN + j*8 + 2*lc;
                float v0 = acc[i][j][half*2 + 0];
                float v1 = acc[i][j][half*2 + 1];
                if (HAS_BIAS) {
                    float2 bv = *reinterpret_cast<const float2*>(&bias[c]);
                    v0 += bv.x; v1 += bv.y;
                }
                if (ADD) {
                    float2 av = *reinterpret_cast<const float2*>(&addsrc[obase + c]);
                    v0 += av.x; v1 += av.y;
                }
                if (RELU_OUT) { v0 = fmaxf(v0, 0.f); v1 = fmaxf(v1, 0.f); }
                float2 ov; ov.x = v0; ov.y = v1;
                *reinterpret_cast<float2*>(&out[obase + c]) = ov;
            }
        }
    }
}

// ======================= codebook prep =======================
__global__ void emb_prep(const float* __restrict__ emb,
                         float* __restrict__ embT, float* __restrict__ ehalf)
{
    int c = blockIdx.x;
    int k = threadIdx.x;
    float v = emb[c*128 + k];
    embT[k*512 + c] = v;
    float s = v*v;
    #pragma unroll
    for (int o = 16; o; o >>= 1) s += __shfl_xor_sync(0xffffffffu, s, o);
    __shared__ float red[4];
    if ((k & 31) == 0) red[k >> 5] = s;
    __syncthreads();
    if (k == 0) ehalf[c] = 0.5f*(red[0]+red[1]+red[2]+red[3]);
}

// ======================= VQ via 3xTF32 tensor GEMM + fragment argmax =======================
__global__ void __launch_bounds__(256)
vq_mma(const float* __restrict__ f, const float* __restrict__ emb,
       const float* __restrict__ embT, const float* __restrict__ ehalf,
       float* __restrict__ q)
{
    constexpr int ASTR = 36, BSTR = 136;
    constexpr int A_WORDS = 128*ASTR, B_WORDS = 32*BSTR;
    extern __shared__ __align__(16) uint32_t vsm[];
    float*    AsF = reinterpret_cast<float*>(vsm);
    uint32_t* BsH = vsm + A_WORDS;
    uint32_t* BsL = BsH + B_WORDS;
    __shared__ float bestV[128][2];
    __shared__ int   bestI[128][2];
    __shared__ int   rowIdx[128];

    const int tid  = threadIdx.x;
    const int wid  = tid >> 5;
    const int lane = tid & 31;
    const int lr   = lane >> 2;
    const int lc   = lane & 3;
    const int m0   = blockIdx.x * 128;
    const int wm   = wid >> 1;
    const int wn   = wid & 1;

    float best[4];
    int   bidx[4];
    #pragma unroll
    for (int t = 0; t < 4; t++) { best[t] = -3.4e38f; bidx[t] = 0; }

    for (int nc = 0; nc < 4; nc++) {
        float acc[2][8][4];
        #pragma unroll
        for (int i = 0; i < 2; i++)
            #pragma unroll
            for (int j = 0; j < 8; j++)
                #pragma unroll
                for (int r = 0; r < 4; r++) acc[i][j][r] = 0.f;

        for (int s = 0; s < 4; s++) {
            const int k0 = s*32;
            #pragma unroll
            for (int it = 0; it < 4; it++) {
                int l = tid + it*256;
                int m = l >> 3, kq = l & 7;
                float4 v = *reinterpret_cast<const float4*>(&f[(m0 + m)*128 + k0 + kq*4]);
                *reinterpret_cast<float4*>(&AsF[m*ASTR + kq*4]) = v;
            }
            #pragma unroll
            for (int it = 0; it < 4; it++) {
                int l = tid + it*256;
                int co = (l & 31)*4;
                int kk = l >> 5;
                float4 w = *reinterpret_cast<const float4*>(&embT[(k0 + kk)*512 + nc*128 + co]);
                uint4 h;
                h.x = f2tf32(w.x); h.y = f2tf32(w.y); h.z = f2tf32(w.z); h.w = f2tf32(w.w);
                *reinterpret_cast<uint4*>(&BsH[kk*BSTR + co]) = h;
                uint4 lo;
                lo.x = f2tf32(w.x - __uint_as_float(h.x));
                lo.y = f2tf32(w.y - __uint_as_float(h.y));
                lo.z = f2tf32(w.z - __uint_as_float(h.z));
                lo.w = f2tf32(w.w - __uint_as_float(h.w));
                *reinterpret_cast<uint4*>(&BsL[kk*BSTR + co]) = lo;
            }
            __syncthreads();
            #pragma unroll
            for (int ks = 0; ks < 32; ks += 8) {
                uint32_t ah[2][4], al[2][4];
                #pragma unroll
                for (int i = 0; i < 2; i++) {
                    int r = wm*32 + i*16 + lr;
                    float v0 = AsF[(r    )*ASTR + ks + lc];
                    float v1 = AsF[(r + 8)*ASTR + ks + lc];
                    float v2 = AsF[(r    )*ASTR + ks + lc + 4];
                    float v3 = AsF[(r + 8)*ASTR + ks + lc + 4];
                    ah[i][0] = f2tf32(v0); ah[i][1] = f2tf32(v1);
                    ah[i][2] = f2tf32(v2); ah[i][3] = f2tf32(v3);
                    al[i][0] = f2tf32(v0 - __uint_as_float(ah[i][0]));
                    al[i][1] = f2tf32(v1 - __uint_as_float(ah[i][1]));
                    al[i][2] = f2tf32(v2 - __uint_as_float(ah[i][2]));
                    al[i][3] = f2tf32(v3 - __uint_as_float(ah[i][3]));
                }
                #pragma unroll
                for (int j = 0; j < 8; j++) {
                    int c = wn*64 + j*8 + lr;
                    uint32_t bh[2], bl[2];
                    bh[0] = BsH[(ks + lc    )*BSTR + c];
                    bh[1] = BsH[(ks + lc + 4)*BSTR + c];
                    bl[0] = BsL[(ks + lc    )*BSTR + c];
                    bl[1] = BsL[(ks + lc + 4)*BSTR + c];
                    #pragma unroll
                    for (int i = 0; i < 2; i++) {
                        mma_tf32(acc[i][j], al[i], bh);
                        mma_tf32(acc[i][j], ah[i], bl);
                        mma_tf32(acc[i][j], ah[i], bh);
                    }
                }
            }
            __syncthreads();
        }
        #pragma unroll
        for (int i = 0; i < 2; i++) {
            #pragma unroll
            for (int half = 0; half < 2; half++) {
                int slot = i*2 + half;
                #pragma unroll
                for (int j = 0; j < 8; j++) {
                    int col = nc*128 + wn*64 + j*8 + 2*lc;
                    float s0 = acc[i][j][half*2 + 0] - __ldg(&ehalf[col]);
                    float s1 = acc[i][j][half*2 + 1] - __ldg(&ehalf[col + 1]);
                    if (s0 > best[slot] || (s0 == best[slot] && col < bidx[slot]))
                        { best[slot] = s0; bidx[slot] = col; }
                    if (s1 > best[slot] || (s1 == best[slot] && col + 1 < bidx[slot]))
                        { best[slot] = s1; bidx[slot] = col + 1; }
                }
            }
        }
    }
    #pragma unroll
    for (int slot = 0; slot < 4; slot++) {
        #pragma unroll
        for (int off = 1; off < 4; off <<= 1) {
            float ov = __shfl_xor_sync(0xffffffffu, best[slot], off);
            int   oi = __shfl_xor_sync(0xffffffffu, bidx[slot], off);
            if (ov > best[slot] || (ov == best[slot] && oi < bidx[slot]))
                { best[slot] = ov; bidx[slot] = oi; }
        }
        if (lc == 0) {
            int i = slot >> 1, half = slot & 1;
            int row = wm*32 + i*16 + half*8 + lr;
            bestV[row][wn] = best[slot];
            bestI[row][wn] = bidx[slot];
        }
    }
    __syncthreads();
    for (int r = tid; r < 128; r += 256) {
        float v0 = bestV[r][0], v1 = bestV[r][1];
        int   i0 = bestI[r][0], i1 = bestI[r][1];
        rowIdx[r] = (v1 > v0 || (v1 == v0 && i1 < i0)) ? i1 : i0;
    }
    __syncthreads();
    for (int l = tid; l < 128*128; l += 256) {
        int r = l >> 7, j = l & 127;
        q[(m0 + r)*128 + j] = emb[rowIdx[r]*128 + j];
    }
}

// ======================= dt2: 4x4 s2 tconv 64->3, direct =======================
__global__ void __launch_bounds__(256)
dt2_kernel(const float* __restrict__ in,
           const float* __restrict__ wgt,
           const float* __restrict__ bias,
           float* __restrict__ out)
{
    __shared__ float ws[4*4*64*3];
    for (int l = threadIdx.x; l < 3072; l += 256) ws[l] = wgt[l];
    __syncthreads();

    const int py = blockIdx.z >> 1, px = blockIdx.z & 1;
    const int m = blockIdx.x * 256 + threadIdx.x;
    const int xq = m & 127; int t = m >> 7; const int yq = t & 127; const int n = t >> 7;

    float a0 = __ldg(&bias[0]), a1 = __ldg(&bias[1]), a2 = __ldg(&bias[2]);
    #pragma unroll
    for (int aa = 0; aa < 2; aa++) {
        #pragma unroll
        for (int bb = 0; bb < 2; bb++) {
            int iy = yq + py + aa - 1;
            int ix = xq + px + bb - 1;
            if (iy < 0 || iy >= 128 || ix < 0 || ix >= 128) continue;
            const float* ip = in + ((n*128 + iy)*128 + ix)*64;
            const float* wp = ws + ((2*aa + py)*4 + (2*bb + px))*64*3;
            #pragma unroll
            for (int ci = 0; ci < 64; ci += 4) {
                float4 v = *reinterpret_cast<const float4*>(ip + ci);
                const float* w0 = wp + ci*3;
                a0 += v.x*w0[0];  a1 += v.x*w0[1];  a2 += v.x*w0[2];
                a0 += v.y*w0[3];  a1 += v.y*w0[4];  a2 += v.y*w0[5];
                a0 += v.z*w0[6];  a1 += v.z*w0[7];  a2 += v.z*w0[8];
                a0 += v.w*w0[9];  a1 += v.w*w0[10]; a2 += v.w*w0[11];
            }
        }
    }
    const int oy = 2*yq + py, ox = 2*xq + px;
    float* op = out + ((n*256 + oy)*256 + ox)*3;
    op[0] = a0; op[1] = a1; op[2] = a2;
}

// ======================= host launcher =======================
extern "C" void kernel_launch(void* const* d_in, const int* in_sizes, int n_in,
                              void* d_out, int out_size)
{
    (void)in_sizes; (void)n_in;
    const float* x       = (const float*)d_in[0];
    const float* emb     = (const float*)d_in[1];
    const float* enc_w1  = (const float*)d_in[2];
    const float* enc_b1  = (const float*)d_in[3];
    const float* enc_w2  = (const float*)d_in[4];
    const float* enc_b2  = (const float*)d_in[5];
    const float* enc_w3  = (const float*)d_in[6];
    const float* enc_b3  = (const float*)d_in[7];
    const float* erb1_w1 = (const float*)d_in[8];
    const float* erb1_w2 = (const float*)d_in[9];
    const float* erb2_w1 = (const float*)d_in[10];
    const float* erb2_w2 = (const float*)d_in[11];
    const float* dec_w   = (const float*)d_in[12];
    const float* dec_b   = (const float*)d_in[13];
    const float* drb1_w1 = (const float*)d_in[14];
    const float* drb1_w2 = (const float*)d_in[15];
    const float* drb2_w1 = (const float*)d_in[16];
    const float* drb2_w2 = (const float*)d_in[17];
    const float* dt1_w   = (const float*)d_in[18];
    const float* dt1_b   = (const float*)d_in[19];
    const float* dt2_w   = (const float*)d_in[20];
    const float* dt2_b   = (const float*)d_in[21];

    float* out = (float*)d_out;
    const int YS = 16*256*256*3;
    const int FS = 16*64*64*128;

    float *buf0,*buf1,*buf2,*tmpb,*embT,*ehalf,*fb,*qb;
    cudaGetSymbolAddress((void**)&buf0,  g_buf0);
    cudaGetSymbolAddress((void**)&buf1,  g_buf1);
    cudaGetSymbolAddress((void**)&buf2,  g_buf2);
    cudaGetSymbolAddress((void**)&tmpb,  g_tmpb);
    cudaGetSymbolAddress((void**)&embT,  g_embT);
    cudaGetSymbolAddress((void**)&ehalf, g_ehalf);
    cudaGetSymbolAddress((void**)&fb,    g_fbuf);
    cudaGetSymbolAddress((void**)&qb,    g_qbuf);

    const bool full = (out_size >= YS + 2*FS);
    float* fptr = full ? (out + YS)      : fb;
    float* qptr = full ? (out + YS + FS) : qb;

    dim3 b(256);

    // smem bytes: 2 x (A_raw + NCOPYB x B) words x 4B
    const int SM3_128 = 2*(4608 + 2*4352)*4;    // 106496  (BM=128)
    const int SM3_32  = 2*(9216 + 2*1280)*4;    // 94208   (BM=256, BN=32)
    const int SM1_128 = 2*(4608 + 4352)*4;      // 71680
    const int SM1_64  = 2*(4608 + 2304)*4;      // 55296
    const int SM1_32  = 2*(9216 + 1280)*4;      // 83968   (BM=256, BN=32)
    const int SM_VQ   = (4608 + 2*4352)*4;      // 53248

    // ---- encoder (3xTF32) ----
    auto kEnc2 = mma_conv7<128, 64,128,4,4,2,1, 128,128, false,true,false,true,false,3>;
    auto kEnc3 = mma_conv7<128, 128,128,3,3,1,1, 64,64, false,true,false,false,false,3>;
    auto kEw1  = mma_conv7<256, 128,32, 3,3,1,1, 64,64, true,false,false,true,false,3>;
    auto kEw2  = mma_conv7<128, 32,128, 1,1,1,0, 64,64, false,false,true,false,false,3>;
    auto kEw2R = mma_conv7<128, 32,128, 1,1,1,0, 64,64, false,false,true,true,false,3>;
    // ---- decoder (single-pass tf32) ----
    auto kDec  = mma_conv7<128, 128,128,3,3,1,1, 64,64, false,true,false,false,false,1>;
    auto kDw1  = mma_conv7<256, 128,32, 3,3,1,1, 64,64, true,false,false,true,false,1>;
    auto kDw2  = mma_conv7<128, 32,128, 1,1,1,0, 64,64, false,false,true,false,false,1>;
    auto kDw2R = mma_conv7<128, 32,128, 1,1,1,0, 64,64, false,false,true,true,false,1>;
    auto kDt1  = mma_conv7<128, 128,64, 4,4,2,0, 64,64, false,true,false,true,true,1>;

    cudaFuncSetAttribute(kEnc2, cudaFuncAttributeMaxDynamicSharedMemorySize, SM3_128);
    cudaFuncSetAttribute(kEnc3, cudaFuncAttributeMaxDynamicSharedMemorySize, SM3_128);
    cudaFuncSetAttribute(kEw1,  cudaFuncAttributeMaxDynamicSharedMemorySize, SM3_32);
    cudaFuncSetAttribute(kEw2,  cudaFuncAttributeMaxDynamicSharedMemorySize, SM3_128);
    cudaFuncSetAttribute(kEw2R, cudaFuncAttributeMaxDynamicSharedMemorySize, SM3_128);
    cudaFuncSetAttribute(kDec,  cudaFuncAttributeMaxDynamicSharedMemorySize, SM1_128);
    cudaFuncSetAttribute(kDw1,  cudaFuncAttributeMaxDynamicSharedMemorySize, SM1_32);
    cudaFuncSetAttribute(kDw2,  cudaFuncAttributeMaxDynamicSharedMemorySize, SM1_128);
    cudaFuncSetAttribute(kDw2R, cudaFuncAttributeMaxDynamicSharedMemorySize, SM1_128);
    cudaFuncSetAttribute(kDt1,  cudaFuncAttributeMaxDynamicSharedMemorySize, SM1_64);
    cudaFuncSetAttribute(vq_mma, cudaFuncAttributeMaxDynamicSharedMemorySize, SM_VQ);

    // ---- encoder ----
    conv_gemm<64,64,16,4,4,  3,64,4,4,2,1, 256,256,16, false,true,false,true>
        <<<dim3(4096,1,1),b>>>(x, enc_w1, enc_b1, nullptr, buf0);
    kEnc2<<<dim3(512,1,1), b, SM3_128>>>(buf0, enc_w2, enc_b2, nullptr, buf1);
    kEnc3<<<dim3(512,1,1), b, SM3_128>>>(buf1, enc_w3, enc_b3, nullptr, buf2);
    kEw1 <<<dim3(256,1,1), b, SM3_32 >>>(buf2, erb1_w1, nullptr, nullptr, tmpb);
    kEw2 <<<dim3(512,1,1), b, SM3_128>>>(tmpb, erb1_w2, nullptr, buf2, buf2);
    kEw1 <<<dim3(256,1,1), b, SM3_32 >>>(buf2, erb2_w1, nullptr, nullptr, tmpb);
    kEw2R<<<dim3(512,1,1), b, SM3_128>>>(tmpb, erb2_w2, nullptr, buf2, fptr);

    // ---- VQ (3xTF32 scores, fp32 norms, full-codebook argmax) ----
    emb_prep<<<512,128>>>(emb, embT, ehalf);
    vq_mma<<<512, b, SM_VQ>>>(fptr, emb, embT, ehalf, qptr);

    // ---- decoder ----
    kDec <<<dim3(512,1,1), b, SM1_128>>>(qptr, dec_w, dec_b, nullptr, buf1);
    kDw1 <<<dim3(256,1,1), b, SM1_32 >>>(buf1, drb1_w1, nullptr, nullptr, tmpb);
    kDw2 <<<dim3(512,1,1), b, SM1_128>>>(tmpb, drb1_w2, nullptr, buf1, buf1);
    kDw1 <<<dim3(256,1,1), b, SM1_32 >>>(buf1, drb2_w1, nullptr, nullptr, tmpb);
    kDw2R<<<dim3(512,1,1), b, SM1_128>>>(tmpb, drb2_w2, nullptr, buf1, buf2);
    kDt1 <<<dim3(512,1,4), b, SM1_64 >>>(buf2, dt1_w, dt1_b, nullptr, buf0);

    dt2_kernel<<<dim3(1024,1,4),b>>>(buf0, dt2_w, dt2_b, out);
}

// round 13
// speedup vs baseline: 2.2850x; 1.0243x over previous
#include <cuda_runtime.h>
#include <cstdint>

// ======================= device scratch (no cudaMalloc allowed) =======================
__device__ float g_buf0[16*128*128*64];   // enc1 out / dt1 out
__device__ float g_buf1[16*64*64*128];
__device__ float g_buf2[16*64*64*128];
__device__ float g_tmpb[16*64*64*32];
__device__ float g_fbuf[16*64*64*128];
__device__ float g_qbuf[16*64*64*128];
__device__ float g_embT[128*512];
__device__ float g_ehalf[512];

__device__ __forceinline__ uint32_t f2tf32(float x) {
    uint32_t r; asm("cvt.rna.tf32.f32 %0, %1;" : "=r"(r) : "f"(x)); return r;
}
__device__ __forceinline__ void mma_tf32(float* d, const uint32_t* a, const uint32_t* b) {
    asm volatile(
        "mma.sync.aligned.m16n8k8.row.col.f32.tf32.tf32.f32 "
        "{%0,%1,%2,%3}, {%4,%5,%6,%7}, {%8,%9}, {%0,%1,%2,%3};"
        : "+f"(d[0]), "+f"(d[1]), "+f"(d[2]), "+f"(d[3])
        : "r"(a[0]), "r"(a[1]), "r"(a[2]), "r"(a[3]), "r"(b[0]), "r"(b[1]));
}

// ======================= fp32 tiled implicit-GEMM conv (enc1 only) =======================
template<int BM,int BN,int BK,int TM,int TN,
         int CIN,int COUT,int KH,int KW,int STRIDE,int PAD,
         int INH,int INW,int NB,
         bool RELU_IN,bool HAS_BIAS,bool ADD,bool RELU_OUT>
__global__ void __launch_bounds__(256)
conv_gemm(const float* __restrict__ in, const float* __restrict__ wgt,
          const float* __restrict__ bias, const float* __restrict__ addsrc,
          float* __restrict__ out)
{
    constexpr int MH = INH / STRIDE;
    constexpr int MW = INW / STRIDE;
    constexpr int K  = KH*KW*CIN;
    constexpr int THREADS = (BM/TM)*(BN/TN);
    static_assert(THREADS == 256, "block must be 256 threads");

    __shared__ __align__(16) float As[BK][BM+4];
    __shared__ __align__(16) float Bs[BK][BN];

    const int tid = threadIdx.x;
    const int m0  = blockIdx.x * BM;
    const int n0  = blockIdx.y * BN;

    const int tcol = tid % (BN/TN);
    const int trow = tid / (BN/TN);

    float acc[TM][TN];
    #pragma unroll
    for (int i = 0; i < TM; i++)
        #pragma unroll
        for (int j = 0; j < TN; j++) acc[i][j] = 0.f;

    for (int k0 = 0; k0 < K; k0 += BK) {
        #pragma unroll
        for (int i = 0; i < (BM*BK)/THREADS; i++) {
            int l = tid + i*THREADS;
            int mloc = l / BK, kloc = l % BK;
            int m = m0 + mloc;
            int k = k0 + kloc;
            int mx = m % MW; int t = m / MW; int my = t % MH; int n = t / MH;
            float v = 0.f;
            int ci = k % CIN; int r = k / CIN;
            int kw = r % KW, kh = r / KW;
            int iy = my*STRIDE - PAD + kh;
            int ix = mx*STRIDE - PAD + kw;
            if (iy >= 0 && iy < INH && ix >= 0 && ix < INW)
                v = in[((n*INH + iy)*INW + ix)*CIN + ci];
            if (RELU_IN) v = fmaxf(v, 0.f);
            As[kloc][mloc] = v;
        }
        #pragma unroll
        for (int i = 0; i < (BK*BN)/THREADS; i++) {
            int l = tid + i*THREADS;
            int kloc = l / BN, nloc = l % BN;
            int k = k0 + kloc;
            Bs[kloc][nloc] = wgt[k*COUT + n0 + nloc];
        }
        __syncthreads();
        #pragma unroll
        for (int kk = 0; kk < BK; kk++) {
            float ra[TM], rb[TN];
            #pragma unroll
            for (int i = 0; i < TM; i += 4) {
                float4 t4 = *reinterpret_cast<const float4*>(&As[kk][trow*TM + i]);
                ra[i]=t4.x; ra[i+1]=t4.y; ra[i+2]=t4.z; ra[i+3]=t4.w;
            }
            #pragma unroll
            for (int j = 0; j < TN; j += 4) {
                float4 t4 = *reinterpret_cast<const float4*>(&Bs[kk][tcol*TN + j]);
                rb[j]=t4.x; rb[j+1]=t4.y; rb[j+2]=t4.z; rb[j+3]=t4.w;
            }
            #pragma unroll
            for (int i = 0; i < TM; i++)
                #pragma unroll
                for (int j = 0; j < TN; j++)
                    acc[i][j] += ra[i]*rb[j];
        }
        __syncthreads();
    }
    #pragma unroll
    for (int i = 0; i < TM; i++) {
        int m = m0 + trow*TM + i;
        int obase = m*COUT;
        #pragma unroll
        for (int j = 0; j < TN; j++) {
            int c = n0 + tcol*TN + j;
            float v = acc[i][j];
            if (HAS_BIAS) v += bias[c];
            if (ADD)      v += addsrc[obase + c];
            if (RELU_OUT) v = fmaxf(v, 0.f);
            out[obase + c] = v;
        }
    }
}

// ====== tf32 mma.sync implicit-GEMM conv: A raw fp32 in smem (cvt at fragment read),
// B pre-converted hi/lo; ping-pong DB, one sync per slab. BM templated (128 or 256).
template<int BM,int CIN,int COUT,int KH,int KW,int STRIDE,int PAD,int INH,int INW,
         bool RELU_IN,bool HAS_BIAS,bool ADD,bool RELU_OUT,bool TRANS,int SPLIT>
__global__ void __launch_bounds__(256)
mma_conv7(const float* __restrict__ in, const float* __restrict__ wgt,
          const float* __restrict__ bias, const float* __restrict__ addsrc,
          float* __restrict__ out)
{
    constexpr int MH = TRANS ? INH : INH / STRIDE;
    constexpr int MW = TRANS ? INW : INW / STRIDE;
    constexpr int K  = TRANS ? 4*CIN : KH*KW*CIN;
    constexpr int BK = 32, BN = COUT;
    constexpr int S  = K / BK;
    constexpr int WARPS_N = (BN >= 64) ? 2 : 1;
    constexpr int WARPS_M = 8 / WARPS_N;
    constexpr int WM = BM / WARPS_M;
    constexpr int WN = BN / WARPS_N;
    constexpr int MF = WM / 16;
    constexpr int NF = WN / 8;
    constexpr int ASTR = BK + 4;
    constexpr int BSTR = BN + 8;
    constexpr int A_WORDS = BM*ASTR;
    constexpr int B_WORDS = BK*BSTR;
    constexpr int NCOPYB = (SPLIT==3 ? 2 : 1);
    constexpr int CSZ = A_WORDS + NCOPYB*B_WORDS;
    constexpr int NAITER = BM/32;
    constexpr int NBREG = (BK*BN)/(4*256);

    extern __shared__ __align__(16) uint32_t smem[];

    const int tid  = threadIdx.x;
    const int wid  = tid >> 5;
    const int lane = tid & 31;
    const int m0   = blockIdx.x * BM;
    const int py   = TRANS ? (int)(blockIdx.z >> 1) : 0;
    const int px   = TRANS ? (int)(blockIdx.z & 1)  : 0;
    const int wm   = wid / WARPS_N;
    const int wn   = wid % WARPS_N;
    const int lr   = lane >> 2;
    const int lc   = lane & 3;

    float acc[MF][NF][4];
    #pragma unroll
    for (int i = 0; i < MF; i++)
        #pragma unroll
        for (int j = 0; j < NF; j++)
            #pragma unroll
            for (int r = 0; r < 4; r++) acc[i][j][r] = 0.f;

    float4 aR[NAITER];
    float4 bR[NBREG];

    auto load_regs = [&](int s) {
        const int k0 = s * BK;
        #pragma unroll
        for (int it = 0; it < NAITER; it++) {
            int l = tid + it*256;
            int m = l >> 3, kq = l & 7;
            int k = k0 + kq*4;
            int mg = m0 + m;
            int mx = mg % MW; int t = mg / MW; int my = t % MH; int n = t / MH;
            int iy, ix, ci;
            if (TRANS) {
                ci = k % CIN; int ab = k / CIN;
                int bb = ab & 1, aa = ab >> 1;
                iy = my + py + aa - 1;
                ix = mx + px + bb - 1;
            } else {
                ci = k % CIN; int r = k / CIN;
                int kw = r % KW, kh = r / KW;
                iy = my*STRIDE - PAD + kh;
                ix = mx*STRIDE - PAD + kw;
            }
            if (iy >= 0 && iy < INH && ix >= 0 && ix < INW)
                aR[it] = *reinterpret_cast<const float4*>(&in[((n*INH + iy)*INW + ix)*CIN + ci]);
            else
                aR[it] = make_float4(0.f,0.f,0.f,0.f);
        }
        #pragma unroll
        for (int it = 0; it < NBREG; it++) {
            int l = tid + it*256;
            int co = (l % (BN/4))*4;
            int kk = l / (BN/4);
            int k = k0 + kk;
            if (TRANS) {
                int ci = k % CIN; int ab = k / CIN;
                int bb = ab & 1, aa = ab >> 1;
                int widx = ((2*aa + py)*KW + (2*bb + px))*CIN + ci;
                bR[it] = *reinterpret_cast<const float4*>(&wgt[widx*COUT + co]);
            } else {
                bR[it] = *reinterpret_cast<const float4*>(&wgt[k*COUT + co]);
            }
        }
    };

    auto store_regs = [&](int buf) {
        float*    AsF = reinterpret_cast<float*>(smem + buf*CSZ);
        uint32_t* BsH = smem + buf*CSZ + A_WORDS;
        uint32_t* BsL = BsH + B_WORDS;
        #pragma unroll
        for (int it = 0; it < NAITER; it++) {
            int l = tid + it*256;
            int m = l >> 3, kq = l & 7;
            float4 v = aR[it];
            if (RELU_IN) {
                v.x = fmaxf(v.x, 0.f); v.y = fmaxf(v.y, 0.f);
                v.z = fmaxf(v.z, 0.f); v.w = fmaxf(v.w, 0.f);
            }
            *reinterpret_cast<float4*>(&AsF[m*ASTR + kq*4]) = v;
        }
        #pragma unroll
        for (int it = 0; it < NBREG; it++) {
            int l = tid + it*256;
            int co = (l % (BN/4))*4;
            int kk = l / (BN/4);
            float4 w = bR[it];
            uint4 h;
            h.x = f2tf32(w.x); h.y = f2tf32(w.y); h.z = f2tf32(w.z); h.w = f2tf32(w.w);
            *reinterpret_cast<uint4*>(&BsH[kk*BSTR + co]) = h;
            if (SPLIT == 3) {
                uint4 lo;
                lo.x = f2tf32(w.x - __uint_as_float(h.x));
                lo.y = f2tf32(w.y - __uint_as_float(h.y));
                lo.z = f2tf32(w.z - __uint_as_float(h.z));
                lo.w = f2tf32(w.w - __uint_as_float(h.w));
                *reinterpret_cast<uint4*>(&BsL[kk*BSTR + co]) = lo;
            }
        }
    };

    auto compute = [&](int buf) {
        const float*    AsF = reinterpret_cast<const float*>(smem + buf*CSZ);
        const uint32_t* BsH = smem + buf*CSZ + A_WORDS;
        const uint32_t* BsL = BsH + B_WORDS;
        #pragma unroll
        for (int ks = 0; ks < BK; ks += 8) {
            uint32_t ah[MF][4], al[MF][4];
            #pragma unroll
            for (int i = 0; i < MF; i++) {
                int r = wm*WM + i*16 + lr;
                float v0 = AsF[(r    )*ASTR + ks + lc];
                float v1 = AsF[(r + 8)*ASTR + ks + lc];
                float v2 = AsF[(r    )*ASTR + ks + lc + 4];
                float v3 = AsF[(r + 8)*ASTR + ks + lc + 4];
                ah[i][0] = f2tf32(v0); ah[i][1] = f2tf32(v1);
                ah[i][2] = f2tf32(v2); ah[i][3] = f2tf32(v3);
                if (SPLIT == 3) {
                    al[i][0] = f2tf32(v0 - __uint_as_float(ah[i][0]));
                    al[i][1] = f2tf32(v1 - __uint_as_float(ah[i][1]));
                    al[i][2] = f2tf32(v2 - __uint_as_float(ah[i][2]));
                    al[i][3] = f2tf32(v3 - __uint_as_float(ah[i][3]));
                }
            }
            #pragma unroll
            for (int j = 0; j < NF; j++) {
                int c = wn*WN + j*8 + lr;
                uint32_t bh[2], bl[2];
                bh[0] = BsH[(ks + lc    )*BSTR + c];
                bh[1] = BsH[(ks + lc + 4)*BSTR + c];
                if (SPLIT == 3) {
                    bl[0] = BsL[(ks + lc    )*BSTR + c];
                    bl[1] = BsL[(ks + lc + 4)*BSTR + c];
                }
                #pragma unroll
                for (int i = 0; i < MF; i++) {
                    if (SPLIT == 3) {
                        mma_tf32(acc[i][j], al[i], bh);
                        mma_tf32(acc[i][j], ah[i], bl);
                    }
                    mma_tf32(acc[i][j], ah[i], bh);
                }
            }
        }
    };

    load_regs(0);
    store_regs(0);
    __syncthreads();
    for (int s = 0; s < S; s++) {
        if (s + 1 < S) load_regs(s + 1);
        compute(s & 1);
        if (s + 1 < S) store_regs((s + 1) & 1);
        __syncthreads();
    }

    // ---- epilogue ----
    #pragma unroll
    for (int i = 0; i < MF; i++) {
        int r0 = m0 + wm*WM + i*16 + lr;
        #pragma unroll
        for (int half = 0; half < 2; half++) {
            int mg = r0 + half*8;
            int obase;
            if (TRANS) {
                int mx = mg % MW; int t = mg / MW; int my = t % MH; int n = t / MH;
                obase = ((n*(2*INH) + 2*my + py)*(2*INW) + 2*mx + px)*COUT;
            } else {
                obase = mg*COUT;
            }
            #pragma unroll
            for (int j = 0; j < NF; j++) {
                int c = wn*WN + j*8 + 2*lc;
                float v0 = acc[i][j][half*2 + 0];
                float v1 = acc[i][j][half*2 + 1];
                if (HAS_BIAS) {
                    float2 bv = *reinterpret_cast<const float2*>(&bias[c]);
                    v0 += bv.x; v1 += bv.y;
                }
                if (ADD) {
                    float2 av = *reinterpret_cast<const float2*>(&addsrc[obase + c]);
                    v0 += av.x; v1 += av.y;
                }
                if (RELU_OUT) { v0 = fmaxf(v0, 0.f); v1 = fmaxf(v1, 0.f); }
                float2 ov; ov.x = v0; ov.y = v1;
                *reinterpret_cast<float2*>(&out[obase + c]) = ov;
            }
        }
    }
}

// ======================= codebook prep =======================
__global__ void emb_prep(const float* __restrict__ emb,
                         float* __restrict__ embT, float* __restrict__ ehalf)
{
    int c = blockIdx.x;
    int k = threadIdx.x;
    float v = emb[c*128 + k];
    embT[k*512 + c] = v;
    float s = v*v;
    #pragma unroll
    for (int o = 16; o; o >>= 1) s += __shfl_xor_sync(0xffffffffu, s, o);
    __shared__ float red[4];
    if ((k & 31) == 0) red[k >> 5] = s;
    __syncthreads();
    if (k == 0) ehalf[c] = 0.5f*(red[0]+red[1]+red[2]+red[3]);
}

// ======================= VQ via 3xTF32 tensor GEMM + fragment argmax =======================
__global__ void __launch_bounds__(256)
vq_mma(const float* __restrict__ f, const float* __restrict__ emb,
       const float* __restrict__ embT, const float* __restrict__ ehalf,
       float* __restrict__ q)
{
    constexpr int ASTR = 36, BSTR = 136;
    constexpr int A_WORDS = 128*ASTR, B_WORDS = 32*BSTR;
    extern __shared__ __align__(16) uint32_t vsm[];
    float*    AsF = reinterpret_cast<float*>(vsm);
    uint32_t* BsH = vsm + A_WORDS;
    uint32_t* BsL = BsH + B_WORDS;
    __shared__ float bestV[128][2];
    __shared__ int   bestI[128][2];
    __shared__ int   rowIdx[128];

    const int tid  = threadIdx.x;
    const int wid  = tid >> 5;
    const int lane = tid & 31;
    const int lr   = lane >> 2;
    const int lc   = lane & 3;
    const int m0   = blockIdx.x * 128;
    const int wm   = wid >> 1;
    const int wn   = wid & 1;

    float best[4];
    int   bidx[4];
    #pragma unroll
    for (int t = 0; t < 4; t++) { best[t] = -3.4e38f; bidx[t] = 0; }

    for (int nc = 0; nc < 4; nc++) {
        float acc[2][8][4];
        #pragma unroll
        for (int i = 0; i < 2; i++)
            #pragma unroll
            for (int j = 0; j < 8; j++)
                #pragma unroll
                for (int r = 0; r < 4; r++) acc[i][j][r] = 0.f;

        for (int s = 0; s < 4; s++) {
            const int k0 = s*32;
            #pragma unroll
            for (int it = 0; it < 4; it++) {
                int l = tid + it*256;
                int m = l >> 3, kq = l & 7;
                float4 v = *reinterpret_cast<const float4*>(&f[(m0 + m)*128 + k0 + kq*4]);
                *reinterpret_cast<float4*>(&AsF[m*ASTR + kq*4]) = v;
            }
            #pragma unroll
            for (int it = 0; it < 4; it++) {
                int l = tid + it*256;
                int co = (l & 31)*4;
                int kk = l >> 5;
                float4 w = *reinterpret_cast<const float4*>(&embT[(k0 + kk)*512 + nc*128 + co]);
                uint4 h;
                h.x = f2tf32(w.x); h.y = f2tf32(w.y); h.z = f2tf32(w.z); h.w = f2tf32(w.w);
                *reinterpret_cast<uint4*>(&BsH[kk*BSTR + co]) = h;
                uint4 lo;
                lo.x = f2tf32(w.x - __uint_as_float(h.x));
                lo.y = f2tf32(w.y - __uint_as_float(h.y));
                lo.z = f2tf32(w.z - __uint_as_float(h.z));
                lo.w = f2tf32(w.w - __uint_as_float(h.w));
                *reinterpret_cast<uint4*>(&BsL[kk*BSTR + co]) = lo;
            }
            __syncthreads();
            #pragma unroll
            for (int ks = 0; ks < 32; ks += 8) {
                uint32_t ah[2][4], al[2][4];
                #pragma unroll
                for (int i = 0; i < 2; i++) {
                    int r = wm*32 + i*16 + lr;
                    float v0 = AsF[(r    )*ASTR + ks + lc];
                    float v1 = AsF[(r + 8)*ASTR + ks + lc];
                    float v2 = AsF[(r    )*ASTR + ks + lc + 4];
                    float v3 = AsF[(r + 8)*ASTR + ks + lc + 4];
                    ah[i][0] = f2tf32(v0); ah[i][1] = f2tf32(v1);
                    ah[i][2] = f2tf32(v2); ah[i][3] = f2tf32(v3);
                    al[i][0] = f2tf32(v0 - __uint_as_float(ah[i][0]));
                    al[i][1] = f2tf32(v1 - __uint_as_float(ah[i][1]));
                    al[i][2] = f2tf32(v2 - __uint_as_float(ah[i][2]));
                    al[i][3] = f2tf32(v3 - __uint_as_float(ah[i][3]));
                }
                #pragma unroll
                for (int j = 0; j < 8; j++) {
                    int c = wn*64 + j*8 + lr;
                    uint32_t bh[2], bl[2];
                    bh[0] = BsH[(ks + lc    )*BSTR + c];
                    bh[1] = BsH[(ks + lc + 4)*BSTR + c];
                    bl[0] = BsL[(ks + lc    )*BSTR + c];
                    bl[1] = BsL[(ks + lc + 4)*BSTR + c];
                    #pragma unroll
                    for (int i = 0; i < 2; i++) {
                        mma_tf32(acc[i][j], al[i], bh);
                        mma_tf32(acc[i][j], ah[i], bl);
                        mma_tf32(acc[i][j], ah[i], bh);
                    }
                }
            }
            __syncthreads();
        }
        #pragma unroll
        for (int i = 0; i < 2; i++) {
            #pragma unroll
            for (int half = 0; half < 2; half++) {
                int slot = i*2 + half;
                #pragma unroll
                for (int j = 0; j < 8; j++) {
                    int col = nc*128 + wn*64 + j*8 + 2*lc;
                    float s0 = acc[i][j][half*2 + 0] - __ldg(&ehalf[col]);
                    float s1 = acc[i][j][half*2 + 1] - __ldg(&ehalf[col + 1]);
                    if (s0 > best[slot] || (s0 == best[slot] && col < bidx[slot]))
                        { best[slot] = s0; bidx[slot] = col; }
                    if (s1 > best[slot] || (s1 == best[slot] && col + 1 < bidx[slot]))
                        { best[slot] = s1; bidx[slot] = col + 1; }
                }
            }
        }
    }
    #pragma unroll
    for (int slot = 0; slot < 4; slot++) {
        #pragma unroll
        for (int off = 1; off < 4; off <<= 1) {
            float ov = __shfl_xor_sync(0xffffffffu, best[slot], off);
            int   oi = __shfl_xor_sync(0xffffffffu, bidx[slot], off);
            if (ov > best[slot] || (ov == best[slot] && oi < bidx[slot]))
                { best[slot] = ov; bidx[slot] = oi; }
        }
        if (lc == 0) {
            int i = slot >> 1, half = slot & 1;
            int row = wm*32 + i*16 + half*8 + lr;
            bestV[row][wn] = best[slot];
            bestI[row][wn] = bidx[slot];
        }
    }
    __syncthreads();
    for (int r = tid; r < 128; r += 256) {
        float v0 = bestV[r][0], v1 = bestV[r][1];
        int   i0 = bestI[r][0], i1 = bestI[r][1];
        rowIdx[r] = (v1 > v0 || (v1 == v0 && i1 < i0)) ? i1 : i0;
    }
    __syncthreads();
    for (int l = tid; l < 128*128; l += 256) {
        int r = l >> 7, j = l & 127;
        q[(m0 + r)*128 + j] = emb[rowIdx[r]*128 + j];
    }
}

// ======= dt2: 4x4 s2 tconv 64->3 — 4-parity fused (input neighborhood read ONCE) =======
// One thread computes the full 2x2 output cell of its (n,yq,xq): loads the 3x3 x 4ch
// input chunk once per ci-step instead of once per parity (4x less L2 traffic).
__global__ void __launch_bounds__(256)
dt2_fused(const float* __restrict__ in,   // [16,128,128,64]
          const float* __restrict__ wgt,  // [4,4,64,3]
          const float* __restrict__ bias,
          float* __restrict__ out)        // [16,256,256,3]
{
    __shared__ float ws[4*4*64*3];
    for (int l = threadIdx.x; l < 3072; l += 256) ws[l] = wgt[l];
    __syncthreads();

    const int m = blockIdx.x * 256 + threadIdx.x;   // 16*128*128 threads
    const int xq = m & 127; int t = m >> 7; const int yq = t & 127; const int n = t >> 7;

    float acc[4][3];
    #pragma unroll
    for (int p = 0; p < 4; p++)
        #pragma unroll
        for (int c = 0; c < 3; c++) acc[p][c] = __ldg(&bias[c]);

    const bool vy0 = (yq - 1 >= 0), vy2 = (yq + 1 < 128);
    const bool vx0 = (xq - 1 >= 0), vx2 = (xq + 1 < 128);
    const bool valid[3][3] = {
        { vy0 && vx0, vy0, vy0 && vx2 },
        { vx0,        true, vx2        },
        { vy2 && vx0, vy2, vy2 && vx2 }
    };
    const float* base = in + ((n*128 + yq)*128 + xq)*64;

    for (int cb = 0; cb < 64; cb += 4) {
        float4 p[3][3];
        #pragma unroll
        for (int dy = 0; dy < 3; dy++)
            #pragma unroll
            for (int dx = 0; dx < 3; dx++)
                p[dy][dx] = valid[dy][dx]
                    ? *reinterpret_cast<const float4*>(base + ((dy-1)*128 + (dx-1))*64 + cb)
                    : make_float4(0.f,0.f,0.f,0.f);
        #pragma unroll
        for (int py = 0; py < 2; py++)
            #pragma unroll
            for (int px = 0; px < 2; px++) {
                const int pi = py*2 + px;
                #pragma unroll
                for (int aa = 0; aa < 2; aa++)
                    #pragma unroll
                    for (int bb = 0; bb < 2; bb++) {
                        const float4 v = p[py + aa][px + bb];
                        const float* w0 = ws + (((2*aa + py)*4 + (2*bb + px))*64 + cb)*3;
                        #pragma unroll
                        for (int c = 0; c < 3; c++) {
                            acc[pi][c] += v.x*w0[c];
                            acc[pi][c] += v.y*w0[3 + c];
                            acc[pi][c] += v.z*w0[6 + c];
                            acc[pi][c] += v.w*w0[9 + c];
                        }
                    }
            }
    }
    #pragma unroll
    for (int py = 0; py < 2; py++)
        #pragma unroll
        for (int px = 0; px < 2; px++) {
            const int oy = 2*yq + py, ox = 2*xq + px;
            float* op = out + ((n*256 + oy)*256 + ox)*3;
            const int pi = py*2 + px;
            op[0] = acc[pi][0]; op[1] = acc[pi][1]; op[2] = acc[pi][2];
        }
}

// ======================= host launcher =======================
extern "C" void kernel_launch(void* const* d_in, const int* in_sizes, int n_in,
                              void* d_out, int out_size)
{
    (void)in_sizes; (void)n_in;
    const float* x       = (const float*)d_in[0];
    const float* emb     = (const float*)d_in[1];
    const float* enc_w1  = (const float*)d_in[2];
    const float* enc_b1  = (const float*)d_in[3];
    const float* enc_w2  = (const float*)d_in[4];
    const float* enc_b2  = (const float*)d_in[5];
    const float* enc_w3  = (const float*)d_in[6];
    const float* enc_b3  = (const float*)d_in[7];
    const float* erb1_w1 = (const float*)d_in[8];
    const float* erb1_w2 = (const float*)d_in[9];
    const float* erb2_w1 = (const float*)d_in[10];
    const float* erb2_w2 = (const float*)d_in[11];
    const float* dec_w   = (const float*)d_in[12];
    const float* dec_b   = (const float*)d_in[13];
    const float* drb1_w1 = (const float*)d_in[14];
    const float* drb1_w2 = (const float*)d_in[15];
    const float* drb2_w1 = (const float*)d_in[16];
    const float* drb2_w2 = (const float*)d_in[17];
    const float* dt1_w   = (const float*)d_in[18];
    const float* dt1_b   = (const float*)d_in[19];
    const float* dt2_w   = (const float*)d_in[20];
    const float* dt2_b   = (const float*)d_in[21];

    float* out = (float*)d_out;
    const int YS = 16*256*256*3;
    const int FS = 16*64*64*128;

    float *buf0,*buf1,*buf2,*tmpb,*embT,*ehalf,*fb,*qb;
    cudaGetSymbolAddress((void**)&buf0,  g_buf0);
    cudaGetSymbolAddress((void**)&buf1,  g_buf1);
    cudaGetSymbolAddress((void**)&buf2,  g_buf2);
    cudaGetSymbolAddress((void**)&tmpb,  g_tmpb);
    cudaGetSymbolAddress((void**)&embT,  g_embT);
    cudaGetSymbolAddress((void**)&ehalf, g_ehalf);
    cudaGetSymbolAddress((void**)&fb,    g_fbuf);
    cudaGetSymbolAddress((void**)&qb,    g_qbuf);

    const bool full = (out_size >= YS + 2*FS);
    float* fptr = full ? (out + YS)      : fb;
    float* qptr = full ? (out + YS + FS) : qb;

    dim3 b(256);

    const int SM3_128 = 2*(4608 + 2*4352)*4;    // 106496  (BM=128)
    const int SM3_32  = 2*(9216 + 2*1280)*4;    // 94208   (BM=256, BN=32)
    const int SM1_128 = 2*(4608 + 4352)*4;      // 71680
    const int SM1_64  = 2*(4608 + 2304)*4;      // 55296
    const int SM1_32  = 2*(9216 + 1280)*4;      // 83968   (BM=256, BN=32)
    const int SM_VQ   = (4608 + 2*4352)*4;      // 53248

    // ---- encoder (3xTF32) ----
    auto kEnc2 = mma_conv7<128, 64,128,4,4,2,1, 128,128, false,true,false,true,false,3>;
    auto kEnc3 = mma_conv7<128, 128,128,3,3,1,1, 64,64, false,true,false,false,false,3>;
    auto kEw1  = mma_conv7<256, 128,32, 3,3,1,1, 64,64, true,false,false,true,false,3>;
    auto kEw2  = mma_conv7<128, 32,128, 1,1,1,0, 64,64, false,false,true,false,false,3>;
    auto kEw2R = mma_conv7<128, 32,128, 1,1,1,0, 64,64, false,false,true,true,false,3>;
    // ---- decoder (single-pass tf32) ----
    auto kDec  = mma_conv7<128, 128,128,3,3,1,1, 64,64, false,true,false,false,false,1>;
    auto kDw1  = mma_conv7<256, 128,32, 3,3,1,1, 64,64, true,false,false,true,false,1>;
    auto kDw2  = mma_conv7<128, 32,128, 1,1,1,0, 64,64, false,false,true,false,false,1>;
    auto kDw2R = mma_conv7<128, 32,128, 1,1,1,0, 64,64, false,false,true,true,false,1>;
    auto kDt1  = mma_conv7<128, 128,64, 4,4,2,0, 64,64, false,true,false,true,true,1>;

    cudaFuncSetAttribute(kEnc2, cudaFuncAttributeMaxDynamicSharedMemorySize, SM3_128);
    cudaFuncSetAttribute(kEnc3, cudaFuncAttributeMaxDynamicSharedMemorySize, SM3_128);
    cudaFuncSetAttribute(kEw1,  cudaFuncAttributeMaxDynamicSharedMemorySize, SM3_32);
    cudaFuncSetAttribute(kEw2,  cudaFuncAttributeMaxDynamicSharedMemorySize, SM3_128);
    cudaFuncSetAttribute(kEw2R, cudaFuncAttributeMaxDynamicSharedMemorySize, SM3_128);
    cudaFuncSetAttribute(kDec,  cudaFuncAttributeMaxDynamicSharedMemorySize, SM1_128);
    cudaFuncSetAttribute(kDw1,  cudaFuncAttributeMaxDynamicSharedMemorySize, SM1_32);
    cudaFuncSetAttribute(kDw2,  cudaFuncAttributeMaxDynamicSharedMemorySize, SM1_128);
    cudaFuncSetAttribute(kDw2R, cudaFuncAttributeMaxDynamicSharedMemorySize, SM1_128);
    cudaFuncSetAttribute(kDt1,  cudaFuncAttributeMaxDynamicSharedMemorySize, SM1_64);
    cudaFuncSetAttribute(vq_mma, cudaFuncAttributeMaxDynamicSharedMemorySize, SM_VQ);

    // ---- encoder ----
    conv_gemm<64,64,16,4,4,  3,64,4,4,2,1, 256,256,16, false,true,false,true>
        <<<dim3(4096,1,1),b>>>(x, enc_w1, enc_b1, nullptr, buf0);
    kEnc2<<<dim3(512,1,1), b, SM3_128>>>(buf0, enc_w2, enc_b2, nullptr, buf1);
    kEnc3<<<dim3(512,1,1), b, SM3_128>>>(buf1, enc_w3, enc_b3, nullptr, buf2);
    kEw1 <<<dim3(256,1,1), b, SM3_32 >>>(buf2, erb1_w1, nullptr, nullptr, tmpb);
    kEw2 <<<dim3(512,1,1), b, SM3_128>>>(tmpb, erb1_w2, nullptr, buf2, buf2);
    kEw1 <<<dim3(256,1,1), b, SM3_32 >>>(buf2, erb2_w1, nullptr, nullptr, tmpb);
    kEw2R<<<dim3(512,1,1), b, SM3_128>>>(tmpb, erb2_w2, nullptr, buf2, fptr);

    // ---- VQ (3xTF32 scores, fp32 norms, full-codebook argmax) ----
    emb_prep<<<512,128>>>(emb, embT, ehalf);
    vq_mma<<<512, b, SM_VQ>>>(fptr, emb, embT, ehalf, qptr);

    // ---- decoder ----
    kDec <<<dim3(512,1,1), b, SM1_128>>>(qptr, dec_w, dec_b, nullptr, buf1);
    kDw1 <<<dim3(256,1,1), b, SM1_32 >>>(buf1, drb1_w1, nullptr, nullptr, tmpb);
    kDw2 <<<dim3(512,1,1), b, SM1_128>>>(tmpb, drb1_w2, nullptr, buf1, buf1);
    kDw1 <<<dim3(256,1,1), b, SM1_32 >>>(buf1, drb2_w1, nullptr, nullptr, tmpb);
    kDw2R<<<dim3(512,1,1), b, SM1_128>>>(tmpb, drb2_w2, nullptr, buf1, buf2);
    kDt1 <<<dim3(512,1,4), b, SM1_64 >>>(buf2, dt1_w, dt1_b, nullptr, buf0);

    dt2_fused<<<dim3(1024,1,1),b>>>(buf0, dt2_w, dt2_b, out);
}

// round 14
// speedup vs baseline: 2.3326x; 1.0208x over previous
#include <cuda_runtime.h>
#include <cstdint>

// ======================= device scratch (no cudaMalloc allowed) =======================
__device__ float g_buf0[16*128*128*64];   // enc1 out / dt1 out
__device__ float g_buf1[16*64*64*128];
__device__ float g_buf2[16*64*64*128];
__device__ float g_fbuf[16*64*64*128];
__device__ float g_qbuf[16*64*64*128];
__device__ float g_embT[128*512];
__device__ float g_ehalf[512];

__device__ __forceinline__ uint32_t f2tf32(float x) {
    uint32_t r; asm("cvt.rna.tf32.f32 %0, %1;" : "=r"(r) : "f"(x)); return r;
}
__device__ __forceinline__ void mma_tf32(float* d, const uint32_t* a, const uint32_t* b) {
    asm volatile(
        "mma.sync.aligned.m16n8k8.row.col.f32.tf32.tf32.f32 "
        "{%0,%1,%2,%3}, {%4,%5,%6,%7}, {%8,%9}, {%0,%1,%2,%3};"
        : "+f"(d[0]), "+f"(d[1]), "+f"(d[2]), "+f"(d[3])
        : "r"(a[0]), "r"(a[1]), "r"(a[2]), "r"(a[3]), "r"(b[0]), "r"(b[1]));
}

// ======================= fp32 tiled implicit-GEMM conv (enc1 only) =======================
template<int BM,int BN,int BK,int TM,int TN,
         int CIN,int COUT,int KH,int KW,int STRIDE,int PAD,
         int INH,int INW,int NB,
         bool RELU_IN,bool HAS_BIAS,bool ADD,bool RELU_OUT>
__global__ void __launch_bounds__(256)
conv_gemm(const float* __restrict__ in, const float* __restrict__ wgt,
          const float* __restrict__ bias, const float* __restrict__ addsrc,
          float* __restrict__ out)
{
    constexpr int MH = INH / STRIDE;
    constexpr int MW = INW / STRIDE;
    constexpr int K  = KH*KW*CIN;
    constexpr int THREADS = (BM/TM)*(BN/TN);
    static_assert(THREADS == 256, "block must be 256 threads");

    __shared__ __align__(16) float As[BK][BM+4];
    __shared__ __align__(16) float Bs[BK][BN];

    const int tid = threadIdx.x;
    const int m0  = blockIdx.x * BM;
    const int n0  = blockIdx.y * BN;

    const int tcol = tid % (BN/TN);
    const int trow = tid / (BN/TN);

    float acc[TM][TN];
    #pragma unroll
    for (int i = 0; i < TM; i++)
        #pragma unroll
        for (int j = 0; j < TN; j++) acc[i][j] = 0.f;

    for (int k0 = 0; k0 < K; k0 += BK) {
        #pragma unroll
        for (int i = 0; i < (BM*BK)/THREADS; i++) {
            int l = tid + i*THREADS;
            int mloc = l / BK, kloc = l % BK;
            int m = m0 + mloc;
            int k = k0 + kloc;
            int mx = m % MW; int t = m / MW; int my = t % MH; int n = t / MH;
            float v = 0.f;
            int ci = k % CIN; int r = k / CIN;
            int kw = r % KW, kh = r / KW;
            int iy = my*STRIDE - PAD + kh;
            int ix = mx*STRIDE - PAD + kw;
            if (iy >= 0 && iy < INH && ix >= 0 && ix < INW)
                v = in[((n*INH + iy)*INW + ix)*CIN + ci];
            if (RELU_IN) v = fmaxf(v, 0.f);
            As[kloc][mloc] = v;
        }
        #pragma unroll
        for (int i = 0; i < (BK*BN)/THREADS; i++) {
            int l = tid + i*THREADS;
            int kloc = l / BN, nloc = l % BN;
            int k = k0 + kloc;
            Bs[kloc][nloc] = wgt[k*COUT + n0 + nloc];
        }
        __syncthreads();
        #pragma unroll
        for (int kk = 0; kk < BK; kk++) {
            float ra[TM], rb[TN];
            #pragma unroll
            for (int i = 0; i < TM; i += 4) {
                float4 t4 = *reinterpret_cast<const float4*>(&As[kk][trow*TM + i]);
                ra[i]=t4.x; ra[i+1]=t4.y; ra[i+2]=t4.z; ra[i+3]=t4.w;
            }
            #pragma unroll
            for (int j = 0; j < TN; j += 4) {
                float4 t4 = *reinterpret_cast<const float4*>(&Bs[kk][tcol*TN + j]);
                rb[j]=t4.x; rb[j+1]=t4.y; rb[j+2]=t4.z; rb[j+3]=t4.w;
            }
            #pragma unroll
            for (int i = 0; i < TM; i++)
                #pragma unroll
                for (int j = 0; j < TN; j++)
                    acc[i][j] += ra[i]*rb[j];
        }
        __syncthreads();
    }
    #pragma unroll
    for (int i = 0; i < TM; i++) {
        int m = m0 + trow*TM + i;
        int obase = m*COUT;
        #pragma unroll
        for (int j = 0; j < TN; j++) {
            int c = n0 + tcol*TN + j;
            float v = acc[i][j];
            if (HAS_BIAS) v += bias[c];
            if (ADD)      v += addsrc[obase + c];
            if (RELU_OUT) v = fmaxf(v, 0.f);
            out[obase + c] = v;
        }
    }
}

// ====== tf32 mma.sync implicit-GEMM conv (R13 config, unchanged) ======
template<int BM,int CIN,int COUT,int KH,int KW,int STRIDE,int PAD,int INH,int INW,
         bool RELU_IN,bool HAS_BIAS,bool ADD,bool RELU_OUT,bool TRANS,int SPLIT>
__global__ void __launch_bounds__(256)
mma_conv7(const float* __restrict__ in, const float* __restrict__ wgt,
          const float* __restrict__ bias, const float* __restrict__ addsrc,
          float* __restrict__ out)
{
    constexpr int MH = TRANS ? INH : INH / STRIDE;
    constexpr int MW = TRANS ? INW : INW / STRIDE;
    constexpr int K  = TRANS ? 4*CIN : KH*KW*CIN;
    constexpr int BK = 32, BN = COUT;
    constexpr int S  = K / BK;
    constexpr int WARPS_N = (BN >= 64) ? 2 : 1;
    constexpr int WARPS_M = 8 / WARPS_N;
    constexpr int WM = BM / WARPS_M;
    constexpr int WN = BN / WARPS_N;
    constexpr int MF = WM / 16;
    constexpr int NF = WN / 8;
    constexpr int ASTR = BK + 4;
    constexpr int BSTR = BN + 8;
    constexpr int A_WORDS = BM*ASTR;
    constexpr int B_WORDS = BK*BSTR;
    constexpr int NCOPYB = (SPLIT==3 ? 2 : 1);
    constexpr int CSZ = A_WORDS + NCOPYB*B_WORDS;
    constexpr int NAITER = BM/32;
    constexpr int NBREG = (BK*BN)/(4*256);

    extern __shared__ __align__(16) uint32_t smem[];

    const int tid  = threadIdx.x;
    const int wid  = tid >> 5;
    const int lane = tid & 31;
    const int m0   = blockIdx.x * BM;
    const int py   = TRANS ? (int)(blockIdx.z >> 1) : 0;
    const int px   = TRANS ? (int)(blockIdx.z & 1)  : 0;
    const int wm   = wid / WARPS_N;
    const int wn   = wid % WARPS_N;
    const int lr   = lane >> 2;
    const int lc   = lane & 3;

    float acc[MF][NF][4];
    #pragma unroll
    for (int i = 0; i < MF; i++)
        #pragma unroll
        for (int j = 0; j < NF; j++)
            #pragma unroll
            for (int r = 0; r < 4; r++) acc[i][j][r] = 0.f;

    float4 aR[NAITER];
    float4 bR[NBREG];

    auto load_regs = [&](int s) {
        const int k0 = s * BK;
        #pragma unroll
        for (int it = 0; it < NAITER; it++) {
            int l = tid + it*256;
            int m = l >> 3, kq = l & 7;
            int k = k0 + kq*4;
            int mg = m0 + m;
            int mx = mg % MW; int t = mg / MW; int my = t % MH; int n = t / MH;
            int iy, ix, ci;
            if (TRANS) {
                ci = k % CIN; int ab = k / CIN;
                int bb = ab & 1, aa = ab >> 1;
                iy = my + py + aa - 1;
                ix = mx + px + bb - 1;
            } else {
                ci = k % CIN; int r = k / CIN;
                int kw = r % KW, kh = r / KW;
                iy = my*STRIDE - PAD + kh;
                ix = mx*STRIDE - PAD + kw;
            }
            if (iy >= 0 && iy < INH && ix >= 0 && ix < INW)
                aR[it] = *reinterpret_cast<const float4*>(&in[((n*INH + iy)*INW + ix)*CIN + ci]);
            else
                aR[it] = make_float4(0.f,0.f,0.f,0.f);
        }
        #pragma unroll
        for (int it = 0; it < NBREG; it++) {
            int l = tid + it*256;
            int co = (l % (BN/4))*4;
            int kk = l / (BN/4);
            int k = k0 + kk;
            if (TRANS) {
                int ci = k % CIN; int ab = k / CIN;
                int bb = ab & 1, aa = ab >> 1;
                int widx = ((2*aa + py)*KW + (2*bb + px))*CIN + ci;
                bR[it] = *reinterpret_cast<const float4*>(&wgt[widx*COUT + co]);
            } else {
                bR[it] = *reinterpret_cast<const float4*>(&wgt[k*COUT + co]);
            }
        }
    };

    auto store_regs = [&](int buf) {
        float*    AsF = reinterpret_cast<float*>(smem + buf*CSZ);
        uint32_t* BsH = smem + buf*CSZ + A_WORDS;
        uint32_t* BsL = BsH + B_WORDS;
        #pragma unroll
        for (int it = 0; it < NAITER; it++) {
            int l = tid + it*256;
            int m = l >> 3, kq = l & 7;
            float4 v = aR[it];
            if (RELU_IN) {
                v.x = fmaxf(v.x, 0.f); v.y = fmaxf(v.y, 0.f);
                v.z = fmaxf(v.z, 0.f); v.w = fmaxf(v.w, 0.f);
            }
            *reinterpret_cast<float4*>(&AsF[m*ASTR + kq*4]) = v;
        }
        #pragma unroll
        for (int it = 0; it < NBREG; it++) {
            int l = tid + it*256;
            int co = (l % (BN/4))*4;
            int kk = l / (BN/4);
            float4 w = bR[it];
            uint4 h;
            h.x = f2tf32(w.x); h.y = f2tf32(w.y); h.z = f2tf32(w.z); h.w = f2tf32(w.w);
            *reinterpret_cast<uint4*>(&BsH[kk*BSTR + co]) = h;
            if (SPLIT == 3) {
                uint4 lo;
                lo.x = f2tf32(w.x - __uint_as_float(h.x));
                lo.y = f2tf32(w.y - __uint_as_float(h.y));
                lo.z = f2tf32(w.z - __uint_as_float(h.z));
                lo.w = f2tf32(w.w - __uint_as_float(h.w));
                *reinterpret_cast<uint4*>(&BsL[kk*BSTR + co]) = lo;
            }
        }
    };

    auto compute = [&](int buf) {
        const float*    AsF = reinterpret_cast<const float*>(smem + buf*CSZ);
        const uint32_t* BsH = smem + buf*CSZ + A_WORDS;
        const uint32_t* BsL = BsH + B_WORDS;
        #pragma unroll
        for (int ks = 0; ks < BK; ks += 8) {
            uint32_t ah[MF][4], al[MF][4];
            #pragma unroll
            for (int i = 0; i < MF; i++) {
                int r = wm*WM + i*16 + lr;
                float v0 = AsF[(r    )*ASTR + ks + lc];
                float v1 = AsF[(r + 8)*ASTR + ks + lc];
                float v2 = AsF[(r    )*ASTR + ks + lc + 4];
                float v3 = AsF[(r + 8)*ASTR + ks + lc + 4];
                ah[i][0] = f2tf32(v0); ah[i][1] = f2tf32(v1);
                ah[i][2] = f2tf32(v2); ah[i][3] = f2tf32(v3);
                if (SPLIT == 3) {
                    al[i][0] = f2tf32(v0 - __uint_as_float(ah[i][0]));
                    al[i][1] = f2tf32(v1 - __uint_as_float(ah[i][1]));
                    al[i][2] = f2tf32(v2 - __uint_as_float(ah[i][2]));
                    al[i][3] = f2tf32(v3 - __uint_as_float(ah[i][3]));
                }
            }
            #pragma unroll
            for (int j = 0; j < NF; j++) {
                int c = wn*WN + j*8 + lr;
                uint32_t bh[2], bl[2];
                bh[0] = BsH[(ks + lc    )*BSTR + c];
                bh[1] = BsH[(ks + lc + 4)*BSTR + c];
                if (SPLIT == 3) {
                    bl[0] = BsL[(ks + lc    )*BSTR + c];
                    bl[1] = BsL[(ks + lc + 4)*BSTR + c];
                }
                #pragma unroll
                for (int i = 0; i < MF; i++) {
                    if (SPLIT == 3) {
                        mma_tf32(acc[i][j], al[i], bh);
                        mma_tf32(acc[i][j], ah[i], bl);
                    }
                    mma_tf32(acc[i][j], ah[i], bh);
                }
            }
        }
    };

    load_regs(0);
    store_regs(0);
    __syncthreads();
    for (int s = 0; s < S; s++) {
        if (s + 1 < S) load_regs(s + 1);
        compute(s & 1);
        if (s + 1 < S) store_regs((s + 1) & 1);
        __syncthreads();
    }

    #pragma unroll
    for (int i = 0; i < MF; i++) {
        int r0 = m0 + wm*WM + i*16 + lr;
        #pragma unroll
        for (int half = 0; half < 2; half++) {
            int mg = r0 + half*8;
            int obase;
            if (TRANS) {
                int mx = mg % MW; int t = mg / MW; int my = t % MH; int n = t / MH;
                obase = ((n*(2*INH) + 2*my + py)*(2*INW) + 2*mx + px)*COUT;
            } else {
                obase = mg*COUT;
            }
            #pragma unroll
            for (int j = 0; j < NF; j++) {
                int c = wn*WN + j*8 + 2*lc;
                float v0 = acc[i][j][half*2 + 0];
                float v1 = acc[i][j][half*2 + 1];
                if (HAS_BIAS) {
                    float2 bv = *reinterpret_cast<const float2*>(&bias[c]);
                    v0 += bv.x; v1 += bv.y;
                }
                if (ADD) {
                    float2 av = *reinterpret_cast<const float2*>(&addsrc[obase + c]);
                    v0 += av.x; v1 += av.y;
                }
                if (RELU_OUT) { v0 = fmaxf(v0, 0.f); v1 = fmaxf(v1, 0.f); }
                float2 ov; ov.x = v0; ov.y = v1;
                *reinterpret_cast<float2*>(&out[obase + c]) = ov;
            }
        }
    }
}

// ====== fused residual block: t=relu(in); t=conv3x3(t) -> relu -> smem;
//        out = t @ w2(1x1) + in; optional final relu. Bit-identical to the
//        unfused pair (phase boundary carries the same fp32 post-relu values).
template<int SPLIT, bool RELU_OUT2>
__global__ void __launch_bounds__(256)
mma_resblk(const float* __restrict__ in, const float* __restrict__ w1,
           const float* __restrict__ w2, float* __restrict__ out)
{
    constexpr int INH=64, INW=64, CIN=128, K1=1152, BK=32, S=K1/BK;
    constexpr int ASTR=36, A_WORDS=128*ASTR;
    constexpr int B1STR=40, B1_WORDS=BK*B1STR;
    constexpr int NCOPYB=(SPLIT==3?2:1);
    constexpr int CSZ=A_WORDS+NCOPYB*B1_WORDS;
    constexpr int MID_OFF=2*CSZ;
    constexpr int W2_OFF=MID_OFF+A_WORDS;
    constexpr int B2STR=136, B2_WORDS=BK*B2STR;

    extern __shared__ __align__(16) uint32_t smem[];

    const int tid=threadIdx.x, wid=tid>>5, lane=tid&31;
    const int lr=lane>>2, lc=lane&3;
    const int m0=blockIdx.x*128;

    // ---- load + convert w2 (32x128) once ----
    {
        uint32_t* W2H = smem + W2_OFF;
        uint32_t* W2L = W2H + B2_WORDS;
        #pragma unroll
        for (int it=0; it<4; it++){
            int l=tid+it*256;
            int co=(l&31)*4, kk=l>>5;
            float4 w=*reinterpret_cast<const float4*>(&w2[kk*128+co]);
            uint4 h; h.x=f2tf32(w.x); h.y=f2tf32(w.y); h.z=f2tf32(w.z); h.w=f2tf32(w.w);
            *reinterpret_cast<uint4*>(&W2H[kk*B2STR+co])=h;
            if (SPLIT==3){
                uint4 lo;
                lo.x=f2tf32(w.x-__uint_as_float(h.x));
                lo.y=f2tf32(w.y-__uint_as_float(h.y));
                lo.z=f2tf32(w.z-__uint_as_float(h.z));
                lo.w=f2tf32(w.w-__uint_as_float(h.w));
                *reinterpret_cast<uint4*>(&W2L[kk*B2STR+co])=lo;
            }
        }
    }

    // ================= phase 1: conv3x3 128->32, relu-in, BM=128/BN=32 =================
    float acc1[4][4];
    #pragma unroll
    for (int j=0;j<4;j++)
        #pragma unroll
        for (int r=0;r<4;r++) acc1[j][r]=0.f;

    float4 aR[4];
    float4 bR1;

    auto load_regs=[&](int s){
        const int k0=s*BK;
        #pragma unroll
        for (int it=0; it<4; it++){
            int l=tid+it*256;
            int m=l>>3, kq=l&7;
            int k=k0+kq*4;
            int mg=m0+m;
            int mx=mg&63; int t=mg>>6; int my=t&63; int n=t>>6;
            int ci=k&127; int r=k>>7;
            int kw=r%3, kh=r/3;
            int iy=my+kh-1, ix=mx+kw-1;
            if (iy>=0 && iy<INH && ix>=0 && ix<INW)
                aR[it]=*reinterpret_cast<const float4*>(&in[((n*INH+iy)*INW+ix)*CIN+ci]);
            else
                aR[it]=make_float4(0.f,0.f,0.f,0.f);
        }
        { int co=(tid&7)*4, kk=tid>>3;
          bR1=*reinterpret_cast<const float4*>(&w1[(k0+kk)*32+co]); }
    };
    auto store_regs=[&](int buf){
        float* AsF=reinterpret_cast<float*>(smem+buf*CSZ);
        uint32_t* BsH=smem+buf*CSZ+A_WORDS;
        uint32_t* BsL=BsH+B1_WORDS;
        #pragma unroll
        for (int it=0; it<4; it++){
            int l=tid+it*256;
            int m=l>>3, kq=l&7;
            float4 v=aR[it];
            v.x=fmaxf(v.x,0.f); v.y=fmaxf(v.y,0.f);
            v.z=fmaxf(v.z,0.f); v.w=fmaxf(v.w,0.f);
            *reinterpret_cast<float4*>(&AsF[m*ASTR+kq*4])=v;
        }
        {
            int co=(tid&7)*4, kk=tid>>3;
            float4 w=bR1;
            uint4 h; h.x=f2tf32(w.x); h.y=f2tf32(w.y); h.z=f2tf32(w.z); h.w=f2tf32(w.w);
            *reinterpret_cast<uint4*>(&BsH[kk*B1STR+co])=h;
            if (SPLIT==3){
                uint4 lo;
                lo.x=f2tf32(w.x-__uint_as_float(h.x));
                lo.y=f2tf32(w.y-__uint_as_float(h.y));
                lo.z=f2tf32(w.z-__uint_as_float(h.z));
                lo.w=f2tf32(w.w-__uint_as_float(h.w));
                *reinterpret_cast<uint4*>(&BsL[kk*B1STR+co])=lo;
            }
        }
    };
    auto compute=[&](int buf){
        const float* AsF=reinterpret_cast<const float*>(smem+buf*CSZ);
        const uint32_t* BsH=smem+buf*CSZ+A_WORDS;
        const uint32_t* BsL=BsH+B1_WORDS;
        #pragma unroll
        for (int ks=0; ks<BK; ks+=8){
            uint32_t ah[4], al[4];
            int r=wid*16+lr;
            float v0=AsF[(r  )*ASTR+ks+lc];
            float v1=AsF[(r+8)*ASTR+ks+lc];
            float v2=AsF[(r  )*ASTR+ks+lc+4];
            float v3=AsF[(r+8)*ASTR+ks+lc+4];
            ah[0]=f2tf32(v0); ah[1]=f2tf32(v1); ah[2]=f2tf32(v2); ah[3]=f2tf32(v3);
            if (SPLIT==3){
                al[0]=f2tf32(v0-__uint_as_float(ah[0]));
                al[1]=f2tf32(v1-__uint_as_float(ah[1]));
                al[2]=f2tf32(v2-__uint_as_float(ah[2]));
                al[3]=f2tf32(v3-__uint_as_float(ah[3]));
            }
            #pragma unroll
            for (int j=0;j<4;j++){
                int c=j*8+lr;
                uint32_t bh[2], bl[2];
                bh[0]=BsH[(ks+lc  )*B1STR+c];
                bh[1]=BsH[(ks+lc+4)*B1STR+c];
                if (SPLIT==3){
                    bl[0]=BsL[(ks+lc  )*B1STR+c];
                    bl[1]=BsL[(ks+lc+4)*B1STR+c];
                    mma_tf32(acc1[j], al, bh);
                    mma_tf32(acc1[j], ah, bl);
                }
                mma_tf32(acc1[j], ah, bh);
            }
        }
    };

    load_regs(0);
    store_regs(0);
    __syncthreads();
    for (int s=0; s<S; s++){
        if (s+1<S) load_regs(s+1);
        compute(s&1);
        if (s+1<S) store_regs((s+1)&1);
        __syncthreads();
    }

    // phase-1 epilogue: relu(mid) -> smem A-layout
    {
        float* midA=reinterpret_cast<float*>(smem+MID_OFF);
        #pragma unroll
        for (int half=0; half<2; half++){
            int mg=wid*16+half*8+lr;
            #pragma unroll
            for (int j=0;j<4;j++){
                int c=j*8+2*lc;
                midA[mg*ASTR+c  ]=fmaxf(acc1[j][half*2+0],0.f);
                midA[mg*ASTR+c+1]=fmaxf(acc1[j][half*2+1],0.f);
            }
        }
    }
    __syncthreads();

    // ================= phase 2: 1x1 32->128 + residual =================
    const int wm2=wid>>1, wn2=wid&1;
    float acc2[2][8][4];
    #pragma unroll
    for (int i=0;i<2;i++)
        #pragma unroll
        for (int j=0;j<8;j++)
            #pragma unroll
            for (int r=0;r<4;r++) acc2[i][j][r]=0.f;

    {
        const float* A2=reinterpret_cast<const float*>(smem+MID_OFF);
        const uint32_t* W2H=smem+W2_OFF;
        const uint32_t* W2L=W2H+B2_WORDS;
        #pragma unroll
        for (int ks=0; ks<32; ks+=8){
            uint32_t ah[2][4], al[2][4];
            #pragma unroll
            for (int i=0;i<2;i++){
                int r=wm2*32+i*16+lr;
                float v0=A2[(r  )*ASTR+ks+lc];
                float v1=A2[(r+8)*ASTR+ks+lc];
                float v2=A2[(r  )*ASTR+ks+lc+4];
                float v3=A2[(r+8)*ASTR+ks+lc+4];
                ah[i][0]=f2tf32(v0); ah[i][1]=f2tf32(v1);
                ah[i][2]=f2tf32(v2); ah[i][3]=f2tf32(v3);
                if (SPLIT==3){
                    al[i][0]=f2tf32(v0-__uint_as_float(ah[i][0]));
                    al[i][1]=f2tf32(v1-__uint_as_float(ah[i][1]));
                    al[i][2]=f2tf32(v2-__uint_as_float(ah[i][2]));
                    al[i][3]=f2tf32(v3-__uint_as_float(ah[i][3]));
                }
            }
            #pragma unroll
            for (int j=0;j<8;j++){
                int c=wn2*64+j*8+lr;
                uint32_t bh[2], bl[2];
                bh[0]=W2H[(ks+lc  )*B2STR+c];
                bh[1]=W2H[(ks+lc+4)*B2STR+c];
                if (SPLIT==3){
                    bl[0]=W2L[(ks+lc  )*B2STR+c];
                    bl[1]=W2L[(ks+lc+4)*B2STR+c];
                }
                #pragma unroll
                for (int i=0;i<2;i++){
                    if (SPLIT==3){
                        mma_tf32(acc2[i][j], al[i], bh);
                        mma_tf32(acc2[i][j], ah[i], bl);
                    }
                    mma_tf32(acc2[i][j], ah[i], bh);
                }
            }
        }
    }
    // phase-2 epilogue: + residual(in), optional relu
    #pragma unroll
    for (int i=0;i<2;i++){
        #pragma unroll
        for (int half=0; half<2; half++){
            int mg=m0+wm2*32+i*16+half*8+lr;
            int obase=mg*128;
            #pragma unroll
            for (int j=0;j<8;j++){
                int c=wn2*64+j*8+2*lc;
                float v0=acc2[i][j][half*2+0];
                float v1=acc2[i][j][half*2+1];
                float2 rv=*reinterpret_cast<const float2*>(&in[obase+c]);
                v0+=rv.x; v1+=rv.y;
                if (RELU_OUT2){ v0=fmaxf(v0,0.f); v1=fmaxf(v1,0.f); }
                float2 ov; ov.x=v0; ov.y=v1;
                *reinterpret_cast<float2*>(&out[obase+c])=ov;
            }
        }
    }
}

// ======================= codebook prep =======================
__global__ void emb_prep(const float* __restrict__ emb,
                         float* __restrict__ embT, float* __restrict__ ehalf)
{
    int c = blockIdx.x;
    int k = threadIdx.x;
    float v = emb[c*128 + k];
    embT[k*512 + c] = v;
    float s = v*v;
    #pragma unroll
    for (int o = 16; o; o >>= 1) s += __shfl_xor_sync(0xffffffffu, s, o);
    __shared__ float red[4];
    if ((k & 31) == 0) red[k >> 5] = s;
    __syncthreads();
    if (k == 0) ehalf[c] = 0.5f*(red[0]+red[1]+red[2]+red[3]);
}

// ======================= VQ via 3xTF32 tensor GEMM + fragment argmax =======================
__global__ void __launch_bounds__(256)
vq_mma(const float* __restrict__ f, const float* __restrict__ emb,
       const float* __restrict__ embT, const float* __restrict__ ehalf,
       float* __restrict__ q)
{
    constexpr int ASTR = 36, BSTR = 136;
    constexpr int A_WORDS = 128*ASTR, B_WORDS = 32*BSTR;
    extern __shared__ __align__(16) uint32_t vsm[];
    float*    AsF = reinterpret_cast<float*>(vsm);
    uint32_t* BsH = vsm + A_WORDS;
    uint32_t* BsL = BsH + B_WORDS;
    __shared__ float bestV[128][2];
    __shared__ int   bestI[128][2];
    __shared__ int   rowIdx[128];

    const int tid  = threadIdx.x;
    const int wid  = tid >> 5;
    const int lane = tid & 31;
    const int lr   = lane >> 2;
    const int lc   = lane & 3;
    const int m0   = blockIdx.x * 128;
    const int wm   = wid >> 1;
    const int wn   = wid & 1;

    float best[4];
    int   bidx[4];
    #pragma unroll
    for (int t = 0; t < 4; t++) { best[t] = -3.4e38f; bidx[t] = 0; }

    for (int nc = 0; nc < 4; nc++) {
        float acc[2][8][4];
        #pragma unroll
        for (int i = 0; i < 2; i++)
            #pragma unroll
            for (int j = 0; j < 8; j++)
                #pragma unroll
                for (int r = 0; r < 4; r++) acc[i][j][r] = 0.f;

        for (int s = 0; s < 4; s++) {
            const int k0 = s*32;
            #pragma unroll
            for (int it = 0; it < 4; it++) {
                int l = tid + it*256;
                int m = l >> 3, kq = l & 7;
                float4 v = *reinterpret_cast<const float4*>(&f[(m0 + m)*128 + k0 + kq*4]);
                *reinterpret_cast<float4*>(&AsF[m*ASTR + kq*4]) = v;
            }
            #pragma unroll
            for (int it = 0; it < 4; it++) {
                int l = tid + it*256;
                int co = (l & 31)*4;
                int kk = l >> 5;
                float4 w = *reinterpret_cast<const float4*>(&embT[(k0 + kk)*512 + nc*128 + co]);
                uint4 h;
                h.x = f2tf32(w.x); h.y = f2tf32(w.y); h.z = f2tf32(w.z); h.w = f2tf32(w.w);
                *reinterpret_cast<uint4*>(&BsH[kk*BSTR + co]) = h;
                uint4 lo;
                lo.x = f2tf32(w.x - __uint_as_float(h.x));
                lo.y = f2tf32(w.y - __uint_as_float(h.y));
                lo.z = f2tf32(w.z - __uint_as_float(h.z));
                lo.w = f2tf32(w.w - __uint_as_float(h.w));
                *reinterpret_cast<uint4*>(&BsL[kk*BSTR + co]) = lo;
            }
            __syncthreads();
            #pragma unroll
            for (int ks = 0; ks < 32; ks += 8) {
                uint32_t ah[2][4], al[2][4];
                #pragma unroll
                for (int i = 0; i < 2; i++) {
                    int r = wm*32 + i*16 + lr;
                    float v0 = AsF[(r    )*ASTR + ks + lc];
                    float v1 = AsF[(r + 8)*ASTR + ks + lc];
                    float v2 = AsF[(r    )*ASTR + ks + lc + 4];
                    float v3 = AsF[(r + 8)*ASTR + ks + lc + 4];
                    ah[i][0] = f2tf32(v0); ah[i][1] = f2tf32(v1);
                    ah[i][2] = f2tf32(v2); ah[i][3] = f2tf32(v3);
                    al[i][0] = f2tf32(v0 - __uint_as_float(ah[i][0]));
                    al[i][1] = f2tf32(v1 - __uint_as_float(ah[i][1]));
                    al[i][2] = f2tf32(v2 - __uint_as_float(ah[i][2]));
                    al[i][3] = f2tf32(v3 - __uint_as_float(ah[i][3]));
                }
                #pragma unroll
                for (int j = 0; j < 8; j++) {
                    int c = wn*64 + j*8 + lr;
                    uint32_t bh[2], bl[2];
                    bh[0] = BsH[(ks + lc    )*BSTR + c];
                    bh[1] = BsH[(ks + lc + 4)*BSTR + c];
                    bl[0] = BsL[(ks + lc    )*BSTR + c];
                    bl[1] = BsL[(ks + lc + 4)*BSTR + c];
                    #pragma unroll
                    for (int i = 0; i < 2; i++) {
                        mma_tf32(acc[i][j], al[i], bh);
                        mma_tf32(acc[i][j], ah[i], bl);
                        mma_tf32(acc[i][j], ah[i], bh);
                    }
                }
            }
            __syncthreads();
        }
        #pragma unroll
        for (int i = 0; i < 2; i++) {
            #pragma unroll
            for (int half = 0; half < 2; half++) {
                int slot = i*2 + half;
                #pragma unroll
                for (int j = 0; j < 8; j++) {
                    int col = nc*128 + wn*64 + j*8 + 2*lc;
                    float s0 = acc[i][j][half*2 + 0] - __ldg(&ehalf[col]);
                    float s1 = acc[i][j][half*2 + 1] - __ldg(&ehalf[col + 1]);
                    if (s0 > best[slot] || (s0 == best[slot] && col < bidx[slot]))
                        { best[slot] = s0; bidx[slot] = col; }
                    if (s1 > best[slot] || (s1 == best[slot] && col + 1 < bidx[slot]))
                        { best[slot] = s1; bidx[slot] = col + 1; }
                }
            }
        }
    }
    #pragma unroll
    for (int slot = 0; slot < 4; slot++) {
        #pragma unroll
        for (int off = 1; off < 4; off <<= 1) {
            float ov = __shfl_xor_sync(0xffffffffu, best[slot], off);
            int   oi = __shfl_xor_sync(0xffffffffu, bidx[slot], off);
            if (ov > best[slot] || (ov == best[slot] && oi < bidx[slot]))
                { best[slot] = ov; bidx[slot] = oi; }
        }
        if (lc == 0) {
            int i = slot >> 1, half = slot & 1;
            int row = wm*32 + i*16 + half*8 + lr;
            bestV[row][wn] = best[slot];
            bestI[row][wn] = bidx[slot];
        }
    }
    __syncthreads();
    for (int r = tid; r < 128; r += 256) {
        float v0 = bestV[r][0], v1 = bestV[r][1];
        int   i0 = bestI[r][0], i1 = bestI[r][1];
        rowIdx[r] = (v1 > v0 || (v1 == v0 && i1 < i0)) ? i1 : i0;
    }
    __syncthreads();
    for (int l = tid; l < 128*128; l += 256) {
        int r = l >> 7, j = l & 127;
        q[(m0 + r)*128 + j] = emb[rowIdx[r]*128 + j];
    }
}

// ======= dt2: 4x4 s2 tconv 64->3 — 4-parity fused =======
__global__ void __launch_bounds__(256)
dt2_fused(const float* __restrict__ in,
          const float* __restrict__ wgt,
          const float* __restrict__ bias,
          float* __restrict__ out)
{
    __shared__ float ws[4*4*64*3];
    for (int l = threadIdx.x; l < 3072; l += 256) ws[l] = wgt[l];
    __syncthreads();

    const int m = blockIdx.x * 256 + threadIdx.x;
    const int xq = m & 127; int t = m >> 7; const int yq = t & 127; const int n = t >> 7;

    float acc[4][3];
    #pragma unroll
    for (int p = 0; p < 4; p++)
        #pragma unroll
        for (int c = 0; c < 3; c++) acc[p][c] = __ldg(&bias[c]);

    const bool vy0 = (yq - 1 >= 0), vy2 = (yq + 1 < 128);
    const bool vx0 = (xq - 1 >= 0), vx2 = (xq + 1 < 128);
    const bool valid[3][3] = {
        { vy0 && vx0, vy0, vy0 && vx2 },
        { vx0,        true, vx2        },
        { vy2 && vx0, vy2, vy2 && vx2 }
    };
    const float* base = in + ((n*128 + yq)*128 + xq)*64;

    for (int cb = 0; cb < 64; cb += 4) {
        float4 p[3][3];
        #pragma unroll
        for (int dy = 0; dy < 3; dy++)
            #pragma unroll
            for (int dx = 0; dx < 3; dx++)
                p[dy][dx] = valid[dy][dx]
                    ? *reinterpret_cast<const float4*>(base + ((dy-1)*128 + (dx-1))*64 + cb)
                    : make_float4(0.f,0.f,0.f,0.f);
        #pragma unroll
        for (int py = 0; py < 2; py++)
            #pragma unroll
            for (int px = 0; px < 2; px++) {
                const int pi = py*2 + px;
                #pragma unroll
                for (int aa = 0; aa < 2; aa++)
                    #pragma unroll
                    for (int bb = 0; bb < 2; bb++) {
                        const float4 v = p[py + aa][px + bb];
                        const float* w0 = ws + (((2*aa + py)*4 + (2*bb + px))*64 + cb)*3;
                        #pragma unroll
                        for (int c = 0; c < 3; c++) {
                            acc[pi][c] += v.x*w0[c];
                            acc[pi][c] += v.y*w0[3 + c];
                            acc[pi][c] += v.z*w0[6 + c];
                            acc[pi][c] += v.w*w0[9 + c];
                        }
                    }
            }
    }
    #pragma unroll
    for (int py = 0; py < 2; py++)
        #pragma unroll
        for (int px = 0; px < 2; px++) {
            const int oy = 2*yq + py, ox = 2*xq + px;
            float* op = out + ((n*256 + oy)*256 + ox)*3;
            const int pi = py*2 + px;
            op[0] = acc[pi][0]; op[1] = acc[pi][1]; op[2] = acc[pi][2];
        }
}

// ======================= host launcher =======================
extern "C" void kernel_launch(void* const* d_in, const int* in_sizes, int n_in,
                              void* d_out, int out_size)
{
    (void)in_sizes; (void)n_in;
    const float* x       = (const float*)d_in[0];
    const float* emb     = (const float*)d_in[1];
    const float* enc_w1  = (const float*)d_in[2];
    const float* enc_b1  = (const float*)d_in[3];
    const float* enc_w2  = (const float*)d_in[4];
    const float* enc_b2  = (const float*)d_in[5];
    const float* enc_w3  = (const float*)d_in[6];
    const float* enc_b3  = (const float*)d_in[7];
    const float* erb1_w1 = (const float*)d_in[8];
    const float* erb1_w2 = (const float*)d_in[9];
    const float* erb2_w1 = (const float*)d_in[10];
    const float* erb2_w2 = (const float*)d_in[11];
    const float* dec_w   = (const float*)d_in[12];
    const float* dec_b   = (const float*)d_in[13];
    const float* drb1_w1 = (const float*)d_in[14];
    const float* drb1_w2 = (const float*)d_in[15];
    const float* drb2_w1 = (const float*)d_in[16];
    const float* drb2_w2 = (const float*)d_in[17];
    const float* dt1_w   = (const float*)d_in[18];
    const float* dt1_b   = (const float*)d_in[19];
    const float* dt2_w   = (const float*)d_in[20];
    const float* dt2_b   = (const float*)d_in[21];

    float* out = (float*)d_out;
    const int YS = 16*256*256*3;
    const int FS = 16*64*64*128;

    float *buf0,*buf1,*buf2,*embT,*ehalf,*fb,*qb;
    cudaGetSymbolAddress((void**)&buf0,  g_buf0);
    cudaGetSymbolAddress((void**)&buf1,  g_buf1);
    cudaGetSymbolAddress((void**)&buf2,  g_buf2);
    cudaGetSymbolAddress((void**)&embT,  g_embT);
    cudaGetSymbolAddress((void**)&ehalf, g_ehalf);
    cudaGetSymbolAddress((void**)&fb,    g_fbuf);
    cudaGetSymbolAddress((void**)&qb,    g_qbuf);

    const bool full = (out_size >= YS + 2*FS);
    float* fptr = full ? (out + YS)      : fb;
    float* qptr = full ? (out + YS + FS) : qb;

    dim3 b(256);

    const int SM3_128 = 2*(4608 + 2*4352)*4;    // 106496
    const int SM1_128 = 2*(4608 + 4352)*4;      // 71680
    const int SM1_64  = 2*(4608 + 2304)*4;      // 55296
    const int SM_VQ   = (4608 + 2*4352)*4;      // 53248
    // fused resblock: 2*(4608 + NCOPYB*1280) + 4608 + NCOPYB*4352 words
    const int SMR3 = (2*(4608 + 2*1280) + 4608 + 2*4352)*4;  // 110592
    const int SMR1 = (2*(4608 + 1280) + 4608 + 4352)*4;      // 82944

    auto kEnc2 = mma_conv7<128, 64,128,4,4,2,1, 128,128, false,true,false,true,false,3>;
    auto kEnc3 = mma_conv7<128, 128,128,3,3,1,1, 64,64, false,true,false,false,false,3>;
    auto kRes3F = mma_resblk<3,false>;
    auto kRes3T = mma_resblk<3,true>;
    auto kDec  = mma_conv7<128, 128,128,3,3,1,1, 64,64, false,true,false,false,false,1>;
    auto kRes1F = mma_resblk<1,false>;
    auto kRes1T = mma_resblk<1,true>;
    auto kDt1  = mma_conv7<128, 128,64, 4,4,2,0, 64,64, false,true,false,true,true,1>;

    cudaFuncSetAttribute(kEnc2, cudaFuncAttributeMaxDynamicSharedMemorySize, SM3_128);
    cudaFuncSetAttribute(kEnc3, cudaFuncAttributeMaxDynamicSharedMemorySize, SM3_128);
    cudaFuncSetAttribute(kRes3F, cudaFuncAttributeMaxDynamicSharedMemorySize, SMR3);
    cudaFuncSetAttribute(kRes3T, cudaFuncAttributeMaxDynamicSharedMemorySize, SMR3);
    cudaFuncSetAttribute(kDec,  cudaFuncAttributeMaxDynamicSharedMemorySize, SM1_128);
    cudaFuncSetAttribute(kRes1F, cudaFuncAttributeMaxDynamicSharedMemorySize, SMR1);
    cudaFuncSetAttribute(kRes1T, cudaFuncAttributeMaxDynamicSharedMemorySize, SMR1);
    cudaFuncSetAttribute(kDt1,  cudaFuncAttributeMaxDynamicSharedMemorySize, SM1_64);
    cudaFuncSetAttribute(vq_mma, cudaFuncAttributeMaxDynamicSharedMemorySize, SM_VQ);

    // ---- encoder (3xTF32) ----
    conv_gemm<64,64,16,4,4,  3,64,4,4,2,1, 256,256,16, false,true,false,true>
        <<<dim3(4096,1,1),b>>>(x, enc_w1, enc_b1, nullptr, buf0);
    kEnc2<<<dim3(512,1,1), b, SM3_128>>>(buf0, enc_w2, enc_b2, nullptr, buf1);
    kEnc3<<<dim3(512,1,1), b, SM3_128>>>(buf1, enc_w3, enc_b3, nullptr, buf2);
    kRes3F<<<dim3(512,1,1), b, SMR3>>>(buf2, erb1_w1, erb1_w2, buf1);
    kRes3T<<<dim3(512,1,1), b, SMR3>>>(buf1, erb2_w1, erb2_w2, fptr);

    // ---- VQ ----
    emb_prep<<<512,128>>>(emb, embT, ehalf);
    vq_mma<<<512, b, SM_VQ>>>(fptr, emb, embT, ehalf, qptr);

    // ---- decoder (single-pass tf32) ----
    kDec <<<dim3(512,1,1), b, SM1_128>>>(qptr, dec_w, dec_b, nullptr, buf1);
    kRes1F<<<dim3(512,1,1), b, SMR1>>>(buf1, drb1_w1, drb1_w2, buf2);
    kRes1T<<<dim3(512,1,1), b, SMR1>>>(buf2, drb2_w1, drb2_w2, buf1);
    kDt1 <<<dim3(512,1,4), b, SM1_64>>>(buf1, dt1_w, dt1_b, nullptr, buf0);

    dt2_fused<<<dim3(1024,1,1),b>>>(buf0, dt2_w, dt2_b, out);
}

// round 15
// speedup vs baseline: 2.3377x; 1.0022x over previous
#include <cuda_runtime.h>
#include <cstdint>

// ======================= device scratch (no cudaMalloc allowed) =======================
__device__ float g_buf0[16*128*128*64];   // enc1 out / dt1 out
__device__ float g_buf1[16*64*64*128];
__device__ float g_buf2[16*64*64*128];
__device__ float g_fbuf[16*64*64*128];
__device__ float g_qbuf[16*64*64*128];
__device__ float g_embT[128*512];
__device__ float g_ehalf[512];
__device__ float g_xpad[16*256*256*4];    // channel-padded input (16.8 MB)
__device__ float g_w1pad[4*4*4*64];       // channel-padded enc_w1

__device__ __forceinline__ uint32_t f2tf32(float x) {
    uint32_t r; asm("cvt.rna.tf32.f32 %0, %1;" : "=r"(r) : "f"(x)); return r;
}
__device__ __forceinline__ void mma_tf32(float* d, const uint32_t* a, const uint32_t* b) {
    asm volatile(
        "mma.sync.aligned.m16n8k8.row.col.f32.tf32.tf32.f32 "
        "{%0,%1,%2,%3}, {%4,%5,%6,%7}, {%8,%9}, {%0,%1,%2,%3};"
        : "+f"(d[0]), "+f"(d[1]), "+f"(d[2]), "+f"(d[3])
        : "r"(a[0]), "r"(a[1]), "r"(a[2]), "r"(a[3]), "r"(b[0]), "r"(b[1]));
}

// ======================= input/weight padding for enc1 (CIN 3 -> 4) =======================
__global__ void pad_input(const float* __restrict__ x, float* __restrict__ xp)
{
    int p = blockIdx.x*256 + threadIdx.x;            // 16*256*256 = 1048576 pixels
    if (p >= 16*256*256) return;
    float4 v;
    v.x = x[p*3 + 0]; v.y = x[p*3 + 1]; v.z = x[p*3 + 2]; v.w = 0.f;
    *reinterpret_cast<float4*>(&xp[p*4]) = v;
}
__global__ void pad_w1(const float* __restrict__ w, float* __restrict__ wp)
{
    int i = blockIdx.x*256 + threadIdx.x;            // 16*4*64 = 4096
    if (i >= 4096) return;
    int co = i & 63, ci = (i >> 6) & 3, tap = i >> 8;
    wp[i] = (ci < 3) ? w[(tap*3 + ci)*64 + co] : 0.f;
}

// ====== tf32 mma.sync implicit-GEMM conv (R13 config, unchanged) ======
template<int BM,int CIN,int COUT,int KH,int KW,int STRIDE,int PAD,int INH,int INW,
         bool RELU_IN,bool HAS_BIAS,bool ADD,bool RELU_OUT,bool TRANS,int SPLIT>
__global__ void __launch_bounds__(256)
mma_conv7(const float* __restrict__ in, const float* __restrict__ wgt,
          const float* __restrict__ bias, const float* __restrict__ addsrc,
          float* __restrict__ out)
{
    constexpr int MH = TRANS ? INH : INH / STRIDE;
    constexpr int MW = TRANS ? INW : INW / STRIDE;
    constexpr int K  = TRANS ? 4*CIN : KH*KW*CIN;
    constexpr int BK = 32, BN = COUT;
    constexpr int S  = K / BK;
    constexpr int WARPS_N = (BN >= 64) ? 2 : 1;
    constexpr int WARPS_M = 8 / WARPS_N;
    constexpr int WM = BM / WARPS_M;
    constexpr int WN = BN / WARPS_N;
    constexpr int MF = WM / 16;
    constexpr int NF = WN / 8;
    constexpr int ASTR = BK + 4;
    constexpr int BSTR = BN + 8;
    constexpr int A_WORDS = BM*ASTR;
    constexpr int B_WORDS = BK*BSTR;
    constexpr int NCOPYB = (SPLIT==3 ? 2 : 1);
    constexpr int CSZ = A_WORDS + NCOPYB*B_WORDS;
    constexpr int NAITER = BM/32;
    constexpr int NBREG = (BK*BN)/(4*256);

    extern __shared__ __align__(16) uint32_t smem[];

    const int tid  = threadIdx.x;
    const int wid  = tid >> 5;
    const int lane = tid & 31;
    const int m0   = blockIdx.x * BM;
    const int py   = TRANS ? (int)(blockIdx.z >> 1) : 0;
    const int px   = TRANS ? (int)(blockIdx.z & 1)  : 0;
    const int wm   = wid / WARPS_N;
    const int wn   = wid % WARPS_N;
    const int lr   = lane >> 2;
    const int lc   = lane & 3;

    float acc[MF][NF][4];
    #pragma unroll
    for (int i = 0; i < MF; i++)
        #pragma unroll
        for (int j = 0; j < NF; j++)
            #pragma unroll
            for (int r = 0; r < 4; r++) acc[i][j][r] = 0.f;

    float4 aR[NAITER];
    float4 bR[NBREG];

    auto load_regs = [&](int s) {
        const int k0 = s * BK;
        #pragma unroll
        for (int it = 0; it < NAITER; it++) {
            int l = tid + it*256;
            int m = l >> 3, kq = l & 7;
            int k = k0 + kq*4;
            int mg = m0 + m;
            int mx = mg % MW; int t = mg / MW; int my = t % MH; int n = t / MH;
            int iy, ix, ci;
            if (TRANS) {
                ci = k % CIN; int ab = k / CIN;
                int bb = ab & 1, aa = ab >> 1;
                iy = my + py + aa - 1;
                ix = mx + px + bb - 1;
            } else {
                ci = k % CIN; int r = k / CIN;
                int kw = r % KW, kh = r / KW;
                iy = my*STRIDE - PAD + kh;
                ix = mx*STRIDE - PAD + kw;
            }
            if (iy >= 0 && iy < INH && ix >= 0 && ix < INW)
                aR[it] = *reinterpret_cast<const float4*>(&in[((n*INH + iy)*INW + ix)*CIN + ci]);
            else
                aR[it] = make_float4(0.f,0.f,0.f,0.f);
        }
        #pragma unroll
        for (int it = 0; it < NBREG; it++) {
            int l = tid + it*256;
            int co = (l % (BN/4))*4;
            int kk = l / (BN/4);
            int k = k0 + kk;
            if (TRANS) {
                int ci = k % CIN; int ab = k / CIN;
                int bb = ab & 1, aa = ab >> 1;
                int widx = ((2*aa + py)*KW + (2*bb + px))*CIN + ci;
                bR[it] = *reinterpret_cast<const float4*>(&wgt[widx*COUT + co]);
            } else {
                bR[it] = *reinterpret_cast<const float4*>(&wgt[k*COUT + co]);
            }
        }
    };

    auto store_regs = [&](int buf) {
        float*    AsF = reinterpret_cast<float*>(smem + buf*CSZ);
        uint32_t* BsH = smem + buf*CSZ + A_WORDS;
        uint32_t* BsL = BsH + B_WORDS;
        #pragma unroll
        for (int it = 0; it < NAITER; it++) {
            int l = tid + it*256;
            int m = l >> 3, kq = l & 7;
            float4 v = aR[it];
            if (RELU_IN) {
                v.x = fmaxf(v.x, 0.f); v.y = fmaxf(v.y, 0.f);
                v.z = fmaxf(v.z, 0.f); v.w = fmaxf(v.w, 0.f);
            }
            *reinterpret_cast<float4*>(&AsF[m*ASTR + kq*4]) = v;
        }
        #pragma unroll
        for (int it = 0; it < NBREG; it++) {
            int l = tid + it*256;
            int co = (l % (BN/4))*4;
            int kk = l / (BN/4);
            float4 w = bR[it];
            uint4 h;
            h.x = f2tf32(w.x); h.y = f2tf32(w.y); h.z = f2tf32(w.z); h.w = f2tf32(w.w);
            *reinterpret_cast<uint4*>(&BsH[kk*BSTR + co]) = h;
            if (SPLIT == 3) {
                uint4 lo;
                lo.x = f2tf32(w.x - __uint_as_float(h.x));
                lo.y = f2tf32(w.y - __uint_as_float(h.y));
                lo.z = f2tf32(w.z - __uint_as_float(h.z));
                lo.w = f2tf32(w.w - __uint_as_float(h.w));
                *reinterpret_cast<uint4*>(&BsL[kk*BSTR + co]) = lo;
            }
        }
    };

    auto compute = [&](int buf) {
        const float*    AsF = reinterpret_cast<const float*>(smem + buf*CSZ);
        const uint32_t* BsH = smem + buf*CSZ + A_WORDS;
        const uint32_t* BsL = BsH + B_WORDS;
        #pragma unroll
        for (int ks = 0; ks < BK; ks += 8) {
            uint32_t ah[MF][4], al[MF][4];
            #pragma unroll
            for (int i = 0; i < MF; i++) {
                int r = wm*WM + i*16 + lr;
                float v0 = AsF[(r    )*ASTR + ks + lc];
                float v1 = AsF[(r + 8)*ASTR + ks + lc];
                float v2 = AsF[(r    )*ASTR + ks + lc + 4];
                float v3 = AsF[(r + 8)*ASTR + ks + lc + 4];
                ah[i][0] = f2tf32(v0); ah[i][1] = f2tf32(v1);
                ah[i][2] = f2tf32(v2); ah[i][3] = f2tf32(v3);
                if (SPLIT == 3) {
                    al[i][0] = f2tf32(v0 - __uint_as_float(ah[i][0]));
                    al[i][1] = f2tf32(v1 - __uint_as_float(ah[i][1]));
                    al[i][2] = f2tf32(v2 - __uint_as_float(ah[i][2]));
                    al[i][3] = f2tf32(v3 - __uint_as_float(ah[i][3]));
                }
            }
            #pragma unroll
            for (int j = 0; j < NF; j++) {
                int c = wn*WN + j*8 + lr;
                uint32_t bh[2], bl[2];
                bh[0] = BsH[(ks + lc    )*BSTR + c];
                bh[1] = BsH[(ks + lc + 4)*BSTR + c];
                if (SPLIT == 3) {
                    bl[0] = BsL[(ks + lc    )*BSTR + c];
                    bl[1] = BsL[(ks + lc + 4)*BSTR + c];
                }
                #pragma unroll
                for (int i = 0; i < MF; i++) {
                    if (SPLIT == 3) {
                        mma_tf32(acc[i][j], al[i], bh);
                        mma_tf32(acc[i][j], ah[i], bl);
                    }
                    mma_tf32(acc[i][j], ah[i], bh);
                }
            }
        }
    };

    load_regs(0);
    store_regs(0);
    __syncthreads();
    for (int s = 0; s < S; s++) {
        if (s + 1 < S) load_regs(s + 1);
        compute(s & 1);
        if (s + 1 < S) store_regs((s + 1) & 1);
        __syncthreads();
    }

    #pragma unroll
    for (int i = 0; i < MF; i++) {
        int r0 = m0 + wm*WM + i*16 + lr;
        #pragma unroll
        for (int half = 0; half < 2; half++) {
            int mg = r0 + half*8;
            int obase;
            if (TRANS) {
                int mx = mg % MW; int t = mg / MW; int my = t % MH; int n = t / MH;
                obase = ((n*(2*INH) + 2*my + py)*(2*INW) + 2*mx + px)*COUT;
            } else {
                obase = mg*COUT;
            }
            #pragma unroll
            for (int j = 0; j < NF; j++) {
                int c = wn*WN + j*8 + 2*lc;
                float v0 = acc[i][j][half*2 + 0];
                float v1 = acc[i][j][half*2 + 1];
                if (HAS_BIAS) {
                    float2 bv = *reinterpret_cast<const float2*>(&bias[c]);
                    v0 += bv.x; v1 += bv.y;
                }
                if (ADD) {
                    float2 av = *reinterpret_cast<const float2*>(&addsrc[obase + c]);
                    v0 += av.x; v1 += av.y;
                }
                if (RELU_OUT) { v0 = fmaxf(v0, 0.f); v1 = fmaxf(v1, 0.f); }
                float2 ov; ov.x = v0; ov.y = v1;
                *reinterpret_cast<float2*>(&out[obase + c]) = ov;
            }
        }
    }
}

// ====== fused residual block (R14, unchanged) ======
template<int SPLIT, bool RELU_OUT2>
__global__ void __launch_bounds__(256)
mma_resblk(const float* __restrict__ in, const float* __restrict__ w1,
           const float* __restrict__ w2, float* __restrict__ out)
{
    constexpr int INH=64, INW=64, CIN=128, K1=1152, BK=32, S=K1/BK;
    constexpr int ASTR=36, A_WORDS=128*ASTR;
    constexpr int B1STR=40, B1_WORDS=BK*B1STR;
    constexpr int NCOPYB=(SPLIT==3?2:1);
    constexpr int CSZ=A_WORDS+NCOPYB*B1_WORDS;
    constexpr int MID_OFF=2*CSZ;
    constexpr int W2_OFF=MID_OFF+A_WORDS;
    constexpr int B2STR=136, B2_WORDS=BK*B2STR;

    extern __shared__ __align__(16) uint32_t smem[];

    const int tid=threadIdx.x, wid=tid>>5, lane=tid&31;
    const int lr=lane>>2, lc=lane&3;
    const int m0=blockIdx.x*128;

    {
        uint32_t* W2H = smem + W2_OFF;
        uint32_t* W2L = W2H + B2_WORDS;
        #pragma unroll
        for (int it=0; it<4; it++){
            int l=tid+it*256;
            int co=(l&31)*4, kk=l>>5;
            float4 w=*reinterpret_cast<const float4*>(&w2[kk*128+co]);
            uint4 h; h.x=f2tf32(w.x); h.y=f2tf32(w.y); h.z=f2tf32(w.z); h.w=f2tf32(w.w);
            *reinterpret_cast<uint4*>(&W2H[kk*B2STR+co])=h;
            if (SPLIT==3){
                uint4 lo;
                lo.x=f2tf32(w.x-__uint_as_float(h.x));
                lo.y=f2tf32(w.y-__uint_as_float(h.y));
                lo.z=f2tf32(w.z-__uint_as_float(h.z));
                lo.w=f2tf32(w.w-__uint_as_float(h.w));
                *reinterpret_cast<uint4*>(&W2L[kk*B2STR+co])=lo;
            }
        }
    }

    float acc1[4][4];
    #pragma unroll
    for (int j=0;j<4;j++)
        #pragma unroll
        for (int r=0;r<4;r++) acc1[j][r]=0.f;

    float4 aR[4];
    float4 bR1;

    auto load_regs=[&](int s){
        const int k0=s*BK;
        #pragma unroll
        for (int it=0; it<4; it++){
            int l=tid+it*256;
            int m=l>>3, kq=l&7;
            int k=k0+kq*4;
            int mg=m0+m;
            int mx=mg&63; int t=mg>>6; int my=t&63; int n=t>>6;
            int ci=k&127; int r=k>>7;
            int kw=r%3, kh=r/3;
            int iy=my+kh-1, ix=mx+kw-1;
            if (iy>=0 && iy<INH && ix>=0 && ix<INW)
                aR[it]=*reinterpret_cast<const float4*>(&in[((n*INH+iy)*INW+ix)*CIN+ci]);
            else
                aR[it]=make_float4(0.f,0.f,0.f,0.f);
        }
        { int co=(tid&7)*4, kk=tid>>3;
          bR1=*reinterpret_cast<const float4*>(&w1[(k0+kk)*32+co]); }
    };
    auto store_regs=[&](int buf){
        float* AsF=reinterpret_cast<float*>(smem+buf*CSZ);
        uint32_t* BsH=smem+buf*CSZ+A_WORDS;
        uint32_t* BsL=BsH+B1_WORDS;
        #pragma unroll
        for (int it=0; it<4; it++){
            int l=tid+it*256;
            int m=l>>3, kq=l&7;
            float4 v=aR[it];
            v.x=fmaxf(v.x,0.f); v.y=fmaxf(v.y,0.f);
            v.z=fmaxf(v.z,0.f); v.w=fmaxf(v.w,0.f);
            *reinterpret_cast<float4*>(&AsF[m*ASTR+kq*4])=v;
        }
        {
            int co=(tid&7)*4, kk=tid>>3;
            float4 w=bR1;
            uint4 h; h.x=f2tf32(w.x); h.y=f2tf32(w.y); h.z=f2tf32(w.z); h.w=f2tf32(w.w);
            *reinterpret_cast<uint4*>(&BsH[kk*B1STR+co])=h;
            if (SPLIT==3){
                uint4 lo;
                lo.x=f2tf32(w.x-__uint_as_float(h.x));
                lo.y=f2tf32(w.y-__uint_as_float(h.y));
                lo.z=f2tf32(w.z-__uint_as_float(h.z));
                lo.w=f2tf32(w.w-__uint_as_float(h.w));
                *reinterpret_cast<uint4*>(&BsL[kk*B1STR+co])=lo;
            }
        }
    };
    auto compute=[&](int buf){
        const float* AsF=reinterpret_cast<const float*>(smem+buf*CSZ);
        const uint32_t* BsH=smem+buf*CSZ+A_WORDS;
        const uint32_t* BsL=BsH+B1_WORDS;
        #pragma unroll
        for (int ks=0; ks<BK; ks+=8){
            uint32_t ah[4], al[4];
            int r=wid*16+lr;
            float v0=AsF[(r  )*ASTR+ks+lc];
            float v1=AsF[(r+8)*ASTR+ks+lc];
            float v2=AsF[(r  )*ASTR+ks+lc+4];
            float v3=AsF[(r+8)*ASTR+ks+lc+4];
            ah[0]=f2tf32(v0); ah[1]=f2tf32(v1); ah[2]=f2tf32(v2); ah[3]=f2tf32(v3);
            if (SPLIT==3){
                al[0]=f2tf32(v0-__uint_as_float(ah[0]));
                al[1]=f2tf32(v1-__uint_as_float(ah[1]));
                al[2]=f2tf32(v2-__uint_as_float(ah[2]));
                al[3]=f2tf32(v3-__uint_as_float(ah[3]));
            }
            #pragma unroll
            for (int j=0;j<4;j++){
                int c=j*8+lr;
                uint32_t bh[2], bl[2];
                bh[0]=BsH[(ks+lc  )*B1STR+c];
                bh[1]=BsH[(ks+lc+4)*B1STR+c];
                if (SPLIT==3){
                    bl[0]=BsL[(ks+lc  )*B1STR+c];
                    bl[1]=BsL[(ks+lc+4)*B1STR+c];
                    mma_tf32(acc1[j], al, bh);
                    mma_tf32(acc1[j], ah, bl);
                }
                mma_tf32(acc1[j], ah, bh);
            }
        }
    };

    load_regs(0);
    store_regs(0);
    __syncthreads();
    for (int s=0; s<S; s++){
        if (s+1<S) load_regs(s+1);
        compute(s&1);
        if (s+1<S) store_regs((s+1)&1);
        __syncthreads();
    }

    {
        float* midA=reinterpret_cast<float*>(smem+MID_OFF);
        #pragma unroll
        for (int half=0; half<2; half++){
            int mg=wid*16+half*8+lr;
            #pragma unroll
            for (int j=0;j<4;j++){
                int c=j*8+2*lc;
                midA[mg*ASTR+c  ]=fmaxf(acc1[j][half*2+0],0.f);
                midA[mg*ASTR+c+1]=fmaxf(acc1[j][half*2+1],0.f);
            }
        }
    }
    __syncthreads();

    const int wm2=wid>>1, wn2=wid&1;
    float acc2[2][8][4];
    #pragma unroll
    for (int i=0;i<2;i++)
        #pragma unroll
        for (int j=0;j<8;j++)
            #pragma unroll
            for (int r=0;r<4;r++) acc2[i][j][r]=0.f;

    {
        const float* A2=reinterpret_cast<const float*>(smem+MID_OFF);
        const uint32_t* W2H=smem+W2_OFF;
        const uint32_t* W2L=W2H+B2_WORDS;
        #pragma unroll
        for (int ks=0; ks<32; ks+=8){
            uint32_t ah[2][4], al[2][4];
            #pragma unroll
            for (int i=0;i<2;i++){
                int r=wm2*32+i*16+lr;
                float v0=A2[(r  )*ASTR+ks+lc];
                float v1=A2[(r+8)*ASTR+ks+lc];
                float v2=A2[(r  )*ASTR+ks+lc+4];
                float v3=A2[(r+8)*ASTR+ks+lc+4];
                ah[i][0]=f2tf32(v0); ah[i][1]=f2tf32(v1);
                ah[i][2]=f2tf32(v2); ah[i][3]=f2tf32(v3);
                if (SPLIT==3){
                    al[i][0]=f2tf32(v0-__uint_as_float(ah[i][0]));
                    al[i][1]=f2tf32(v1-__uint_as_float(ah[i][1]));
                    al[i][2]=f2tf32(v2-__uint_as_float(ah[i][2]));
                    al[i][3]=f2tf32(v3-__uint_as_float(ah[i][3]));
                }
            }
            #pragma unroll
            for (int j=0;j<8;j++){
                int c=wn2*64+j*8+lr;
                uint32_t bh[2], bl[2];
                bh[0]=W2H[(ks+lc  )*B2STR+c];
                bh[1]=W2H[(ks+lc+4)*B2STR+c];
                if (SPLIT==3){
                    bl[0]=W2L[(ks+lc  )*B2STR+c];
                    bl[1]=W2L[(ks+lc+4)*B2STR+c];
                }
                #pragma unroll
                for (int i=0;i<2;i++){
                    if (SPLIT==3){
                        mma_tf32(acc2[i][j], al[i], bh);
                        mma_tf32(acc2[i][j], ah[i], bl);
                    }
                    mma_tf32(acc2[i][j], ah[i], bh);
                }
            }
        }
    }
    #pragma unroll
    for (int i=0;i<2;i++){
        #pragma unroll
        for (int half=0; half<2; half++){
            int mg=m0+wm2*32+i*16+half*8+lr;
            int obase=mg*128;
            #pragma unroll
            for (int j=0;j<8;j++){
                int c=wn2*64+j*8+2*lc;
                float v0=acc2[i][j][half*2+0];
                float v1=acc2[i][j][half*2+1];
                float2 rv=*reinterpret_cast<const float2*>(&in[obase+c]);
                v0+=rv.x; v1+=rv.y;
                if (RELU_OUT2){ v0=fmaxf(v0,0.f); v1=fmaxf(v1,0.f); }
                float2 ov; ov.x=v0; ov.y=v1;
                *reinterpret_cast<float2*>(&out[obase+c])=ov;
            }
        }
    }
}

// ======================= codebook prep =======================
__global__ void emb_prep(const float* __restrict__ emb,
                         float* __restrict__ embT, float* __restrict__ ehalf)
{
    int c = blockIdx.x;
    int k = threadIdx.x;
    float v = emb[c*128 + k];
    embT[k*512 + c] = v;
    float s = v*v;
    #pragma unroll
    for (int o = 16; o; o >>= 1) s += __shfl_xor_sync(0xffffffffu, s, o);
    __shared__ float red[4];
    if ((k & 31) == 0) red[k >> 5] = s;
    __syncthreads();
    if (k == 0) ehalf[c] = 0.5f*(red[0]+red[1]+red[2]+red[3]);
}

// ======================= VQ via 3xTF32 tensor GEMM + fragment argmax =======================
__global__ void __launch_bounds__(256)
vq_mma(const float* __restrict__ f, const float* __restrict__ emb,
       const float* __restrict__ embT, const float* __restrict__ ehalf,
       float* __restrict__ q)
{
    constexpr int ASTR = 36, BSTR = 136;
    constexpr int A_WORDS = 128*ASTR, B_WORDS = 32*BSTR;
    extern __shared__ __align__(16) uint32_t vsm[];
    float*    AsF = reinterpret_cast<float*>(vsm);
    uint32_t* BsH = vsm + A_WORDS;
    uint32_t* BsL = BsH + B_WORDS;
    __shared__ float bestV[128][2];
    __shared__ int   bestI[128][2];
    __shared__ int   rowIdx[128];

    const int tid  = threadIdx.x;
    const int wid  = tid >> 5;
    const int lane = tid & 31;
    const int lr   = lane >> 2;
    const int lc   = lane & 3;
    const int m0   = blockIdx.x * 128;
    const int wm   = wid >> 1;
    const int wn   = wid & 1;

    float best[4];
    int   bidx[4];
    #pragma unroll
    for (int t = 0; t < 4; t++) { best[t] = -3.4e38f; bidx[t] = 0; }

    for (int nc = 0; nc < 4; nc++) {
        float acc[2][8][4];
        #pragma unroll
        for (int i = 0; i < 2; i++)
            #pragma unroll
            for (int j = 0; j < 8; j++)
                #pragma unroll
                for (int r = 0; r < 4; r++) acc[i][j][r] = 0.f;

        for (int s = 0; s < 4; s++) {
            const int k0 = s*32;
            #pragma unroll
            for (int it = 0; it < 4; it++) {
                int l = tid + it*256;
                int m = l >> 3, kq = l & 7;
                float4 v = *reinterpret_cast<const float4*>(&f[(m0 + m)*128 + k0 + kq*4]);
                *reinterpret_cast<float4*>(&AsF[m*ASTR + kq*4]) = v;
            }
            #pragma unroll
            for (int it = 0; it < 4; it++) {
                int l = tid + it*256;
                int co = (l & 31)*4;
                int kk = l >> 5;
                float4 w = *reinterpret_cast<const float4*>(&embT[(k0 + kk)*512 + nc*128 + co]);
                uint4 h;
                h.x = f2tf32(w.x); h.y = f2tf32(w.y); h.z = f2tf32(w.z); h.w = f2tf32(w.w);
                *reinterpret_cast<uint4*>(&BsH[kk*BSTR + co]) = h;
                uint4 lo;
                lo.x = f2tf32(w.x - __uint_as_float(h.x));
                lo.y = f2tf32(w.y - __uint_as_float(h.y));
                lo.z = f2tf32(w.z - __uint_as_float(h.z));
                lo.w = f2tf32(w.w - __uint_as_float(h.w));
                *reinterpret_cast<uint4*>(&BsL[kk*BSTR + co]) = lo;
            }
            __syncthreads();
            #pragma unroll
            for (int ks = 0; ks < 32; ks += 8) {
                uint32_t ah[2][4], al[2][4];
                #pragma unroll
                for (int i = 0; i < 2; i++) {
                    int r = wm*32 + i*16 + lr;
                    float v0 = AsF[(r    )*ASTR + ks + lc];
                    float v1 = AsF[(r + 8)*ASTR + ks + lc];
                    float v2 = AsF[(r    )*ASTR + ks + lc + 4];
                    float v3 = AsF[(r + 8)*ASTR + ks + lc + 4];
                    ah[i][0] = f2tf32(v0); ah[i][1] = f2tf32(v1);
                    ah[i][2] = f2tf32(v2); ah[i][3] = f2tf32(v3);
                    al[i][0] = f2tf32(v0 - __uint_as_float(ah[i][0]));
                    al[i][1] = f2tf32(v1 - __uint_as_float(ah[i][1]));
                    al[i][2] = f2tf32(v2 - __uint_as_float(ah[i][2]));
                    al[i][3] = f2tf32(v3 - __uint_as_float(ah[i][3]));
                }
                #pragma unroll
                for (int j = 0; j < 8; j++) {
                    int c = wn*64 + j*8 + lr;
                    uint32_t bh[2], bl[2];
                    bh[0] = BsH[(ks + lc    )*BSTR + c];
                    bh[1] = BsH[(ks + lc + 4)*BSTR + c];
                    bl[0] = BsL[(ks + lc    )*BSTR + c];
                    bl[1] = BsL[(ks + lc + 4)*BSTR + c];
                    #pragma unroll
                    for (int i = 0; i < 2; i++) {
                        mma_tf32(acc[i][j], al[i], bh);
                        mma_tf32(acc[i][j], ah[i], bl);
                        mma_tf32(acc[i][j], ah[i], bh);
                    }
                }
            }
            __syncthreads();
        }
        #pragma unroll
        for (int i = 0; i < 2; i++) {
            #pragma unroll
            for (int half = 0; half < 2; half++) {
                int slot = i*2 + half;
                #pragma unroll
                for (int j = 0; j < 8; j++) {
                    int col = nc*128 + wn*64 + j*8 + 2*lc;
                    float s0 = acc[i][j][half*2 + 0] - __ldg(&ehalf[col]);
                    float s1 = acc[i][j][half*2 + 1] - __ldg(&ehalf[col + 1]);
                    if (s0 > best[slot] || (s0 == best[slot] && col < bidx[slot]))
                        { best[slot] = s0; bidx[slot] = col; }
                    if (s1 > best[slot] || (s1 == best[slot] && col + 1 < bidx[slot]))
                        { best[slot] = s1; bidx[slot] = col + 1; }
                }
            }
        }
    }
    #pragma unroll
    for (int slot = 0; slot < 4; slot++) {
        #pragma unroll
        for (int off = 1; off < 4; off <<= 1) {
            float ov = __shfl_xor_sync(0xffffffffu, best[slot], off);
            int   oi = __shfl_xor_sync(0xffffffffu, bidx[slot], off);
            if (ov > best[slot] || (ov == best[slot] && oi < bidx[slot]))
                { best[slot] = ov; bidx[slot] = oi; }
        }
        if (lc == 0) {
            int i = slot >> 1, half = slot & 1;
            int row = wm*32 + i*16 + half*8 + lr;
            bestV[row][wn] = best[slot];
            bestI[row][wn] = bidx[slot];
        }
    }
    __syncthreads();
    for (int r = tid; r < 128; r += 256) {
        float v0 = bestV[r][0], v1 = bestV[r][1];
        int   i0 = bestI[r][0], i1 = bestI[r][1];
        rowIdx[r] = (v1 > v0 || (v1 == v0 && i1 < i0)) ? i1 : i0;
    }
    __syncthreads();
    for (int l = tid; l < 128*128; l += 256) {
        int r = l >> 7, j = l & 127;
        q[(m0 + r)*128 + j] = emb[rowIdx[r]*128 + j];
    }
}

// ======= dt2: 4x4 s2 tconv 64->3 — 4-parity fused =======
__global__ void __launch_bounds__(256)
dt2_fused(const float* __restrict__ in,
          const float* __restrict__ wgt,
          const float* __restrict__ bias,
          float* __restrict__ out)
{
    __shared__ float ws[4*4*64*3];
    for (int l = threadIdx.x; l < 3072; l += 256) ws[l] = wgt[l];
    __syncthreads();

    const int m = blockIdx.x * 256 + threadIdx.x;
    const int xq = m & 127; int t = m >> 7; const int yq = t & 127; const int n = t >> 7;

    float acc[4][3];
    #pragma unroll
    for (int p = 0; p < 4; p++)
        #pragma unroll
        for (int c = 0; c < 3; c++) acc[p][c] = __ldg(&bias[c]);

    const bool vy0 = (yq - 1 >= 0), vy2 = (yq + 1 < 128);
    const bool vx0 = (xq - 1 >= 0), vx2 = (xq + 1 < 128);
    const bool valid[3][3] = {
        { vy0 && vx0, vy0, vy0 && vx2 },
        { vx0,        true, vx2        },
        { vy2 && vx0, vy2, vy2 && vx2 }
    };
    const float* base = in + ((n*128 + yq)*128 + xq)*64;

    for (int cb = 0; cb < 64; cb += 4) {
        float4 p[3][3];
        #pragma unroll
        for (int dy = 0; dy < 3; dy++)
            #pragma unroll
            for (int dx = 0; dx < 3; dx++)
                p[dy][dx] = valid[dy][dx]
                    ? *reinterpret_cast<const float4*>(base + ((dy-1)*128 + (dx-1))*64 + cb)
                    : make_float4(0.f,0.f,0.f,0.f);
        #pragma unroll
        for (int py = 0; py < 2; py++)
            #pragma unroll
            for (int px = 0; px < 2; px++) {
                const int pi = py*2 + px;
                #pragma unroll
                for (int aa = 0; aa < 2; aa++)
                    #pragma unroll
                    for (int bb = 0; bb < 2; bb++) {
                        const float4 v = p[py + aa][px + bb];
                        const float* w0 = ws + (((2*aa + py)*4 + (2*bb + px))*64 + cb)*3;
                        #pragma unroll
                        for (int c = 0; c < 3; c++) {
                            acc[pi][c] += v.x*w0[c];
                            acc[pi][c] += v.y*w0[3 + c];
                            acc[pi][c] += v.z*w0[6 + c];
                            acc[pi][c] += v.w*w0[9 + c];
                        }
                    }
            }
    }
    #pragma unroll
    for (int py = 0; py < 2; py++)
        #pragma unroll
        for (int px = 0; px < 2; px++) {
            const int oy = 2*yq + py, ox = 2*xq + px;
            float* op = out + ((n*256 + oy)*256 + ox)*3;
            const int pi = py*2 + px;
            op[0] = acc[pi][0]; op[1] = acc[pi][1]; op[2] = acc[pi][2];
        }
}

// ======================= host launcher =======================
extern "C" void kernel_launch(void* const* d_in, const int* in_sizes, int n_in,
                              void* d_out, int out_size)
{
    (void)in_sizes; (void)n_in;
    const float* x       = (const float*)d_in[0];
    const float* emb     = (const float*)d_in[1];
    const float* enc_w1  = (const float*)d_in[2];
    const float* enc_b1  = (const float*)d_in[3];
    const float* enc_w2  = (const float*)d_in[4];
    const float* enc_b2  = (const float*)d_in[5];
    const float* enc_w3  = (const float*)d_in[6];
    const float* enc_b3  = (const float*)d_in[7];
    const float* erb1_w1 = (const float*)d_in[8];
    const float* erb1_w2 = (const float*)d_in[9];
    const float* erb2_w1 = (const float*)d_in[10];
    const float* erb2_w2 = (const float*)d_in[11];
    const float* dec_w   = (const float*)d_in[12];
    const float* dec_b   = (const float*)d_in[13];
    const float* drb1_w1 = (const float*)d_in[14];
    const float* drb1_w2 = (const float*)d_in[15];
    const float* drb2_w1 = (const float*)d_in[16];
    const float* drb2_w2 = (const float*)d_in[17];
    const float* dt1_w   = (const float*)d_in[18];
    const float* dt1_b   = (const float*)d_in[19];
    const float* dt2_w   = (const float*)d_in[20];
    const float* dt2_b   = (const float*)d_in[21];

    float* out = (float*)d_out;
    const int YS = 16*256*256*3;
    const int FS = 16*64*64*128;

    float *buf0,*buf1,*buf2,*embT,*ehalf,*fb,*qb,*xpad,*w1pad;
    cudaGetSymbolAddress((void**)&buf0,  g_buf0);
    cudaGetSymbolAddress((void**)&buf1,  g_buf1);
    cudaGetSymbolAddress((void**)&buf2,  g_buf2);
    cudaGetSymbolAddress((void**)&embT,  g_embT);
    cudaGetSymbolAddress((void**)&ehalf, g_ehalf);
    cudaGetSymbolAddress((void**)&fb,    g_fbuf);
    cudaGetSymbolAddress((void**)&qb,    g_qbuf);
    cudaGetSymbolAddress((void**)&xpad,  g_xpad);
    cudaGetSymbolAddress((void**)&w1pad, g_w1pad);

    const bool full = (out_size >= YS + 2*FS);
    float* fptr = full ? (out + YS)      : fb;
    float* qptr = full ? (out + YS + FS) : qb;

    dim3 b(256);

    const int SM3_128 = 2*(4608 + 2*4352)*4;    // 106496
    const int SM3_64  = 2*(4608 + 2*2304)*4;    // 73728
    const int SM1_128 = 2*(4608 + 4352)*4;      // 71680
    const int SM1_64  = 2*(4608 + 2304)*4;      // 55296
    const int SM_VQ   = (4608 + 2*4352)*4;      // 53248
    const int SMR3 = (2*(4608 + 2*1280) + 4608 + 2*4352)*4;  // 110592
    const int SMR1 = (2*(4608 + 1280) + 4608 + 4352)*4;      // 82944

    auto kEnc1 = mma_conv7<128, 4,64, 4,4,2,1, 256,256, false,true,false,true,false,3>;
    auto kEnc2 = mma_conv7<128, 64,128,4,4,2,1, 128,128, false,true,false,true,false,3>;
    auto kEnc3 = mma_conv7<128, 128,128,3,3,1,1, 64,64, false,true,false,false,false,3>;
    auto kRes3F = mma_resblk<3,false>;
    auto kRes3T = mma_resblk<3,true>;
    auto kDec  = mma_conv7<128, 128,128,3,3,1,1, 64,64, false,true,false,false,false,1>;
    auto kRes1F = mma_resblk<1,false>;
    auto kRes1T = mma_resblk<1,true>;
    auto kDt1  = mma_conv7<128, 128,64, 4,4,2,0, 64,64, false,true,false,true,true,1>;

    cudaFuncSetAttribute(kEnc1, cudaFuncAttributeMaxDynamicSharedMemorySize, SM3_64);
    cudaFuncSetAttribute(kEnc2, cudaFuncAttributeMaxDynamicSharedMemorySize, SM3_128);
    cudaFuncSetAttribute(kEnc3, cudaFuncAttributeMaxDynamicSharedMemorySize, SM3_128);
    cudaFuncSetAttribute(kRes3F, cudaFuncAttributeMaxDynamicSharedMemorySize, SMR3);
    cudaFuncSetAttribute(kRes3T, cudaFuncAttributeMaxDynamicSharedMemorySize, SMR3);
    cudaFuncSetAttribute(kDec,  cudaFuncAttributeMaxDynamicSharedMemorySize, SM1_128);
    cudaFuncSetAttribute(kRes1F, cudaFuncAttributeMaxDynamicSharedMemorySize, SMR1);
    cudaFuncSetAttribute(kRes1T, cudaFuncAttributeMaxDynamicSharedMemorySize, SMR1);
    cudaFuncSetAttribute(kDt1,  cudaFuncAttributeMaxDynamicSharedMemorySize, SM1_64);
    cudaFuncSetAttribute(vq_mma, cudaFuncAttributeMaxDynamicSharedMemorySize, SM_VQ);

    // ---- enc1 prep: pad channels 3->4 ----
    pad_input<<<dim3(4096,1,1), b>>>(x, xpad);
    pad_w1<<<dim3(16,1,1), b>>>(enc_w1, w1pad);

    // ---- encoder (3xTF32, ~fp32 precision -> argmin-exact) ----
    kEnc1<<<dim3(2048,1,1), b, SM3_64>>>(xpad, w1pad, enc_b1, nullptr, buf0);
    kEnc2<<<dim3(512,1,1), b, SM3_128>>>(buf0, enc_w2, enc_b2, nullptr, buf1);
    kEnc3<<<dim3(512,1,1), b, SM3_128>>>(buf1, enc_w3, enc_b3, nullptr, buf2);
    kRes3F<<<dim3(512,1,1), b, SMR3>>>(buf2, erb1_w1, erb1_w2, buf1);
    kRes3T<<<dim3(512,1,1), b, SMR3>>>(buf1, erb2_w1, erb2_w2, fptr);

    // ---- VQ ----
    emb_prep<<<512,128>>>(emb, embT, ehalf);
    vq_mma<<<512, b, SM_VQ>>>(fptr, emb, embT, ehalf, qptr);

    // ---- decoder (single-pass tf32) ----
    kDec <<<dim3(512,1,1), b, SM1_128>>>(qptr, dec_w, dec_b, nullptr, buf1);
    kRes1F<<<dim3(512,1,1), b, SMR1>>>(buf1, drb1_w1, drb1_w2, buf2);
    kRes1T<<<dim3(512,1,1), b, SMR1>>>(buf2, drb2_w1, drb2_w2, buf1);
    kDt1 <<<dim3(512,1,4), b, SM1_64>>>(buf1, dt1_w, dt1_b, nullptr, buf0);

    dt2_fused<<<dim3(1024,1,1),b>>>(buf0, dt2_w, dt2_b, out);
}

// round 16
// speedup vs baseline: 2.3831x; 1.0194x over previous
#include <cuda_runtime.h>
#include <cstdint>

// ======================= device scratch (no cudaMalloc allowed) =======================
__device__ float g_buf0[16*128*128*64];   // enc1 out / dt1 out
__device__ float g_buf1[16*64*64*128];
__device__ float g_buf2[16*64*64*128];
__device__ float g_fbuf[16*64*64*128];
__device__ float g_qbuf[16*64*64*128];
__device__ float g_embT[128*512];
__device__ float g_ehalf[512];
__device__ float g_xpad[16*256*256*4];    // channel-padded input (16.8 MB)
__device__ float g_w1pad[4*4*4*64];       // channel-padded enc_w1

__device__ __forceinline__ uint32_t f2tf32(float x) {
    uint32_t r; asm("cvt.rna.tf32.f32 %0, %1;" : "=r"(r) : "f"(x)); return r;
}
__device__ __forceinline__ void mma_tf32(float* d, const uint32_t* a, const uint32_t* b) {
    asm volatile(
        "mma.sync.aligned.m16n8k8.row.col.f32.tf32.tf32.f32 "
        "{%0,%1,%2,%3}, {%4,%5,%6,%7}, {%8,%9}, {%0,%1,%2,%3};"
        : "+f"(d[0]), "+f"(d[1]), "+f"(d[2]), "+f"(d[3])
        : "r"(a[0]), "r"(a[1]), "r"(a[2]), "r"(a[3]), "r"(b[0]), "r"(b[1]));
}

// ======================= input/weight padding for enc1 (CIN 3 -> 4) =======================
__global__ void pad_input(const float* __restrict__ x, float* __restrict__ xp)
{
    int p = blockIdx.x*256 + threadIdx.x;
    if (p >= 16*256*256) return;
    float4 v;
    v.x = x[p*3 + 0]; v.y = x[p*3 + 1]; v.z = x[p*3 + 2]; v.w = 0.f;
    *reinterpret_cast<float4*>(&xp[p*4]) = v;
}
__global__ void pad_w1(const float* __restrict__ w, float* __restrict__ wp)
{
    int i = blockIdx.x*256 + threadIdx.x;
    if (i >= 4096) return;
    int co = i & 63, ci = (i >> 6) & 3, tap = i >> 8;
    wp[i] = (ci < 3) ? w[(tap*3 + ci)*64 + co] : 0.f;
}

// ====== tf32 mma.sync implicit-GEMM conv. BN may be < COUT (N-split via blockIdx.y)
// to cut register pressure on big SPLIT3 kernels (acc/fragments scale with NF).
template<int BM,int BN,int CIN,int COUT,int KH,int KW,int STRIDE,int PAD,int INH,int INW,
         bool RELU_IN,bool HAS_BIAS,bool ADD,bool RELU_OUT,bool TRANS,int SPLIT>
__global__ void __launch_bounds__(256)
mma_conv7(const float* __restrict__ in, const float* __restrict__ wgt,
          const float* __restrict__ bias, const float* __restrict__ addsrc,
          float* __restrict__ out)
{
    constexpr int MH = TRANS ? INH : INH / STRIDE;
    constexpr int MW = TRANS ? INW : INW / STRIDE;
    constexpr int K  = TRANS ? 4*CIN : KH*KW*CIN;
    constexpr int BK = 32;
    constexpr int S  = K / BK;
    constexpr int WARPS_N = (BN >= 64) ? 2 : 1;
    constexpr int WARPS_M = 8 / WARPS_N;
    constexpr int WM = BM / WARPS_M;
    constexpr int WN = BN / WARPS_N;
    constexpr int MF = WM / 16;
    constexpr int NF = WN / 8;
    constexpr int ASTR = BK + 4;
    constexpr int BSTR = BN + 8;
    constexpr int A_WORDS = BM*ASTR;
    constexpr int B_WORDS = BK*BSTR;
    constexpr int NCOPYB = (SPLIT==3 ? 2 : 1);
    constexpr int CSZ = A_WORDS + NCOPYB*B_WORDS;
    constexpr int NAITER = BM/32;
    constexpr int NBREG = (BK*BN)/(4*256);

    extern __shared__ __align__(16) uint32_t smem[];

    const int tid  = threadIdx.x;
    const int wid  = tid >> 5;
    const int lane = tid & 31;
    const int m0   = blockIdx.x * BM;
    const int n0   = blockIdx.y * BN;
    const int py   = TRANS ? (int)(blockIdx.z >> 1) : 0;
    const int px   = TRANS ? (int)(blockIdx.z & 1)  : 0;
    const int wm   = wid / WARPS_N;
    const int wn   = wid % WARPS_N;
    const int lr   = lane >> 2;
    const int lc   = lane & 3;

    float acc[MF][NF][4];
    #pragma unroll
    for (int i = 0; i < MF; i++)
        #pragma unroll
        for (int j = 0; j < NF; j++)
            #pragma unroll
            for (int r = 0; r < 4; r++) acc[i][j][r] = 0.f;

    float4 aR[NAITER];
    float4 bR[NBREG];

    auto load_regs = [&](int s) {
        const int k0 = s * BK;
        #pragma unroll
        for (int it = 0; it < NAITER; it++) {
            int l = tid + it*256;
            int m = l >> 3, kq = l & 7;
            int k = k0 + kq*4;
            int mg = m0 + m;
            int mx = mg % MW; int t = mg / MW; int my = t % MH; int n = t / MH;
            int iy, ix, ci;
            if (TRANS) {
                ci = k % CIN; int ab = k / CIN;
                int bb = ab & 1, aa = ab >> 1;
                iy = my + py + aa - 1;
                ix = mx + px + bb - 1;
            } else {
                ci = k % CIN; int r = k / CIN;
                int kw = r % KW, kh = r / KW;
                iy = my*STRIDE - PAD + kh;
                ix = mx*STRIDE - PAD + kw;
            }
            if (iy >= 0 && iy < INH && ix >= 0 && ix < INW)
                aR[it] = *reinterpret_cast<const float4*>(&in[((n*INH + iy)*INW + ix)*CIN + ci]);
            else
                aR[it] = make_float4(0.f,0.f,0.f,0.f);
        }
        #pragma unroll
        for (int it = 0; it < NBREG; it++) {
            int l = tid + it*256;
            int co = (l % (BN/4))*4;
            int kk = l / (BN/4);
            int k = k0 + kk;
            if (TRANS) {
                int ci = k % CIN; int ab = k / CIN;
                int bb = ab & 1, aa = ab >> 1;
                int widx = ((2*aa + py)*KW + (2*bb + px))*CIN + ci;
                bR[it] = *reinterpret_cast<const float4*>(&wgt[widx*COUT + n0 + co]);
            } else {
                bR[it] = *reinterpret_cast<const float4*>(&wgt[k*COUT + n0 + co]);
            }
        }
    };

    auto store_regs = [&](int buf) {
        float*    AsF = reinterpret_cast<float*>(smem + buf*CSZ);
        uint32_t* BsH = smem + buf*CSZ + A_WORDS;
        uint32_t* BsL = BsH + B_WORDS;
        #pragma unroll
        for (int it = 0; it < NAITER; it++) {
            int l = tid + it*256;
            int m = l >> 3, kq = l & 7;
            float4 v = aR[it];
            if (RELU_IN) {
                v.x = fmaxf(v.x, 0.f); v.y = fmaxf(v.y, 0.f);
                v.z = fmaxf(v.z, 0.f); v.w = fmaxf(v.w, 0.f);
            }
            *reinterpret_cast<float4*>(&AsF[m*ASTR + kq*4]) = v;
        }
        #pragma unroll
        for (int it = 0; it < NBREG; it++) {
            int l = tid + it*256;
            int co = (l % (BN/4))*4;
            int kk = l / (BN/4);
            float4 w = bR[it];
            uint4 h;
            h.x = f2tf32(w.x); h.y = f2tf32(w.y); h.z = f2tf32(w.z); h.w = f2tf32(w.w);
            *reinterpret_cast<uint4*>(&BsH[kk*BSTR + co]) = h;
            if (SPLIT == 3) {
                uint4 lo;
                lo.x = f2tf32(w.x - __uint_as_float(h.x));
                lo.y = f2tf32(w.y - __uint_as_float(h.y));
                lo.z = f2tf32(w.z - __uint_as_float(h.z));
                lo.w = f2tf32(w.w - __uint_as_float(h.w));
                *reinterpret_cast<uint4*>(&BsL[kk*BSTR + co]) = lo;
            }
        }
    };

    auto compute = [&](int buf) {
        const float*    AsF = reinterpret_cast<const float*>(smem + buf*CSZ);
        const uint32_t* BsH = smem + buf*CSZ + A_WORDS;
        const uint32_t* BsL = BsH + B_WORDS;
        #pragma unroll
        for (int ks = 0; ks < BK; ks += 8) {
            uint32_t ah[MF][4], al[MF][4];
            #pragma unroll
            for (int i = 0; i < MF; i++) {
                int r = wm*WM + i*16 + lr;
                float v0 = AsF[(r    )*ASTR + ks + lc];
                float v1 = AsF[(r + 8)*ASTR + ks + lc];
                float v2 = AsF[(r    )*ASTR + ks + lc + 4];
                float v3 = AsF[(r + 8)*ASTR + ks + lc + 4];
                ah[i][0] = f2tf32(v0); ah[i][1] = f2tf32(v1);
                ah[i][2] = f2tf32(v2); ah[i][3] = f2tf32(v3);
                if (SPLIT == 3) {
                    al[i][0] = f2tf32(v0 - __uint_as_float(ah[i][0]));
                    al[i][1] = f2tf32(v1 - __uint_as_float(ah[i][1]));
                    al[i][2] = f2tf32(v2 - __uint_as_float(ah[i][2]));
                    al[i][3] = f2tf32(v3 - __uint_as_float(ah[i][3]));
                }
            }
            #pragma unroll
            for (int j = 0; j < NF; j++) {
                int c = wn*WN + j*8 + lr;
                uint32_t bh[2], bl[2];
                bh[0] = BsH[(ks + lc    )*BSTR + c];
                bh[1] = BsH[(ks + lc + 4)*BSTR + c];
                if (SPLIT == 3) {
                    bl[0] = BsL[(ks + lc    )*BSTR + c];
                    bl[1] = BsL[(ks + lc + 4)*BSTR + c];
                }
                #pragma unroll
                for (int i = 0; i < MF; i++) {
                    if (SPLIT == 3) {
                        mma_tf32(acc[i][j], al[i], bh);
                        mma_tf32(acc[i][j], ah[i], bl);
                    }
                    mma_tf32(acc[i][j], ah[i], bh);
                }
            }
        }
    };

    load_regs(0);
    store_regs(0);
    __syncthreads();
    for (int s = 0; s < S; s++) {
        if (s + 1 < S) load_regs(s + 1);
        compute(s & 1);
        if (s + 1 < S) store_regs((s + 1) & 1);
        __syncthreads();
    }

    #pragma unroll
    for (int i = 0; i < MF; i++) {
        int r0 = m0 + wm*WM + i*16 + lr;
        #pragma unroll
        for (int half = 0; half < 2; half++) {
            int mg = r0 + half*8;
            int obase;
            if (TRANS) {
                int mx = mg % MW; int t = mg / MW; int my = t % MH; int n = t / MH;
                obase = ((n*(2*INH) + 2*my + py)*(2*INW) + 2*mx + px)*COUT;
            } else {
                obase = mg*COUT;
            }
            #pragma unroll
            for (int j = 0; j < NF; j++) {
                int c = wn*WN + j*8 + 2*lc;
                float v0 = acc[i][j][half*2 + 0];
                float v1 = acc[i][j][half*2 + 1];
                if (HAS_BIAS) {
                    float2 bv = *reinterpret_cast<const float2*>(&bias[n0 + c]);
                    v0 += bv.x; v1 += bv.y;
                }
                if (ADD) {
                    float2 av = *reinterpret_cast<const float2*>(&addsrc[obase + n0 + c]);
                    v0 += av.x; v1 += av.y;
                }
                if (RELU_OUT) { v0 = fmaxf(v0, 0.f); v1 = fmaxf(v1, 0.f); }
                float2 ov; ov.x = v0; ov.y = v1;
                *reinterpret_cast<float2*>(&out[obase + n0 + c]) = ov;
            }
        }
    }
}

// ====== fused residual block (R14, unchanged) ======
template<int SPLIT, bool RELU_OUT2>
__global__ void __launch_bounds__(256)
mma_resblk(const float* __restrict__ in, const float* __restrict__ w1,
           const float* __restrict__ w2, float* __restrict__ out)
{
    constexpr int INH=64, INW=64, CIN=128, K1=1152, BK=32, S=K1/BK;
    constexpr int ASTR=36, A_WORDS=128*ASTR;
    constexpr int B1STR=40, B1_WORDS=BK*B1STR;
    constexpr int NCOPYB=(SPLIT==3?2:1);
    constexpr int CSZ=A_WORDS+NCOPYB*B1_WORDS;
    constexpr int MID_OFF=2*CSZ;
    constexpr int W2_OFF=MID_OFF+A_WORDS;
    constexpr int B2STR=136, B2_WORDS=BK*B2STR;

    extern __shared__ __align__(16) uint32_t smem[];

    const int tid=threadIdx.x, wid=tid>>5, lane=tid&31;
    const int lr=lane>>2, lc=lane&3;
    const int m0=blockIdx.x*128;

    {
        uint32_t* W2H = smem + W2_OFF;
        uint32_t* W2L = W2H + B2_WORDS;
        #pragma unroll
        for (int it=0; it<4; it++){
            int l=tid+it*256;
            int co=(l&31)*4, kk=l>>5;
            float4 w=*reinterpret_cast<const float4*>(&w2[kk*128+co]);
            uint4 h; h.x=f2tf32(w.x); h.y=f2tf32(w.y); h.z=f2tf32(w.z); h.w=f2tf32(w.w);
            *reinterpret_cast<uint4*>(&W2H[kk*B2STR+co])=h;
            if (SPLIT==3){
                uint4 lo;
                lo.x=f2tf32(w.x-__uint_as_float(h.x));
                lo.y=f2tf32(w.y-__uint_as_float(h.y));
                lo.z=f2tf32(w.z-__uint_as_float(h.z));
                lo.w=f2tf32(w.w-__uint_as_float(h.w));
                *reinterpret_cast<uint4*>(&W2L[kk*B2STR+co])=lo;
            }
        }
    }

    float acc1[4][4];
    #pragma unroll
    for (int j=0;j<4;j++)
        #pragma unroll
        for (int r=0;r<4;r++) acc1[j][r]=0.f;

    float4 aR[4];
    float4 bR1;

    auto load_regs=[&](int s){
        const int k0=s*BK;
        #pragma unroll
        for (int it=0; it<4; it++){
            int l=tid+it*256;
            int m=l>>3, kq=l&7;
            int k=k0+kq*4;
            int mg=m0+m;
            int mx=mg&63; int t=mg>>6; int my=t&63; int n=t>>6;
            int ci=k&127; int r=k>>7;
            int kw=r%3, kh=r/3;
            int iy=my+kh-1, ix=mx+kw-1;
            if (iy>=0 && iy<INH && ix>=0 && ix<INW)
                aR[it]=*reinterpret_cast<const float4*>(&in[((n*INH+iy)*INW+ix)*CIN+ci]);
            else
                aR[it]=make_float4(0.f,0.f,0.f,0.f);
        }
        { int co=(tid&7)*4, kk=tid>>3;
          bR1=*reinterpret_cast<const float4*>(&w1[(k0+kk)*32+co]); }
    };
    auto store_regs=[&](int buf){
        float* AsF=reinterpret_cast<float*>(smem+buf*CSZ);
        uint32_t* BsH=smem+buf*CSZ+A_WORDS;
        uint32_t* BsL=BsH+B1_WORDS;
        #pragma unroll
        for (int it=0; it<4; it++){
            int l=tid+it*256;
            int m=l>>3, kq=l&7;
            float4 v=aR[it];
            v.x=fmaxf(v.x,0.f); v.y=fmaxf(v.y,0.f);
            v.z=fmaxf(v.z,0.f); v.w=fmaxf(v.w,0.f);
            *reinterpret_cast<float4*>(&AsF[m*ASTR+kq*4])=v;
        }
        {
            int co=(tid&7)*4, kk=tid>>3;
            float4 w=bR1;
            uint4 h; h.x=f2tf32(w.x); h.y=f2tf32(w.y); h.z=f2tf32(w.z); h.w=f2tf32(w.w);
            *reinterpret_cast<uint4*>(&BsH[kk*B1STR+co])=h;
            if (SPLIT==3){
                uint4 lo;
                lo.x=f2tf32(w.x-__uint_as_float(h.x));
                lo.y=f2tf32(w.y-__uint_as_float(h.y));
                lo.z=f2tf32(w.z-__uint_as_float(h.z));
                lo.w=f2tf32(w.w-__uint_as_float(h.w));
                *reinterpret_cast<uint4*>(&BsL[kk*B1STR+co])=lo;
            }
        }
    };
    auto compute=[&](int buf){
        const float* AsF=reinterpret_cast<const float*>(smem+buf*CSZ);
        const uint32_t* BsH=smem+buf*CSZ+A_WORDS;
        const uint32_t* BsL=BsH+B1_WORDS;
        #pragma unroll
        for (int ks=0; ks<BK; ks+=8){
            uint32_t ah[4], al[4];
            int r=wid*16+lr;
            float v0=AsF[(r  )*ASTR+ks+lc];
            float v1=AsF[(r+8)*ASTR+ks+lc];
            float v2=AsF[(r  )*ASTR+ks+lc+4];
            float v3=AsF[(r+8)*ASTR+ks+lc+4];
            ah[0]=f2tf32(v0); ah[1]=f2tf32(v1); ah[2]=f2tf32(v2); ah[3]=f2tf32(v3);
            if (SPLIT==3){
                al[0]=f2tf32(v0-__uint_as_float(ah[0]));
                al[1]=f2tf32(v1-__uint_as_float(ah[1]));
                al[2]=f2tf32(v2-__uint_as_float(ah[2]));
                al[3]=f2tf32(v3-__uint_as_float(ah[3]));
            }
            #pragma unroll
            for (int j=0;j<4;j++){
                int c=j*8+lr;
                uint32_t bh[2], bl[2];
                bh[0]=BsH[(ks+lc  )*B1STR+c];
                bh[1]=BsH[(ks+lc+4)*B1STR+c];
                if (SPLIT==3){
                    bl[0]=BsL[(ks+lc  )*B1STR+c];
                    bl[1]=BsL[(ks+lc+4)*B1STR+c];
                    mma_tf32(acc1[j], al, bh);
                    mma_tf32(acc1[j], ah, bl);
                }
                mma_tf32(acc1[j], ah, bh);
            }
        }
    };

    load_regs(0);
    store_regs(0);
    __syncthreads();
    for (int s=0; s<S; s++){
        if (s+1<S) load_regs(s+1);
        compute(s&1);
        if (s+1<S) store_regs((s+1)&1);
        __syncthreads();
    }

    {
        float* midA=reinterpret_cast<float*>(smem+MID_OFF);
        #pragma unroll
        for (int half=0; half<2; half++){
            int mg=wid*16+half*8+lr;
            #pragma unroll
            for (int j=0;j<4;j++){
                int c=j*8+2*lc;
                midA[mg*ASTR+c  ]=fmaxf(acc1[j][half*2+0],0.f);
                midA[mg*ASTR+c+1]=fmaxf(acc1[j][half*2+1],0.f);
            }
        }
    }
    __syncthreads();

    const int wm2=wid>>1, wn2=wid&1;
    float acc2[2][8][4];
    #pragma unroll
    for (int i=0;i<2;i++)
        #pragma unroll
        for (int j=0;j<8;j++)
            #pragma unroll
            for (int r=0;r<4;r++) acc2[i][j][r]=0.f;

    {
        const float* A2=reinterpret_cast<const float*>(smem+MID_OFF);
        const uint32_t* W2H=smem+W2_OFF;
        const uint32_t* W2L=W2H+B2_WORDS;
        #pragma unroll
        for (int ks=0; ks<32; ks+=8){
            uint32_t ah[2][4], al[2][4];
            #pragma unroll
            for (int i=0;i<2;i++){
                int r=wm2*32+i*16+lr;
                float v0=A2[(r  )*ASTR+ks+lc];
                float v1=A2[(r+8)*ASTR+ks+lc];
                float v2=A2[(r  )*ASTR+ks+lc+4];
                float v3=A2[(r+8)*ASTR+ks+lc+4];
                ah[i][0]=f2tf32(v0); ah[i][1]=f2tf32(v1);
                ah[i][2]=f2tf32(v2); ah[i][3]=f2tf32(v3);
                if (SPLIT==3){
                    al[i][0]=f2tf32(v0-__uint_as_float(ah[i][0]));
                    al[i][1]=f2tf32(v1-__uint_as_float(ah[i][1]));
                    al[i][2]=f2tf32(v2-__uint_as_float(ah[i][2]));
                    al[i][3]=f2tf32(v3-__uint_as_float(ah[i][3]));
                }
            }
            #pragma unroll
            for (int j=0;j<8;j++){
                int c=wn2*64+j*8+lr;
                uint32_t bh[2], bl[2];
                bh[0]=W2H[(ks+lc  )*B2STR+c];
                bh[1]=W2H[(ks+lc+4)*B2STR+c];
                if (SPLIT==3){
                    bl[0]=W2L[(ks+lc  )*B2STR+c];
                    bl[1]=W2L[(ks+lc+4)*B2STR+c];
                }
                #pragma unroll
                for (int i=0;i<2;i++){
                    if (SPLIT==3){
                        mma_tf32(acc2[i][j], al[i], bh);
                        mma_tf32(acc2[i][j], ah[i], bl);
                    }
                    mma_tf32(acc2[i][j], ah[i], bh);
                }
            }
        }
    }
    #pragma unroll
    for (int i=0;i<2;i++){
        #pragma unroll
        for (int half=0; half<2; half++){
            int mg=m0+wm2*32+i*16+half*8+lr;
            int obase=mg*128;
            #pragma unroll
            for (int j=0;j<8;j++){
                int c=wn2*64+j*8+2*lc;
                float v0=acc2[i][j][half*2+0];
                float v1=acc2[i][j][half*2+1];
                float2 rv=*reinterpret_cast<const float2*>(&in[obase+c]);
                v0+=rv.x; v1+=rv.y;
                if (RELU_OUT2){ v0=fmaxf(v0,0.f); v1=fmaxf(v1,0.f); }
                float2 ov; ov.x=v0; ov.y=v1;
                *reinterpret_cast<float2*>(&out[obase+c])=ov;
            }
        }
    }
}

// ======================= codebook prep =======================
__global__ void emb_prep(const float* __restrict__ emb,
                         float* __restrict__ embT, float* __restrict__ ehalf)
{
    int c = blockIdx.x;
    int k = threadIdx.x;
    float v = emb[c*128 + k];
    embT[k*512 + c] = v;
    float s = v*v;
    #pragma unroll
    for (int o = 16; o; o >>= 1) s += __shfl_xor_sync(0xffffffffu, s, o);
    __shared__ float red[4];
    if ((k & 31) == 0) red[k >> 5] = s;
    __syncthreads();
    if (k == 0) ehalf[c] = 0.5f*(red[0]+red[1]+red[2]+red[3]);
}

// ======================= VQ via 3xTF32 tensor GEMM + fragment argmax =======================
__global__ void __launch_bounds__(256)
vq_mma(const float* __restrict__ f, const float* __restrict__ emb,
       const float* __restrict__ embT, const float* __restrict__ ehalf,
       float* __restrict__ q)
{
    constexpr int ASTR = 36, BSTR = 136;
    constexpr int A_WORDS = 128*ASTR, B_WORDS = 32*BSTR;
    extern __shared__ __align__(16) uint32_t vsm[];
    float*    AsF = reinterpret_cast<float*>(vsm);
    uint32_t* BsH = vsm + A_WORDS;
    uint32_t* BsL = BsH + B_WORDS;
    __shared__ float bestV[128][2];
    __shared__ int   bestI[128][2];
    __shared__ int   rowIdx[128];

    const int tid  = threadIdx.x;
    const int wid  = tid >> 5;
    const int lane = tid & 31;
    const int lr   = lane >> 2;
    const int lc   = lane & 3;
    const int m0   = blockIdx.x * 128;
    const int wm   = wid >> 1;
    const int wn   = wid & 1;

    float best[4];
    int   bidx[4];
    #pragma unroll
    for (int t = 0; t < 4; t++) { best[t] = -3.4e38f; bidx[t] = 0; }

    for (int nc = 0; nc < 4; nc++) {
        float acc[2][8][4];
        #pragma unroll
        for (int i = 0; i < 2; i++)
            #pragma unroll
            for (int j = 0; j < 8; j++)
                #pragma unroll
                for (int r = 0; r < 4; r++) acc[i][j][r] = 0.f;

        for (int s = 0; s < 4; s++) {
            const int k0 = s*32;
            #pragma unroll
            for (int it = 0; it < 4; it++) {
                int l = tid + it*256;
                int m = l >> 3, kq = l & 7;
                float4 v = *reinterpret_cast<const float4*>(&f[(m0 + m)*128 + k0 + kq*4]);
                *reinterpret_cast<float4*>(&AsF[m*ASTR + kq*4]) = v;
            }
            #pragma unroll
            for (int it = 0; it < 4; it++) {
                int l = tid + it*256;
                int co = (l & 31)*4;
                int kk = l >> 5;
                float4 w = *reinterpret_cast<const float4*>(&embT[(k0 + kk)*512 + nc*128 + co]);
                uint4 h;
                h.x = f2tf32(w.x); h.y = f2tf32(w.y); h.z = f2tf32(w.z); h.w = f2tf32(w.w);
                *reinterpret_cast<uint4*>(&BsH[kk*BSTR + co]) = h;
                uint4 lo;
                lo.x = f2tf32(w.x - __uint_as_float(h.x));
                lo.y = f2tf32(w.y - __uint_as_float(h.y));
                lo.z = f2tf32(w.z - __uint_as_float(h.z));
                lo.w = f2tf32(w.w - __uint_as_float(h.w));
                *reinterpret_cast<uint4*>(&BsL[kk*BSTR + co]) = lo;
            }
            __syncthreads();
            #pragma unroll
            for (int ks = 0; ks < 32; ks += 8) {
                uint32_t ah[2][4], al[2][4];
                #pragma unroll
                for (int i = 0; i < 2; i++) {
                    int r = wm*32 + i*16 + lr;
                    float v0 = AsF[(r    )*ASTR + ks + lc];
                    float v1 = AsF[(r + 8)*ASTR + ks + lc];
                    float v2 = AsF[(r    )*ASTR + ks + lc + 4];
                    float v3 = AsF[(r + 8)*ASTR + ks + lc + 4];
                    ah[i][0] = f2tf32(v0); ah[i][1] = f2tf32(v1);
                    ah[i][2] = f2tf32(v2); ah[i][3] = f2tf32(v3);
                    al[i][0] = f2tf32(v0 - __uint_as_float(ah[i][0]));
                    al[i][1] = f2tf32(v1 - __uint_as_float(ah[i][1]));
                    al[i][2] = f2tf32(v2 - __uint_as_float(ah[i][2]));
                    al[i][3] = f2tf32(v3 - __uint_as_float(ah[i][3]));
                }
                #pragma unroll
                for (int j = 0; j < 8; j++) {
                    int c = wn*64 + j*8 + lr;
                    uint32_t bh[2], bl[2];
                    bh[0] = BsH[(ks + lc    )*BSTR + c];
                    bh[1] = BsH[(ks + lc + 4)*BSTR + c];
                    bl[0] = BsL[(ks + lc    )*BSTR + c];
                    bl[1] = BsL[(ks + lc + 4)*BSTR + c];
                    #pragma unroll
                    for (int i = 0; i < 2; i++) {
                        mma_tf32(acc[i][j], al[i], bh);
                        mma_tf32(acc[i][j], ah[i], bl);
                        mma_tf32(acc[i][j], ah[i], bh);
                    }
                }
            }
            __syncthreads();
        }
        #pragma unroll
        for (int i = 0; i < 2; i++) {
            #pragma unroll
            for (int half = 0; half < 2; half++) {
                int slot = i*2 + half;
                #pragma unroll
                for (int j = 0; j < 8; j++) {
                    int col = nc*128 + wn*64 + j*8 + 2*lc;
                    float s0 = acc[i][j][half*2 + 0] - __ldg(&ehalf[col]);
                    float s1 = acc[i][j][half*2 + 1] - __ldg(&ehalf[col + 1]);
                    if (s0 > best[slot] || (s0 == best[slot] && col < bidx[slot]))
                        { best[slot] = s0; bidx[slot] = col; }
                    if (s1 > best[slot] || (s1 == best[slot] && col + 1 < bidx[slot]))
                        { best[slot] = s1; bidx[slot] = col + 1; }
                }
            }
        }
    }
    #pragma unroll
    for (int slot = 0; slot < 4; slot++) {
        #pragma unroll
        for (int off = 1; off < 4; off <<= 1) {
            float ov = __shfl_xor_sync(0xffffffffu, best[slot], off);
            int   oi = __shfl_xor_sync(0xffffffffu, bidx[slot], off);
            if (ov > best[slot] || (ov == best[slot] && oi < bidx[slot]))
                { best[slot] = ov; bidx[slot] = oi; }
        }
        if (lc == 0) {
            int i = slot >> 1, half = slot & 1;
            int row = wm*32 + i*16 + half*8 + lr;
            bestV[row][wn] = best[slot];
            bestI[row][wn] = bidx[slot];
        }
    }
    __syncthreads();
    for (int r = tid; r < 128; r += 256) {
        float v0 = bestV[r][0], v1 = bestV[r][1];
        int   i0 = bestI[r][0], i1 = bestI[r][1];
        rowIdx[r] = (v1 > v0 || (v1 == v0 && i1 < i0)) ? i1 : i0;
    }
    __syncthreads();
    for (int l = tid; l < 128*128; l += 256) {
        int r = l >> 7, j = l & 127;
        q[(m0 + r)*128 + j] = emb[rowIdx[r]*128 + j];
    }
}

// ======= dt2: 4x4 s2 tconv 64->3 — 4-parity fused =======
__global__ void __launch_bounds__(256)
dt2_fused(const float* __restrict__ in,
          const float* __restrict__ wgt,
          const float* __restrict__ bias,
          float* __restrict__ out)
{
    __shared__ float ws[4*4*64*3];
    for (int l = threadIdx.x; l < 3072; l += 256) ws[l] = wgt[l];
    __syncthreads();

    const int m = blockIdx.x * 256 + threadIdx.x;
    const int xq = m & 127; int t = m >> 7; const int yq = t & 127; const int n = t >> 7;

    float acc[4][3];
    #pragma unroll
    for (int p = 0; p < 4; p++)
        #pragma unroll
        for (int c = 0; c < 3; c++) acc[p][c] = __ldg(&bias[c]);

    const bool vy0 = (yq - 1 >= 0), vy2 = (yq + 1 < 128);
    const bool vx0 = (xq - 1 >= 0), vx2 = (xq + 1 < 128);
    const bool valid[3][3] = {
        { vy0 && vx0, vy0, vy0 && vx2 },
        { vx0,        true, vx2        },
        { vy2 && vx0, vy2, vy2 && vx2 }
    };
    const float* base = in + ((n*128 + yq)*128 + xq)*64;

    for (int cb = 0; cb < 64; cb += 4) {
        float4 p[3][3];
        #pragma unroll
        for (int dy = 0; dy < 3; dy++)
            #pragma unroll
            for (int dx = 0; dx < 3; dx++)
                p[dy][dx] = valid[dy][dx]
                    ? *reinterpret_cast<const float4*>(base + ((dy-1)*128 + (dx-1))*64 + cb)
                    : make_float4(0.f,0.f,0.f,0.f);
        #pragma unroll
        for (int py = 0; py < 2; py++)
            #pragma unroll
            for (int px = 0; px < 2; px++) {
                const int pi = py*2 + px;
                #pragma unroll
                for (int aa = 0; aa < 2; aa++)
                    #pragma unroll
                    for (int bb = 0; bb < 2; bb++) {
                        const float4 v = p[py + aa][px + bb];
                        const float* w0 = ws + (((2*aa + py)*4 + (2*bb + px))*64 + cb)*3;
                        #pragma unroll
                        for (int c = 0; c < 3; c++) {
                            acc[pi][c] += v.x*w0[c];
                            acc[pi][c] += v.y*w0[3 + c];
                            acc[pi][c] += v.z*w0[6 + c];
                            acc[pi][c] += v.w*w0[9 + c];
                        }
                    }
            }
    }
    #pragma unroll
    for (int py = 0; py < 2; py++)
        #pragma unroll
        for (int px = 0; px < 2; px++) {
            const int oy = 2*yq + py, ox = 2*xq + px;
            float* op = out + ((n*256 + oy)*256 + ox)*3;
            const int pi = py*2 + px;
            op[0] = acc[pi][0]; op[1] = acc[pi][1]; op[2] = acc[pi][2];
        }
}

// ======================= host launcher =======================
extern "C" void kernel_launch(void* const* d_in, const int* in_sizes, int n_in,
                              void* d_out, int out_size)
{
    (void)in_sizes; (void)n_in;
    const float* x       = (const float*)d_in[0];
    const float* emb     = (const float*)d_in[1];
    const float* enc_w1  = (const float*)d_in[2];
    const float* enc_b1  = (const float*)d_in[3];
    const float* enc_w2  = (const float*)d_in[4];
    const float* enc_b2  = (const float*)d_in[5];
    const float* enc_w3  = (const float*)d_in[6];
    const float* enc_b3  = (const float*)d_in[7];
    const float* erb1_w1 = (const float*)d_in[8];
    const float* erb1_w2 = (const float*)d_in[9];
    const float* erb2_w1 = (const float*)d_in[10];
    const float* erb2_w2 = (const float*)d_in[11];
    const float* dec_w   = (const float*)d_in[12];
    const float* dec_b   = (const float*)d_in[13];
    const float* drb1_w1 = (const float*)d_in[14];
    const float* drb1_w2 = (const float*)d_in[15];
    const float* drb2_w1 = (const float*)d_in[16];
    const float* drb2_w2 = (const float*)d_in[17];
    const float* dt1_w   = (const float*)d_in[18];
    const float* dt1_b   = (const float*)d_in[19];
    const float* dt2_w   = (const float*)d_in[20];
    const float* dt2_b   = (const float*)d_in[21];

    float* out = (float*)d_out;
    const int YS = 16*256*256*3;
    const int FS = 16*64*64*128;

    float *buf0,*buf1,*buf2,*embT,*ehalf,*fb,*qb,*xpad,*w1pad;
    cudaGetSymbolAddress((void**)&buf0,  g_buf0);
    cudaGetSymbolAddress((void**)&buf1,  g_buf1);
    cudaGetSymbolAddress((void**)&buf2,  g_buf2);
    cudaGetSymbolAddress((void**)&embT,  g_embT);
    cudaGetSymbolAddress((void**)&ehalf, g_ehalf);
    cudaGetSymbolAddress((void**)&fb,    g_fbuf);
    cudaGetSymbolAddress((void**)&qb,    g_qbuf);
    cudaGetSymbolAddress((void**)&xpad,  g_xpad);
    cudaGetSymbolAddress((void**)&w1pad, g_w1pad);

    const bool full = (out_size >= YS + 2*FS);
    float* fptr = full ? (out + YS)      : fb;
    float* qptr = full ? (out + YS + FS) : qb;

    dim3 b(256);

    // smem: 2*(A 4608 + NCOPYB*(32*(BN+8))) words *4B
    const int SM3_64  = 2*(4608 + 2*2304)*4;    // 73728  (BN=64 SPLIT3)
    const int SM1_128 = 2*(4608 + 4352)*4;      // 71680
    const int SM1_64  = 2*(4608 + 2304)*4;      // 55296
    const int SM_VQ   = (4608 + 2*4352)*4;      // 53248
    const int SMR3 = (2*(4608 + 2*1280) + 4608 + 2*4352)*4;  // 110592
    const int SMR1 = (2*(4608 + 1280) + 4608 + 4352)*4;      // 82944

    // BN=64 N-split for the big SPLIT3 kernels (register relief -> 2 blocks/SM)
    auto kEnc1 = mma_conv7<128,64, 4,64, 4,4,2,1, 256,256, false,true,false,true,false,3>;
    auto kEnc2 = mma_conv7<128,64, 64,128,4,4,2,1, 128,128, false,true,false,true,false,3>;
    auto kEnc3 = mma_conv7<128,64, 128,128,3,3,1,1, 64,64, false,true,false,false,false,3>;
    auto kRes3F = mma_resblk<3,false>;
    auto kRes3T = mma_resblk<3,true>;
    auto kDec  = mma_conv7<128,128, 128,128,3,3,1,1, 64,64, false,true,false,false,false,1>;
    auto kRes1F = mma_resblk<1,false>;
    auto kRes1T = mma_resblk<1,true>;
    auto kDt1  = mma_conv7<128,64, 128,64, 4,4,2,0, 64,64, false,true,false,true,true,1>;

    cudaFuncSetAttribute(kEnc1, cudaFuncAttributeMaxDynamicSharedMemorySize, SM3_64);
    cudaFuncSetAttribute(kEnc2, cudaFuncAttributeMaxDynamicSharedMemorySize, SM3_64);
    cudaFuncSetAttribute(kEnc3, cudaFuncAttributeMaxDynamicSharedMemorySize, SM3_64);
    cudaFuncSetAttribute(kRes3F, cudaFuncAttributeMaxDynamicSharedMemorySize, SMR3);
    cudaFuncSetAttribute(kRes3T, cudaFuncAttributeMaxDynamicSharedMemorySize, SMR3);
    cudaFuncSetAttribute(kDec,  cudaFuncAttributeMaxDynamicSharedMemorySize, SM1_128);
    cudaFuncSetAttribute(kRes1F, cudaFuncAttributeMaxDynamicSharedMemorySize, SMR1);
    cudaFuncSetAttribute(kRes1T, cudaFuncAttributeMaxDynamicSharedMemorySize, SMR1);
    cudaFuncSetAttribute(kDt1,  cudaFuncAttributeMaxDynamicSharedMemorySize, SM1_64);
    cudaFuncSetAttribute(vq_mma, cudaFuncAttributeMaxDynamicSharedMemorySize, SM_VQ);

    // ---- enc1 prep: pad channels 3->4 ----
    pad_input<<<dim3(4096,1,1), b>>>(x, xpad);
    pad_w1<<<dim3(16,1,1), b>>>(enc_w1, w1pad);

    // ---- encoder (3xTF32, ~fp32 precision -> argmin-exact) ----
    kEnc1<<<dim3(2048,1,1), b, SM3_64>>>(xpad, w1pad, enc_b1, nullptr, buf0);
    kEnc2<<<dim3(512,2,1), b, SM3_64>>>(buf0, enc_w2, enc_b2, nullptr, buf1);
    kEnc3<<<dim3(512,2,1), b, SM3_64>>>(buf1, enc_w3, enc_b3, nullptr, buf2);
    kRes3F<<<dim3(512,1,1), b, SMR3>>>(buf2, erb1_w1, erb1_w2, buf1);
    kRes3T<<<dim3(512,1,1), b, SMR3>>>(buf1, erb2_w1, erb2_w2, fptr);

    // ---- VQ ----
    emb_prep<<<512,128>>>(emb, embT, ehalf);
    vq_mma<<<512, b, SM_VQ>>>(fptr, emb, embT, ehalf, qptr);

    // ---- decoder (single-pass tf32) ----
    kDec <<<dim3(512,1,1), b, SM1_128>>>(qptr, dec_w, dec_b, nullptr, buf1);
    kRes1F<<<dim3(512,1,1), b, SMR1>>>(buf1, drb1_w1, drb1_w2, buf2);
    kRes1T<<<dim3(512,1,1), b, SMR1>>>(buf2, drb2_w1, drb2_w2, buf1);
    kDt1 <<<dim3(512,1,4), b, SM1_64>>>(buf1, dt1_w, dt1_b, nullptr, buf0);

    dt2_fused<<<dim3(1024,1,1),b>>>(buf0, dt2_w, dt2_b, out);
}